// round 11
// baseline (speedup 1.0000x reference)
#include <cuda_runtime.h>
#include <cuda_bf16.h>
#include <math.h>
#include <stdint.h>

// ---------------- static problem config ----------------
#define Bq    8
#define Pp    8
#define Nn    100
#define Dm    256
#define Hh    8
#define DKk   32
#define Mm    64
#define Kg    16
#define Ll    800            // P*N
#define BL    6400           // B*L
#define NSPLIT 125
#define KCHUNK 80            // 125*80 = 10000

#define PHI_SCALE 0.84089641525f   // 2 * 32^-0.25
#define KVS_ELEMS (64*512*64)

typedef unsigned long long ull;

// ---------------- packed f32x2 helpers ----------------
__device__ __forceinline__ ull pack2(float x, float y) {
    ull r; asm("mov.b64 %0, {%1,%2};" : "=l"(r) : "f"(x), "f"(y)); return r;
}
__device__ __forceinline__ ull fma2(ull a, ull b, ull c) {
    ull d; asm("fma.rn.f32x2 %0, %1, %2, %3;" : "=l"(d) : "l"(a), "l"(b), "l"(c)); return d;
}
__device__ __forceinline__ float2 unpack2(ull p) {
    float2 r; asm("mov.b64 {%0,%1}, %2;" : "=f"(r.x), "=f"(r.y) : "l"(p)); return r;
}

// ---------------- scratch (device globals; no allocation) ----------------
__device__ __align__(16) float g_q   [BL*Dm];
__device__ __align__(16) float g_k   [BL*Dm];
__device__ __align__(16) float g_v   [BL*Dm];
__device__ __align__(16) float g_qp  [BL*Hh*Mm];
__device__ __align__(16) float g_kdd [BL*Hh*Mm];
__device__              float g_kdiag[BL*Hh];
__device__              float g_krmax[BL*Hh];
__device__ __align__(16) float g_kp  [BL*Hh*Mm];
__device__ __align__(16) __nv_bfloat16 g_kvsT_hi[KVS_ELEMS];
__device__ __align__(16) __nv_bfloat16 g_kvsT_lo[KVS_ELEMS];
__device__ __align__(16) float g_ksum[Bq*Hh*Kg*Mm];
__device__ __align__(16) float g_winv[BL*Hh*Kg];
__device__ __align__(16) float g_z   [BL*Dm];
__device__ __align__(16) float g_h1p [NSPLIT*512*128];
__device__              float g_gscore[512];
__device__              float g_wpat [512];
__device__ __align__(16) float g_fused[Bq*Pp*Nn*Nn];
__device__              float g_rden [Bq*Pp*Nn];

// ================= mma.sync primitive =================
__device__ __forceinline__ void mma16816(float* d, const uint32_t* a, const uint32_t* b)
{
    asm volatile(
        "mma.sync.aligned.m16n8k16.row.col.f32.bf16.bf16.f32 "
        "{%0,%1,%2,%3}, {%4,%5,%6,%7}, {%8,%9}, {%0,%1,%2,%3};"
        : "+f"(d[0]), "+f"(d[1]), "+f"(d[2]), "+f"(d[3])
        : "r"(a[0]), "r"(a[1]), "r"(a[2]), "r"(a[3]), "r"(b[0]), "r"(b[1]));
}

__device__ __forceinline__ void bf16_split(float f, __nv_bfloat16& hi, __nv_bfloat16& lo)
{
    hi = __float2bfloat16(f);
    lo = __float2bfloat16(f - __bfloat162float(hi));
}
__device__ __forceinline__ uint32_t pack_bf2(__nv_bfloat16 a, __nv_bfloat16 b)
{
    __nv_bfloat162 p = __halves2bfloat162(a, b);
    return reinterpret_cast<uint32_t&>(p);
}

// ================= projection GEMM (bf16x3, proven in R6) =================
#define SMS 40

__device__ __forceinline__ void load_slab32(const float* __restrict__ src,
                                            __nv_bfloat16* __restrict__ hi,
                                            __nv_bfloat16* __restrict__ lo, int tid)
{
    for (int idx = tid; idx < 1024; idx += 256) {
        int r = idx >> 3, c4 = (idx & 7) * 4;
        float4 f = *(const float4*)(src + (size_t)r * 256 + c4);
        __nv_bfloat16 h0, l0, h1, l1, h2, l2, h3, l3;
        bf16_split(f.x, h0, l0); bf16_split(f.y, h1, l1);
        bf16_split(f.z, h2, l2); bf16_split(f.w, h3, l3);
        uint2 hw = make_uint2(pack_bf2(h0, h1), pack_bf2(h2, h3));
        uint2 lw = make_uint2(pack_bf2(l0, l1), pack_bf2(l2, l3));
        *(uint2*)(hi + r * SMS + c4) = hw;
        *(uint2*)(lo + r * SMS + c4) = lw;
    }
}

__device__ __forceinline__ void mma_gemm_body(const float* __restrict__ A,
                                              const float* __restrict__ W,
                                              const float* __restrict__ bias,
                                              float* __restrict__ C)
{
    __shared__ __align__(16) __nv_bfloat16 sm[4 * 128 * SMS];
    __nv_bfloat16* Ah = sm;
    __nv_bfloat16* Al = sm + 128 * SMS;
    __nv_bfloat16* Wh = sm + 2 * 128 * SMS;
    __nv_bfloat16* Wl = sm + 3 * 128 * SMS;

    int tid = threadIdx.x, lane = tid & 31, warp = tid >> 5;
    int wm = warp & 3, wn = warp >> 2;
    int row0 = blockIdx.x * 128, col0 = blockIdx.y * 128;
    int g = lane >> 2, tg = lane & 3;

    float d[2][8][4];
#pragma unroll
    for (int mt = 0; mt < 2; mt++)
#pragma unroll
        for (int nt = 0; nt < 8; nt++)
#pragma unroll
            for (int i = 0; i < 4; i++) d[mt][nt][i] = 0.f;

    for (int kc = 0; kc < 8; kc++) {
        load_slab32(A + (size_t)row0 * 256 + kc * 32, Ah, Al, tid);
        load_slab32(W + (size_t)col0 * 256 + kc * 32, Wh, Wl, tid);
        __syncthreads();
#pragma unroll
        for (int ks = 0; ks < 2; ks++) {
            int kb = ks * 16;
            uint32_t ah[2][4], al[2][4];
#pragma unroll
            for (int mt = 0; mt < 2; mt++) {
                int rb = wm * 32 + mt * 16;
                const __nv_bfloat16* p0 = &Ah[(rb + g) * SMS + kb + tg * 2];
                const __nv_bfloat16* p1 = &Ah[(rb + g + 8) * SMS + kb + tg * 2];
                ah[mt][0] = *(const uint32_t*)p0;
                ah[mt][1] = *(const uint32_t*)p1;
                ah[mt][2] = *(const uint32_t*)(p0 + 8);
                ah[mt][3] = *(const uint32_t*)(p1 + 8);
                const __nv_bfloat16* q0 = &Al[(rb + g) * SMS + kb + tg * 2];
                const __nv_bfloat16* q1 = &Al[(rb + g + 8) * SMS + kb + tg * 2];
                al[mt][0] = *(const uint32_t*)q0;
                al[mt][1] = *(const uint32_t*)q1;
                al[mt][2] = *(const uint32_t*)(q0 + 8);
                al[mt][3] = *(const uint32_t*)(q1 + 8);
            }
#pragma unroll
            for (int nt = 0; nt < 8; nt++) {
                int nb = wn * 64 + nt * 8;
                const __nv_bfloat16* qh = &Wh[(nb + g) * SMS + kb + tg * 2];
                const __nv_bfloat16* ql = &Wl[(nb + g) * SMS + kb + tg * 2];
                uint32_t bh2[2] = {*(const uint32_t*)qh, *(const uint32_t*)(qh + 8)};
                uint32_t bl2[2] = {*(const uint32_t*)ql, *(const uint32_t*)(ql + 8)};
#pragma unroll
                for (int mt = 0; mt < 2; mt++) {
                    mma16816(d[mt][nt], ah[mt], bh2);
                    mma16816(d[mt][nt], ah[mt], bl2);
                    mma16816(d[mt][nt], al[mt], bh2);
                }
            }
        }
        __syncthreads();
    }

#pragma unroll
    for (int mt = 0; mt < 2; mt++) {
        int r0 = row0 + wm * 32 + mt * 16 + g;
#pragma unroll
        for (int nt = 0; nt < 8; nt++) {
            int col = col0 + wn * 64 + nt * 8 + tg * 2;
            float2 b2 = *(const float2*)&bias[col];
            float2 o0 = make_float2(d[mt][nt][0] + b2.x, d[mt][nt][1] + b2.y);
            float2 o1 = make_float2(d[mt][nt][2] + b2.x, d[mt][nt][3] + b2.y);
            *(float2*)&C[(size_t)r0 * 256 + col]       = o0;
            *(float2*)&C[(size_t)(r0 + 8) * 256 + col] = o1;
        }
    }
}

__global__ void __launch_bounds__(256) qkv_mma(
    const float* __restrict__ x,
    const float* __restrict__ Wq, const float* __restrict__ Wk, const float* __restrict__ Wv,
    const float* __restrict__ bq, const float* __restrict__ bk, const float* __restrict__ bv,
    float* __restrict__ q, float* __restrict__ k, float* __restrict__ v)
{
    const float* W = blockIdx.z == 0 ? Wq : (blockIdx.z == 1 ? Wk : Wv);
    const float* b = blockIdx.z == 0 ? bq : (blockIdx.z == 1 ? bk : bv);
    float* C       = blockIdx.z == 0 ? q  : (blockIdx.z == 1 ? k  : v);
    mma_gemm_body(x, W, b, C);
}

__global__ void __launch_bounds__(256) wo_mma(
    const float* __restrict__ A, const float* __restrict__ W,
    const float* __restrict__ b, float* __restrict__ C)
{
    mma_gemm_body(A, W, b, C);
}

// ================= fc GEMM on HMMA (bf16x3, split-K) =================
#define SF 24
__global__ void __launch_bounds__(256) fc_mma(
    const float* __restrict__ A, const float* __restrict__ W, float* __restrict__ C)
{
    __shared__ __align__(16) __nv_bfloat16 Ah[128*SF], Al_[128*SF];
    __shared__ __align__(16) __nv_bfloat16 Wh[128*SF], Wl[128*SF];

    int t = threadIdx.x, lane = t & 31, warp = t >> 5;
    int wm = warp & 3, wn = warp >> 2;
    int row0 = blockIdx.x * 128;
    int k0 = blockIdx.y * KCHUNK;
    int g = lane >> 2, tg = lane & 3;

    float d[2][8][4];
#pragma unroll
    for (int mt = 0; mt < 2; mt++)
#pragma unroll
        for (int nt = 0; nt < 8; nt++)
#pragma unroll
            for (int i = 0; i < 4; i++) d[mt][nt][i] = 0.f;

    for (int kc = 0; kc < 5; kc++) {
        int kk = k0 + kc * 16;
        __syncthreads();
#pragma unroll
        for (int j = 0; j < 2; j++) {
            int idx = t + j * 256;              // < 512
            int r = idx >> 2, c4 = (idx & 3) * 4;
            float4 fa = *(const float4*)(A + (size_t)(row0 + r) * 10000 + kk + c4);
            __nv_bfloat16 h0,l0,h1,l1,h2,l2,h3,l3;
            bf16_split(fa.x,h0,l0); bf16_split(fa.y,h1,l1);
            bf16_split(fa.z,h2,l2); bf16_split(fa.w,h3,l3);
            *(uint32_t*)&Ah [r*SF + c4]     = pack_bf2(h0,h1);
            *(uint32_t*)&Ah [r*SF + c4 + 2] = pack_bf2(h2,h3);
            *(uint32_t*)&Al_[r*SF + c4]     = pack_bf2(l0,l1);
            *(uint32_t*)&Al_[r*SF + c4 + 2] = pack_bf2(l2,l3);
            float4 fw = *(const float4*)(W + (size_t)r * 10000 + kk + c4);
            bf16_split(fw.x,h0,l0); bf16_split(fw.y,h1,l1);
            bf16_split(fw.z,h2,l2); bf16_split(fw.w,h3,l3);
            *(uint32_t*)&Wh[r*SF + c4]     = pack_bf2(h0,h1);
            *(uint32_t*)&Wh[r*SF + c4 + 2] = pack_bf2(h2,h3);
            *(uint32_t*)&Wl[r*SF + c4]     = pack_bf2(l0,l1);
            *(uint32_t*)&Wl[r*SF + c4 + 2] = pack_bf2(l2,l3);
        }
        __syncthreads();
        uint32_t ah[2][4], al[2][4];
#pragma unroll
        for (int mt = 0; mt < 2; mt++) {
            int rb = wm * 32 + mt * 16;
            const __nv_bfloat16* p0 = &Ah[(rb + g) * SF + tg*2];
            const __nv_bfloat16* p1 = &Ah[(rb + g + 8) * SF + tg*2];
            ah[mt][0] = *(const uint32_t*)p0;
            ah[mt][1] = *(const uint32_t*)p1;
            ah[mt][2] = *(const uint32_t*)(p0 + 8);
            ah[mt][3] = *(const uint32_t*)(p1 + 8);
            const __nv_bfloat16* q0 = &Al_[(rb + g) * SF + tg*2];
            const __nv_bfloat16* q1 = &Al_[(rb + g + 8) * SF + tg*2];
            al[mt][0] = *(const uint32_t*)q0;
            al[mt][1] = *(const uint32_t*)q1;
            al[mt][2] = *(const uint32_t*)(q0 + 8);
            al[mt][3] = *(const uint32_t*)(q1 + 8);
        }
#pragma unroll
        for (int nt = 0; nt < 8; nt++) {
            int nb = wn * 64 + nt * 8;
            const __nv_bfloat16* qh = &Wh[(nb + g) * SF + tg*2];
            const __nv_bfloat16* ql = &Wl[(nb + g) * SF + tg*2];
            uint32_t bh2[2] = {*(const uint32_t*)qh, *(const uint32_t*)(qh + 8)};
            uint32_t bl2[2] = {*(const uint32_t*)ql, *(const uint32_t*)(ql + 8)};
#pragma unroll
            for (int mt = 0; mt < 2; mt++) {
                mma16816(d[mt][nt], ah[mt], bh2);
                mma16816(d[mt][nt], ah[mt], bl2);
                mma16816(d[mt][nt], al[mt], bh2);
            }
        }
    }
    float* Cp = C + (size_t)blockIdx.y * 512 * 128;
#pragma unroll
    for (int mt = 0; mt < 2; mt++) {
        int r0 = row0 + wm * 32 + mt * 16 + g;
#pragma unroll
        for (int nt = 0; nt < 8; nt++) {
            int col = wn * 64 + nt * 8 + tg * 2;
            *(float2*)&Cp[(size_t)r0 * 128 + col]       = make_float2(d[mt][nt][0], d[mt][nt][1]);
            *(float2*)&Cp[(size_t)(r0 + 8) * 128 + col] = make_float2(d[mt][nt][2], d[mt][nt][3]);
        }
    }
}

// ---------------- h1 split reduction + relu + dot(out_w): 512 blocks x 128 ----
__global__ void hsum_kernel(const float* __restrict__ h1p, const float* __restrict__ fc_b,
                            const float* __restrict__ out_w, const float* __restrict__ out_b,
                            float* __restrict__ gscore)
{
    __shared__ float red[128];
    int row = blockIdx.x;          // < 512
    int j = threadIdx.x;           // < 128
    float s = 0.f;
    size_t base = (size_t)row * 128 + j;
#pragma unroll 5
    for (int sp = 0; sp < NSPLIT; sp++) s += h1p[(size_t)sp * 65536 + base];
    float hv = fmaxf(s + fc_b[j], 0.f) * out_w[j];
    red[j] = hv;
    __syncthreads();
    for (int o = 64; o > 0; o >>= 1) {
        if (j < o) red[j] += red[j + o];
        __syncthreads();
    }
    if (j == 0) gscore[row] = red[0] + out_b[0];
}

// softmax over groups of 8 patch scores; 64 threads, one per bp
__global__ void softmax8_kernel(const float* __restrict__ gscore, float* __restrict__ wpat)
{
    int bp = threadIdx.x;          // < 64
    float sc[8];
    float mx = -1e30f;
#pragma unroll
    for (int i = 0; i < 8; i++) { sc[i] = gscore[bp*8 + i]; mx = fmaxf(mx, sc[i]); }
    float sum = 0.f;
#pragma unroll
    for (int i = 0; i < 8; i++) { sc[i] = expf(sc[i] - mx); sum += sc[i]; }
    float inv = 1.0f / sum;
#pragma unroll
    for (int i = 0; i < 8; i++) wpat[bp*8 + i] = sc[i] * inv;
}

// ================= kvs on HMMA, single pass, packed staging =================
// grid (64 bh, 4 q). Direct transposed bf16 hi/lo output.
#define SA 36
__global__ void __launch_bounds__(256) kvs_mma(
    const float* __restrict__ kp, const float* __restrict__ v,
    const float* __restrict__ gum,
    __nv_bfloat16* __restrict__ kvsT_hi, __nv_bfloat16* __restrict__ kvsT_lo)
{
    __shared__ __align__(16) __nv_bfloat16 As_hi[64*SA], As_lo[64*SA];
    __shared__ __align__(16) __nv_bfloat16 Bs_hi[128*SA], Bs_lo[128*SA];
    __shared__ float v_s[32][32];
    __shared__ float e_s[32][4];

    int bh = blockIdx.x, q = blockIdx.y;
    int b = bh >> 3, h = bh & 7;
    int t = threadIdx.x, lane = t & 31, warp = t >> 5;
    int wm = warp & 3, wn = warp >> 2;
    int g = lane >> 2, tg = lane & 3;

    float d[8][4];
#pragma unroll
    for (int nt = 0; nt < 8; nt++)
#pragma unroll
        for (int i = 0; i < 4; i++) d[nt][i] = 0.f;

    for (int l0 = 0; l0 < Ll; l0 += 32) {
        __syncthreads();
        {
            int l = t >> 3, d4 = (t & 7) * 4;
            *(float4*)&v_s[l][d4] =
                *(const float4*)&v[(size_t)(b*Ll + l0 + l)*Dm + h*32 + d4];
        }
        if (t < 128) {
            int l = t >> 2, kq = t & 3;
            e_s[l][kq] = expf(gum[(((b*Ll + l0 + l)*Hh + h) << 4) + q*4 + kq]);
        }
#pragma unroll
        for (int j = 0; j < 4; j++) {
            int idx = t + j * 256;
            int m = idx & 63, lp = idx >> 6;
            int l = l0 + lp * 2;
            float f0 = kp[((size_t)((b*Ll + l    )*Hh + h) << 6) + m];
            float f1 = kp[((size_t)((b*Ll + l + 1)*Hh + h) << 6) + m];
            __nv_bfloat16 h0, lo0, h1, lo1;
            bf16_split(f0, h0, lo0); bf16_split(f1, h1, lo1);
            *(uint32_t*)&As_hi[m*SA + lp*2] = pack_bf2(h0, h1);
            *(uint32_t*)&As_lo[m*SA + lp*2] = pack_bf2(lo0, lo1);
        }
        __syncthreads();
        {
            int n = t >> 1;
            int lpb = (t & 1) * 8;
            int kq = n >> 5, dd = n & 31;
#pragma unroll
            for (int j = 0; j < 8; j++) {
                int lp = lpb + j;
                float f0 = e_s[2*lp][kq]     * v_s[2*lp][dd];
                float f1 = e_s[2*lp + 1][kq] * v_s[2*lp + 1][dd];
                __nv_bfloat16 h0, lo0, h1, lo1;
                bf16_split(f0, h0, lo0); bf16_split(f1, h1, lo1);
                *(uint32_t*)&Bs_hi[n*SA + lp*2] = pack_bf2(h0, h1);
                *(uint32_t*)&Bs_lo[n*SA + lp*2] = pack_bf2(lo0, lo1);
            }
        }
        __syncthreads();
#pragma unroll
        for (int ks = 0; ks < 2; ks++) {
            int kb = ks * 16;
            uint32_t ah[4], al[4];
            {
                int rb = wm * 16;
                const __nv_bfloat16* p0 = &As_hi[(rb + g) * SA + kb + tg*2];
                const __nv_bfloat16* p1 = &As_hi[(rb + g + 8) * SA + kb + tg*2];
                ah[0] = *(const uint32_t*)p0;
                ah[1] = *(const uint32_t*)p1;
                ah[2] = *(const uint32_t*)(p0 + 8);
                ah[3] = *(const uint32_t*)(p1 + 8);
                const __nv_bfloat16* q0 = &As_lo[(rb + g) * SA + kb + tg*2];
                const __nv_bfloat16* q1 = &As_lo[(rb + g + 8) * SA + kb + tg*2];
                al[0] = *(const uint32_t*)q0;
                al[1] = *(const uint32_t*)q1;
                al[2] = *(const uint32_t*)(q0 + 8);
                al[3] = *(const uint32_t*)(q1 + 8);
            }
#pragma unroll
            for (int nt = 0; nt < 8; nt++) {
                int nb = wn * 64 + nt * 8;
                const __nv_bfloat16* qh = &Bs_hi[(nb + g) * SA + kb + tg*2];
                const __nv_bfloat16* ql = &Bs_lo[(nb + g) * SA + kb + tg*2];
                uint32_t bh2[2] = {*(const uint32_t*)qh, *(const uint32_t*)(qh + 8)};
                uint32_t bl2[2] = {*(const uint32_t*)ql, *(const uint32_t*)(ql + 8)};
                mma16816(d[nt], ah, bh2);
                mma16816(d[nt], ah, bl2);
                mma16816(d[nt], al, bh2);
            }
        }
    }
    // epilogue: store transposed [kd][m] hi/lo
    int m = wm * 16 + g;
#pragma unroll
    for (int nt = 0; nt < 8; nt++) {
        int n = q*128 + wn*64 + nt*8 + tg*2;
        size_t base0 = ((size_t)bh * 512 + n) * 64;
        size_t base1 = base0 + 64;
        __nv_bfloat16 hi, lo;
        bf16_split(d[nt][0], hi, lo); kvsT_hi[base0 + m] = hi;     kvsT_lo[base0 + m] = lo;
        bf16_split(d[nt][1], hi, lo); kvsT_hi[base1 + m] = hi;     kvsT_lo[base1 + m] = lo;
        bf16_split(d[nt][2], hi, lo); kvsT_hi[base0 + m + 8] = hi; kvsT_lo[base0 + m + 8] = lo;
        bf16_split(d[nt][3], hi, lo); kvsT_hi[base1 + m + 8] = hi; kvsT_lo[base1 + m + 8] = lo;
    }
}

// ================= z on HMMA + winv reduction + LayerNorm =================
#define SQ 68
__global__ void __launch_bounds__(256) z_mma(
    const float* __restrict__ qp,
    const __nv_bfloat16* __restrict__ kvsT_hi, const __nv_bfloat16* __restrict__ kvsT_lo,
    const float* __restrict__ winv, float* __restrict__ z,
    const float* __restrict__ ln_g, const float* __restrict__ ln_b)
{
    __shared__ __align__(16) __nv_bfloat16 Aq_hi[32*SQ], Aq_lo[32*SQ];
    __shared__ __align__(16) __nv_bfloat16 Bs_hi[64*SQ], Bs_lo[64*SQ];
    __shared__ float winv_s[32][16];
    __shared__ float zred[4][32][33];

    int bh = blockIdx.x;
    int b = bh >> 3, h = bh & 7;
    int l0 = blockIdx.y * 32;
    int t = threadIdx.x, lane = t & 31, warp = t >> 5;
    int wm = warp & 1, wn = warp >> 1;
    int g = lane >> 2, tg = lane & 3;

#pragma unroll
    for (int j = 0; j < 4; j++) {
        int idx = t + j * 256;
        int l = idx >> 5, mp = idx & 31;
        float2 q2 = *(const float2*)&qp[((size_t)((b*Ll + l0 + l)*Hh + h) << 6) + mp*2];
        __nv_bfloat16 h0, lo0, h1, lo1;
        bf16_split(q2.x, h0, lo0); bf16_split(q2.y, h1, lo1);
        *(uint32_t*)&Aq_hi[l*SQ + mp*2] = pack_bf2(h0, h1);
        *(uint32_t*)&Aq_lo[l*SQ + mp*2] = pack_bf2(lo0, lo1);
    }
#pragma unroll
    for (int j = 0; j < 2; j++) {
        int idx = t + j * 256;
        int l = idx >> 4, kk = idx & 15;
        winv_s[l][kk] = winv[(((b*Ll + l0 + l)*Hh + h) << 4) + kk];
    }
    for (int idx = t; idx < 4*32*33; idx += 256) ((float*)zred)[idx] = 0.f;
    __syncthreads();

    for (int ch = 0; ch < 8; ch++) {
#pragma unroll
        for (int j = 0; j < 8; j++) {
            int idx = t + j * 256;
            int n = idx >> 5, m2 = (idx & 31) * 2;
            size_t src = ((size_t)bh * 512 + ch*64 + n) * 64 + m2;
            *(uint32_t*)&Bs_hi[n*SQ + m2] = *(const uint32_t*)&kvsT_hi[src];
            *(uint32_t*)&Bs_lo[n*SQ + m2] = *(const uint32_t*)&kvsT_lo[src];
        }
        __syncthreads();

        float dfr[2][4];
#pragma unroll
        for (int nt = 0; nt < 2; nt++)
#pragma unroll
            for (int i = 0; i < 4; i++) dfr[nt][i] = 0.f;

#pragma unroll
        for (int ks = 0; ks < 4; ks++) {
            int kb = ks * 16;
            uint32_t ah[4], al[4];
            {
                int rb = wm * 16;
                const __nv_bfloat16* p0 = &Aq_hi[(rb + g) * SQ + kb + tg*2];
                const __nv_bfloat16* p1 = &Aq_hi[(rb + g + 8) * SQ + kb + tg*2];
                ah[0] = *(const uint32_t*)p0;
                ah[1] = *(const uint32_t*)p1;
                ah[2] = *(const uint32_t*)(p0 + 8);
                ah[3] = *(const uint32_t*)(p1 + 8);
                const __nv_bfloat16* q0 = &Aq_lo[(rb + g) * SQ + kb + tg*2];
                const __nv_bfloat16* q1 = &Aq_lo[(rb + g + 8) * SQ + kb + tg*2];
                al[0] = *(const uint32_t*)q0;
                al[1] = *(const uint32_t*)q1;
                al[2] = *(const uint32_t*)(q0 + 8);
                al[3] = *(const uint32_t*)(q1 + 8);
            }
#pragma unroll
            for (int nt = 0; nt < 2; nt++) {
                int nb = wn * 16 + nt * 8;
                const __nv_bfloat16* qh = &Bs_hi[(nb + g) * SQ + kb + tg*2];
                const __nv_bfloat16* ql = &Bs_lo[(nb + g) * SQ + kb + tg*2];
                uint32_t bh2[2] = {*(const uint32_t*)qh, *(const uint32_t*)(qh + 8)};
                uint32_t bl2[2] = {*(const uint32_t*)ql, *(const uint32_t*)(ql + 8)};
                mma16816(dfr[nt], ah, bh2);
                mma16816(dfr[nt], ah, bl2);
                mma16816(dfr[nt], al, bh2);
            }
        }
        int k = ch*2 + (wn >> 1);
        int la = wm*16 + g, lb = la + 8;
        float wia = winv_s[la][k], wib = winv_s[lb][k];
#pragma unroll
        for (int nt = 0; nt < 2; nt++) {
            int dl = (wn & 1)*16 + nt*8 + tg*2;
            zred[wn][la][dl]     += dfr[nt][0] * wia;
            zred[wn][la][dl + 1] += dfr[nt][1] * wia;
            zred[wn][lb][dl]     += dfr[nt][2] * wib;
            zred[wn][lb][dl + 1] += dfr[nt][3] * wib;
        }
        __syncthreads();
    }

    float gl = ln_g[lane], bl = ln_b[lane];
#pragma unroll
    for (int j = 0; j < 4; j++) {
        int tok = warp + j * 8;
        float ss = zred[0][tok][lane] + zred[1][tok][lane]
                 + zred[2][tok][lane] + zred[3][tok][lane];
        float mu = ss;
#pragma unroll
        for (int o = 16; o > 0; o >>= 1) mu += __shfl_xor_sync(0xffffffffu, mu, o);
        mu *= (1.0f / 32.0f);
        float df = ss - mu;
        float v2 = df * df;
#pragma unroll
        for (int o = 16; o > 0; o >>= 1) v2 += __shfl_xor_sync(0xffffffffu, v2, o);
        float var = v2 * (1.0f / 32.0f);
        z[(size_t)(b*Ll + l0 + tok)*Dm + h*32 + lane] =
            df * rsqrtf(var + 1e-5f) * gl + bl;
    }
}

// ---------------- Performer feature map (FFMA2) ----------------
__global__ void phi_kernel(const float* __restrict__ din, const float* __restrict__ proj,
                           float* __restrict__ outphi, float* __restrict__ dd_out,
                           float* __restrict__ diag_out, float* __restrict__ rmax_out,
                           int is_query)
{
    __shared__ __align__(16) float proj_s[64][34];
    __shared__ __align__(16) float data_s[4][32];
    __shared__ float wmax[4][2];
    int tid = threadIdx.x;
    for (int i = tid; i < 2048; i += 256) proj_s[i >> 5][i & 31] = proj[i];
    int sub = tid >> 6;
    int m = tid & 63;
    int u0 = blockIdx.x * 16;
    for (int g = 0; g < 16; g += 4) {
        int u = u0 + g + sub;
        __syncthreads();
        if (m < 32) data_s[sub][m] = din[(size_t)u*32 + m] * PHI_SCALE;
        __syncthreads();
        ull dd2 = 0ULL, dg2 = 0ULL;
#pragma unroll
        for (int d2 = 0; d2 < 16; d2++) {
            ull x2 = *(const ull*)&data_s[sub][d2*2];
            ull p2 = *(const ull*)&proj_s[m][d2*2];
            dd2 = fma2(x2, p2, dd2);
            dg2 = fma2(x2, x2, dg2);
        }
        float2 dp = unpack2(dd2);
        float2 gp = unpack2(dg2);
        float dd = dp.x + dp.y;
        float diag = 0.5f * (gp.x + gp.y);
        float mx = dd;
#pragma unroll
        for (int o = 16; o > 0; o >>= 1) mx = fmaxf(mx, __shfl_xor_sync(0xffffffffu, mx, o));
        if ((tid & 31) == 0) wmax[sub][m >> 5] = mx;
        __syncthreads();
        float stab = fmaxf(wmax[sub][0], wmax[sub][1]);
        if (is_query) {
            outphi[(size_t)u*64 + m] = 0.125f * (expf(dd - diag - stab) + 1e-6f);
        } else {
            dd_out[(size_t)u*64 + m] = dd;
            if (m == 0) { diag_out[u] = diag; rmax_out[u] = stab; }
        }
    }
}

// ---------------- fused kmax + kp finalize ----------------
__global__ void kp_finalize(const float* __restrict__ kdd, const float* __restrict__ kdiag,
                            const float* __restrict__ krmax, float* __restrict__ kp)
{
    int bh = blockIdx.x; int b = bh >> 3, h = bh & 7;
    int t = threadIdx.x;
    __shared__ float red[256];
    float mx = -1e30f;
    for (int l = t; l < Ll; l += 256) mx = fmaxf(mx, krmax[(b*Ll + l)*Hh + h]);
    red[t] = mx; __syncthreads();
    for (int s = 128; s > 0; s >>= 1) {
        if (t < s) red[t] = fmaxf(red[t], red[t + s]);
        __syncthreads();
    }
    float km = red[0];
    for (int i = t; i < Ll * 64; i += 256) {
        int l = i >> 6, m = i & 63;
        size_t u = (size_t)(b*Ll + l)*Hh + h;
        kp[u*64 + m] = 0.125f * (expf(kdd[u*64 + m] - kdiag[u] - km) + 1e-6f);
    }
}

// ---------------- ksum[bh][k][m] = sum_l kp[l,m] * exp(gum[l,k]) ----------------
__global__ void ksum_kernel(const float* __restrict__ kp, const float* __restrict__ gum,
                            float* __restrict__ ksum)
{
    __shared__ __align__(16) float kp_s[16][64];
    __shared__ float eg_s[16][16];
    int bh = blockIdx.x; int b = bh >> 3, h = bh & 7;
    int t = threadIdx.x;
    int lc = t >> 4, lf = t & 15;
    float4 acc = make_float4(0,0,0,0);
    for (int l0 = 0; l0 < Ll; l0 += 16) {
        __syncthreads();
        *(float4*)&kp_s[lc][lf*4] =
            *(const float4*)&kp[((size_t)((b*Ll + l0 + lc)*Hh + h) << 6) + lf*4];
        eg_s[lc][lf] = expf(gum[(((b*Ll + l0 + lc)*Hh + h) << 4) + lf]);
        __syncthreads();
#pragma unroll
        for (int c = 0; c < 16; c++) {
            float e = eg_s[c][lc];
            float4 kp4 = *(const float4*)&kp_s[c][lf*4];
            acc.x += kp4.x * e; acc.y += kp4.y * e;
            acc.z += kp4.z * e; acc.w += kp4.w * e;
        }
    }
    *(float4*)&ksum[((size_t)(bh*16 + lc) << 6) + lf*4] = acc;
}

// ---------------- winv[l,k] = 1/((qp . ksum + 1e-8)*16) per bh ----------------
__global__ void winv_kernel(const float* __restrict__ qp, const float* __restrict__ ksum,
                            float* __restrict__ winv)
{
    __shared__ __align__(16) float ks_s[16][64];
    __shared__ __align__(16) float qp_s[16][64];
    int bh = blockIdx.x; int b = bh >> 3, h = bh & 7;
    int t = threadIdx.x;
    int lc = t >> 4, lf = t & 15;
    *(float4*)&ks_s[lc][lf*4] = *(const float4*)&ksum[((size_t)(bh*16 + lc) << 6) + lf*4];
    for (int l0 = 0; l0 < Ll; l0 += 16) {
        __syncthreads();
        *(float4*)&qp_s[lc][lf*4] =
            *(const float4*)&qp[((size_t)((b*Ll + l0 + lc)*Hh + h) << 6) + lf*4];
        __syncthreads();
        ull d2 = 0ULL;
#pragma unroll
        for (int m2 = 0; m2 < 32; m2++) {
            ull q2 = *(const ull*)&qp_s[lc][m2*2];
            ull k2 = *(const ull*)&ks_s[lf][m2*2];
            d2 = fma2(q2, k2, d2);
        }
        float2 dp = unpack2(d2);
        winv[(((b*Ll + l0 + lc)*Hh + h) << 4) + lf] =
            1.0f / ((dp.x + dp.y + 1e-8f) * 16.0f);
    }
}

__global__ void fused_kernel(const float* __restrict__ adj, const float* __restrict__ wpat,
                             float* __restrict__ fused)
{
    int i4 = blockIdx.x * 256 + threadIdx.x;    // < 160000
    if (i4 >= 160000) return;
    int bp = i4 / 2500;
    int r4 = i4 - bp * 2500;
    float4 s = make_float4(0,0,0,0);
#pragma unroll
    for (int t = 0; t < 8; t++) {
        float w = wpat[bp*8 + t];
        float4 a = *(const float4*)&adj[(size_t)(bp*8 + t)*10000 + r4*4];
        s.x += a.x*w; s.y += a.y*w; s.z += a.z*w; s.w += a.w*w;
    }
    *(float4*)&fused[(size_t)bp*10000 + r4*4] = s;
}

__global__ void rden_kernel(const float* __restrict__ fused, float* __restrict__ rden)
{
    int w = threadIdx.x >> 5, lane = threadIdx.x & 31;
    int row = blockIdx.x * 8 + w;
    float s = 0.f;
    for (int j = lane; j < 100; j += 32) s += fabsf(fused[(size_t)row*100 + j]);
#pragma unroll
    for (int o = 16; o > 0; o >>= 1) s += __shfl_xor_sync(0xffffffffu, s, o);
    if (lane == 0) rden[row] = fmaxf(s, 1e-12f);
}

// relational bias: z += (fused/rden) @ V (FFMA2); grid (64, 5)
__global__ void biasadd_kernel(const float* __restrict__ fused, const float* __restrict__ rden,
                               const float* __restrict__ v, float* __restrict__ z)
{
    __shared__ __align__(16) float A_s[20][102];
    int blk = blockIdx.x;
    int i0 = blockIdx.y * 20;
    int t = threadIdx.x;
    for (int idx = t; idx < 2000; idx += 256) {
        int i = idx / 100, j = idx - i * 100;
        A_s[i][j] = fused[(size_t)blk*10000 + (i0 + i)*100 + j] / rden[blk*100 + i0 + i];
    }
    __syncthreads();
    int base = blk * 100;
    ull accp[20];
#pragma unroll
    for (int ii = 0; ii < 20; ii++) accp[ii] = 0ULL;
    for (int j = 0; j < 100; j += 2) {
        float vj0 = v[(size_t)(base + j)*256 + t];
        float vj1 = v[(size_t)(base + j + 1)*256 + t];
        ull vp = pack2(vj0, vj1);
#pragma unroll
        for (int ii = 0; ii < 20; ii++)
            accp[ii] = fma2(*(const ull*)&A_s[ii][j], vp, accp[ii]);
    }
#pragma unroll
    for (int ii = 0; ii < 20; ii++) {
        float2 p = unpack2(accp[ii]);
        z[(size_t)(base + i0 + ii)*256 + t] += p.x + p.y;
    }
}

// ---------------- launcher ----------------
extern "C" void kernel_launch(void* const* d_in, const int* in_sizes, int n_in,
                              void* d_out, int out_size)
{
    const float* x     = (const float*)d_in[0];
    const float* adj   = (const float*)d_in[1];
    const float* Wq_w  = (const float*)d_in[2];
    const float* Wq_b  = (const float*)d_in[3];
    const float* Wk_w  = (const float*)d_in[4];
    const float* Wk_b  = (const float*)d_in[5];
    const float* Wv_w  = (const float*)d_in[6];
    const float* Wv_b  = (const float*)d_in[7];
    const float* Wo_w  = (const float*)d_in[8];
    const float* Wo_b  = (const float*)d_in[9];
    const float* ln_g  = (const float*)d_in[10];
    const float* ln_b  = (const float*)d_in[11];
    const float* fc_w  = (const float*)d_in[12];
    const float* fc_b  = (const float*)d_in[13];
    const float* out_w = (const float*)d_in[14];
    const float* out_b = (const float*)d_in[15];
    const float* proj  = (const float*)d_in[16];
    const float* gum   = (const float*)d_in[17];
    float* out = (float*)d_out;

    float *q, *k, *v, *qp, *kdd, *kdiag, *krmax, *kp, *ksum, *winv, *z;
    float *h1p, *gscore, *wpat, *fused, *rden;
    __nv_bfloat16 *kvsT_hi, *kvsT_lo;
    cudaGetSymbolAddress((void**)&q,     g_q);
    cudaGetSymbolAddress((void**)&k,     g_k);
    cudaGetSymbolAddress((void**)&v,     g_v);
    cudaGetSymbolAddress((void**)&qp,    g_qp);
    cudaGetSymbolAddress((void**)&kdd,   g_kdd);
    cudaGetSymbolAddress((void**)&kdiag, g_kdiag);
    cudaGetSymbolAddress((void**)&krmax, g_krmax);
    cudaGetSymbolAddress((void**)&kp,    g_kp);
    cudaGetSymbolAddress((void**)&kvsT_hi, g_kvsT_hi);
    cudaGetSymbolAddress((void**)&kvsT_lo, g_kvsT_lo);
    cudaGetSymbolAddress((void**)&ksum,  g_ksum);
    cudaGetSymbolAddress((void**)&winv,  g_winv);
    cudaGetSymbolAddress((void**)&z,     g_z);
    cudaGetSymbolAddress((void**)&h1p,   g_h1p);
    cudaGetSymbolAddress((void**)&gscore,g_gscore);
    cudaGetSymbolAddress((void**)&wpat,  g_wpat);
    cudaGetSymbolAddress((void**)&fused, g_fused);
    cudaGetSymbolAddress((void**)&rden,  g_rden);

    // 1) fc GEMM on HMMA (independent of qkv)
    fc_mma<<<dim3(4, NSPLIT), 256>>>(adj, fc_w, h1p);
    // 2) h1 split reduction + relu + dot
    hsum_kernel<<<512, 128>>>(h1p, fc_b, out_w, out_b, gscore);
    // 3) softmax over patch dim
    softmax8_kernel<<<1, 64>>>(gscore, wpat);
    // 4) fused Q/K/V projections (HMMA)  <-- profiled launch slot
    qkv_mma<<<dim3(BL/128, 2, 3), 256>>>(x, Wq_w, Wk_w, Wv_w,
                                         Wq_b, Wk_b, Wv_b, q, k, v);
    // 5) key feature map
    phi_kernel<<<BL*Hh/16, 256>>>(k, proj, nullptr, kdd, kdiag, krmax, 0);
    // 6) fused kmax + kp finalize
    kp_finalize<<<Bq*Hh, 256>>>(kdd, kdiag, krmax, kp);
    // 7) kvs on HMMA (single pass, packed staging, bf16 out)
    kvs_mma<<<dim3(Bq*Hh, 4), 256>>>(kp, v, gum, kvsT_hi, kvsT_lo);
    // 8) query feature map
    phi_kernel<<<BL*Hh/16, 256>>>(q, proj, qp, nullptr, nullptr, nullptr, 1);
    // 9) ksum, 10) winv
    ksum_kernel<<<Bq*Hh, 256>>>(kp, gum, ksum);
    winv_kernel<<<Bq*Hh, 256>>>(qp, ksum, winv);
    // 11) z on HMMA (+winv reduction + LayerNorm)
    z_mma<<<dim3(Bq*Hh, 25), 256>>>(qp, kvsT_hi, kvsT_lo, winv, z, ln_g, ln_b);
    // 12) fuse adjacency patches, 13) rden
    fused_kernel<<<(160000 + 255)/256, 256>>>(adj, wpat, fused);
    rden_kernel<<<Bq*Pp*Nn/8, 256>>>(fused, rden);
    // 14) relational bias
    biasadd_kernel<<<dim3(Bq*Pp, 5), 256>>>(fused, rden, v, z);
    // 15) output projection (HMMA)
    wo_mma<<<dim3(BL/128, 2), 256>>>(z, Wo_w, Wo_b, out);
}

// round 12
// speedup vs baseline: 1.4295x; 1.4295x over previous
#include <cuda_runtime.h>
#include <cuda_bf16.h>
#include <math.h>
#include <stdint.h>

// ---------------- static problem config ----------------
#define Bq    8
#define Pp    8
#define Nn    100
#define Dm    256
#define Hh    8
#define DKk   32
#define Mm    64
#define Kg    16
#define Ll    800            // P*N
#define BL    6400           // B*L
#define NSPLIT 125
#define KCHUNK 80            // 125*80 = 10000

#define PHI_SCALE 0.84089641525f   // 2 * 32^-0.25
#define KVS_ELEMS (64*512*64)

typedef unsigned long long ull;

// ---------------- packed f32x2 helpers ----------------
__device__ __forceinline__ ull pack2(float x, float y) {
    ull r; asm("mov.b64 %0, {%1,%2};" : "=l"(r) : "f"(x), "f"(y)); return r;
}
__device__ __forceinline__ ull fma2(ull a, ull b, ull c) {
    ull d; asm("fma.rn.f32x2 %0, %1, %2, %3;" : "=l"(d) : "l"(a), "l"(b), "l"(c)); return d;
}
__device__ __forceinline__ float2 unpack2(ull p) {
    float2 r; asm("mov.b64 {%0,%1}, %2;" : "=f"(r.x), "=f"(r.y) : "l"(p)); return r;
}

// ---------------- scratch (device globals; no allocation) ----------------
__device__ __align__(16) float g_q   [BL*Dm];
__device__ __align__(16) float g_k   [BL*Dm];
__device__ __align__(16) float g_v   [BL*Dm];
__device__ __align__(16) float g_qp  [BL*Hh*Mm];
__device__ __align__(16) float g_kdd [BL*Hh*Mm];
__device__              float g_kdiag[BL*Hh];
__device__              float g_krmax[BL*Hh];
__device__ __align__(16) float g_kp  [BL*Hh*Mm];
__device__ __align__(16) __nv_bfloat16 g_kvsT_hi[KVS_ELEMS];
__device__ __align__(16) __nv_bfloat16 g_kvsT_lo[KVS_ELEMS];
__device__ __align__(16) float g_ksum[Bq*Hh*Kg*Mm];
__device__ __align__(16) float g_winv[BL*Hh*Kg];
__device__ __align__(16) float g_z   [BL*Dm];
__device__ __align__(16) float g_h1p [NSPLIT*512*128];
__device__              float g_wpat [512];
__device__ __align__(16) float g_fused[Bq*Pp*Nn*Nn];
__device__              float g_rden [Bq*Pp*Nn];

// ================= mma.sync primitive =================
__device__ __forceinline__ void mma16816(float* d, const uint32_t* a, const uint32_t* b)
{
    asm volatile(
        "mma.sync.aligned.m16n8k16.row.col.f32.bf16.bf16.f32 "
        "{%0,%1,%2,%3}, {%4,%5,%6,%7}, {%8,%9}, {%0,%1,%2,%3};"
        : "+f"(d[0]), "+f"(d[1]), "+f"(d[2]), "+f"(d[3])
        : "r"(a[0]), "r"(a[1]), "r"(a[2]), "r"(a[3]), "r"(b[0]), "r"(b[1]));
}

__device__ __forceinline__ void bf16_split(float f, __nv_bfloat16& hi, __nv_bfloat16& lo)
{
    hi = __float2bfloat16(f);
    lo = __float2bfloat16(f - __bfloat162float(hi));
}
__device__ __forceinline__ uint32_t pack_bf2(__nv_bfloat16 a, __nv_bfloat16 b)
{
    __nv_bfloat162 p = __halves2bfloat162(a, b);
    return reinterpret_cast<uint32_t&>(p);
}

// ================= projection GEMM (bf16x3, proven in R6) =================
#define SMS 40

__device__ __forceinline__ void load_slab32(const float* __restrict__ src,
                                            __nv_bfloat16* __restrict__ hi,
                                            __nv_bfloat16* __restrict__ lo, int tid)
{
    for (int idx = tid; idx < 1024; idx += 256) {
        int r = idx >> 3, c4 = (idx & 7) * 4;
        float4 f = *(const float4*)(src + (size_t)r * 256 + c4);
        __nv_bfloat16 h0, l0, h1, l1, h2, l2, h3, l3;
        bf16_split(f.x, h0, l0); bf16_split(f.y, h1, l1);
        bf16_split(f.z, h2, l2); bf16_split(f.w, h3, l3);
        uint2 hw = make_uint2(pack_bf2(h0, h1), pack_bf2(h2, h3));
        uint2 lw = make_uint2(pack_bf2(l0, l1), pack_bf2(l2, l3));
        *(uint2*)(hi + r * SMS + c4) = hw;
        *(uint2*)(lo + r * SMS + c4) = lw;
    }
}

__device__ __forceinline__ void mma_gemm_body(const float* __restrict__ A,
                                              const float* __restrict__ W,
                                              const float* __restrict__ bias,
                                              float* __restrict__ C)
{
    __shared__ __align__(16) __nv_bfloat16 sm[4 * 128 * SMS];
    __nv_bfloat16* Ah = sm;
    __nv_bfloat16* Al = sm + 128 * SMS;
    __nv_bfloat16* Wh = sm + 2 * 128 * SMS;
    __nv_bfloat16* Wl = sm + 3 * 128 * SMS;

    int tid = threadIdx.x, lane = tid & 31, warp = tid >> 5;
    int wm = warp & 3, wn = warp >> 2;
    int row0 = blockIdx.x * 128, col0 = blockIdx.y * 128;
    int g = lane >> 2, tg = lane & 3;

    float d[2][8][4];
#pragma unroll
    for (int mt = 0; mt < 2; mt++)
#pragma unroll
        for (int nt = 0; nt < 8; nt++)
#pragma unroll
            for (int i = 0; i < 4; i++) d[mt][nt][i] = 0.f;

    for (int kc = 0; kc < 8; kc++) {
        load_slab32(A + (size_t)row0 * 256 + kc * 32, Ah, Al, tid);
        load_slab32(W + (size_t)col0 * 256 + kc * 32, Wh, Wl, tid);
        __syncthreads();
#pragma unroll
        for (int ks = 0; ks < 2; ks++) {
            int kb = ks * 16;
            uint32_t ah[2][4], al[2][4];
#pragma unroll
            for (int mt = 0; mt < 2; mt++) {
                int rb = wm * 32 + mt * 16;
                const __nv_bfloat16* p0 = &Ah[(rb + g) * SMS + kb + tg * 2];
                const __nv_bfloat16* p1 = &Ah[(rb + g + 8) * SMS + kb + tg * 2];
                ah[mt][0] = *(const uint32_t*)p0;
                ah[mt][1] = *(const uint32_t*)p1;
                ah[mt][2] = *(const uint32_t*)(p0 + 8);
                ah[mt][3] = *(const uint32_t*)(p1 + 8);
                const __nv_bfloat16* q0 = &Al[(rb + g) * SMS + kb + tg * 2];
                const __nv_bfloat16* q1 = &Al[(rb + g + 8) * SMS + kb + tg * 2];
                al[mt][0] = *(const uint32_t*)q0;
                al[mt][1] = *(const uint32_t*)q1;
                al[mt][2] = *(const uint32_t*)(q0 + 8);
                al[mt][3] = *(const uint32_t*)(q1 + 8);
            }
#pragma unroll
            for (int nt = 0; nt < 8; nt++) {
                int nb = wn * 64 + nt * 8;
                const __nv_bfloat16* qh = &Wh[(nb + g) * SMS + kb + tg * 2];
                const __nv_bfloat16* ql = &Wl[(nb + g) * SMS + kb + tg * 2];
                uint32_t bh2[2] = {*(const uint32_t*)qh, *(const uint32_t*)(qh + 8)};
                uint32_t bl2[2] = {*(const uint32_t*)ql, *(const uint32_t*)(ql + 8)};
#pragma unroll
                for (int mt = 0; mt < 2; mt++) {
                    mma16816(d[mt][nt], ah[mt], bh2);
                    mma16816(d[mt][nt], ah[mt], bl2);
                    mma16816(d[mt][nt], al[mt], bh2);
                }
            }
        }
        __syncthreads();
    }

#pragma unroll
    for (int mt = 0; mt < 2; mt++) {
        int r0 = row0 + wm * 32 + mt * 16 + g;
#pragma unroll
        for (int nt = 0; nt < 8; nt++) {
            int col = col0 + wn * 64 + nt * 8 + tg * 2;
            float2 b2 = *(const float2*)&bias[col];
            float2 o0 = make_float2(d[mt][nt][0] + b2.x, d[mt][nt][1] + b2.y);
            float2 o1 = make_float2(d[mt][nt][2] + b2.x, d[mt][nt][3] + b2.y);
            *(float2*)&C[(size_t)r0 * 256 + col]       = o0;
            *(float2*)&C[(size_t)(r0 + 8) * 256 + col] = o1;
        }
    }
}

__global__ void __launch_bounds__(256) qkv_mma(
    const float* __restrict__ x,
    const float* __restrict__ Wq, const float* __restrict__ Wk, const float* __restrict__ Wv,
    const float* __restrict__ bq, const float* __restrict__ bk, const float* __restrict__ bv,
    float* __restrict__ q, float* __restrict__ k, float* __restrict__ v)
{
    const float* W = blockIdx.z == 0 ? Wq : (blockIdx.z == 1 ? Wk : Wv);
    const float* b = blockIdx.z == 0 ? bq : (blockIdx.z == 1 ? bk : bv);
    float* C       = blockIdx.z == 0 ? q  : (blockIdx.z == 1 ? k  : v);
    mma_gemm_body(x, W, b, C);
}

__global__ void __launch_bounds__(256) wo_mma(
    const float* __restrict__ A, const float* __restrict__ W,
    const float* __restrict__ b, float* __restrict__ C)
{
    mma_gemm_body(A, W, b, C);
}

// ================= kvs on HMMA, single pass, packed staging =================
// grid (64 bh, 4 q). Direct transposed bf16 hi/lo output.
#define SA 36
__global__ void __launch_bounds__(256) kvs_mma(
    const float* __restrict__ kp, const float* __restrict__ v,
    const float* __restrict__ gum,
    __nv_bfloat16* __restrict__ kvsT_hi, __nv_bfloat16* __restrict__ kvsT_lo)
{
    __shared__ __align__(16) __nv_bfloat16 As_hi[64*SA], As_lo[64*SA];
    __shared__ __align__(16) __nv_bfloat16 Bs_hi[128*SA], Bs_lo[128*SA];
    __shared__ float v_s[32][32];
    __shared__ float e_s[32][4];

    int bh = blockIdx.x, q = blockIdx.y;
    int b = bh >> 3, h = bh & 7;
    int t = threadIdx.x, lane = t & 31, warp = t >> 5;
    int wm = warp & 3, wn = warp >> 2;
    int g = lane >> 2, tg = lane & 3;

    float d[8][4];
#pragma unroll
    for (int nt = 0; nt < 8; nt++)
#pragma unroll
        for (int i = 0; i < 4; i++) d[nt][i] = 0.f;

    for (int l0 = 0; l0 < Ll; l0 += 32) {
        __syncthreads();
        // stage v, e
        {
            int l = t >> 3, d4 = (t & 7) * 4;
            *(float4*)&v_s[l][d4] =
                *(const float4*)&v[(size_t)(b*Ll + l0 + l)*Dm + h*32 + d4];
        }
        if (t < 128) {
            int l = t >> 2, kq = t & 3;
            e_s[l][kq] = expf(gum[(((b*Ll + l0 + l)*Hh + h) << 4) + q*4 + kq]);
        }
        // stage A = kp^T packed (2 l's per u32)
#pragma unroll
        for (int j = 0; j < 4; j++) {
            int idx = t + j * 256;          // < 1024
            int m = idx & 63, lp = idx >> 6;
            int l = l0 + lp * 2;
            float f0 = kp[((size_t)((b*Ll + l    )*Hh + h) << 6) + m];
            float f1 = kp[((size_t)((b*Ll + l + 1)*Hh + h) << 6) + m];
            __nv_bfloat16 h0, lo0, h1, lo1;
            bf16_split(f0, h0, lo0); bf16_split(f1, h1, lo1);
            *(uint32_t*)&As_hi[m*SA + lp*2] = pack_bf2(h0, h1);
            *(uint32_t*)&As_lo[m*SA + lp*2] = pack_bf2(lo0, lo1);
        }
        __syncthreads();
        // build B[n=kd][l] = e[l, n>>5] * v[l, n&31], packed (2 l's per u32)
        {
            int n = t >> 1;
            int lpb = (t & 1) * 8;
            int kq = n >> 5, dd = n & 31;
#pragma unroll
            for (int j = 0; j < 8; j++) {
                int lp = lpb + j;
                float f0 = e_s[2*lp][kq]     * v_s[2*lp][dd];
                float f1 = e_s[2*lp + 1][kq] * v_s[2*lp + 1][dd];
                __nv_bfloat16 h0, lo0, h1, lo1;
                bf16_split(f0, h0, lo0); bf16_split(f1, h1, lo1);
                *(uint32_t*)&Bs_hi[n*SA + lp*2] = pack_bf2(h0, h1);
                *(uint32_t*)&Bs_lo[n*SA + lp*2] = pack_bf2(lo0, lo1);
            }
        }
        __syncthreads();
        // MMA: warp tile 16m x 64n
#pragma unroll
        for (int ks = 0; ks < 2; ks++) {
            int kb = ks * 16;
            uint32_t ah[4], al[4];
            {
                int rb = wm * 16;
                const __nv_bfloat16* p0 = &As_hi[(rb + g) * SA + kb + tg*2];
                const __nv_bfloat16* p1 = &As_hi[(rb + g + 8) * SA + kb + tg*2];
                ah[0] = *(const uint32_t*)p0;
                ah[1] = *(const uint32_t*)p1;
                ah[2] = *(const uint32_t*)(p0 + 8);
                ah[3] = *(const uint32_t*)(p1 + 8);
                const __nv_bfloat16* q0 = &As_lo[(rb + g) * SA + kb + tg*2];
                const __nv_bfloat16* q1 = &As_lo[(rb + g + 8) * SA + kb + tg*2];
                al[0] = *(const uint32_t*)q0;
                al[1] = *(const uint32_t*)q1;
                al[2] = *(const uint32_t*)(q0 + 8);
                al[3] = *(const uint32_t*)(q1 + 8);
            }
#pragma unroll
            for (int nt = 0; nt < 8; nt++) {
                int nb = wn * 64 + nt * 8;
                const __nv_bfloat16* qh = &Bs_hi[(nb + g) * SA + kb + tg*2];
                const __nv_bfloat16* ql = &Bs_lo[(nb + g) * SA + kb + tg*2];
                uint32_t bh2[2] = {*(const uint32_t*)qh, *(const uint32_t*)(qh + 8)};
                uint32_t bl2[2] = {*(const uint32_t*)ql, *(const uint32_t*)(ql + 8)};
                mma16816(d[nt], ah, bh2);
                mma16816(d[nt], ah, bl2);
                mma16816(d[nt], al, bh2);
            }
        }
    }
    // epilogue: store transposed [kd][m] hi/lo
    int m = wm * 16 + g;
#pragma unroll
    for (int nt = 0; nt < 8; nt++) {
        int n = q*128 + wn*64 + nt*8 + tg*2;
        size_t base0 = ((size_t)bh * 512 + n) * 64;
        size_t base1 = base0 + 64;   // n+1
        __nv_bfloat16 hi, lo;
        bf16_split(d[nt][0], hi, lo); kvsT_hi[base0 + m] = hi;     kvsT_lo[base0 + m] = lo;
        bf16_split(d[nt][1], hi, lo); kvsT_hi[base1 + m] = hi;     kvsT_lo[base1 + m] = lo;
        bf16_split(d[nt][2], hi, lo); kvsT_hi[base0 + m + 8] = hi; kvsT_lo[base0 + m + 8] = lo;
        bf16_split(d[nt][3], hi, lo); kvsT_hi[base1 + m + 8] = hi; kvsT_lo[base1 + m + 8] = lo;
    }
}

// ================= z on HMMA + winv reduction + LayerNorm =================
#define SQ 68
__global__ void __launch_bounds__(256) z_mma(
    const float* __restrict__ qp,
    const __nv_bfloat16* __restrict__ kvsT_hi, const __nv_bfloat16* __restrict__ kvsT_lo,
    const float* __restrict__ winv, float* __restrict__ z,
    const float* __restrict__ ln_g, const float* __restrict__ ln_b)
{
    __shared__ __align__(16) __nv_bfloat16 Aq_hi[32*SQ], Aq_lo[32*SQ];
    __shared__ __align__(16) __nv_bfloat16 Bs_hi[64*SQ], Bs_lo[64*SQ];
    __shared__ float winv_s[32][16];
    __shared__ float zred[4][32][33];

    int bh = blockIdx.x;
    int b = bh >> 3, h = bh & 7;
    int l0 = blockIdx.y * 32;
    int t = threadIdx.x, lane = t & 31, warp = t >> 5;
    int wm = warp & 1, wn = warp >> 1;       // 2 x 4 warps; warp tile 16l x 16n
    int g = lane >> 2, tg = lane & 3;

    // stage A = qp tile [32 l][64 m] hi/lo
#pragma unroll
    for (int j = 0; j < 2; j++) {
        int idx = t + j * 256;
        int l = idx >> 4, m4 = (idx & 15) * 4;
        float4 q4 = *(const float4*)&qp[((size_t)((b*Ll + l0 + l)*Hh + h) << 6) + m4];
        float fv[4] = {q4.x, q4.y, q4.z, q4.w};
#pragma unroll
        for (int i = 0; i < 4; i++) {
            __nv_bfloat16 hi, lo; bf16_split(fv[i], hi, lo);
            Aq_hi[l*SQ + m4 + i] = hi;
            Aq_lo[l*SQ + m4 + i] = lo;
        }
    }
    // stage winv
#pragma unroll
    for (int j = 0; j < 2; j++) {
        int idx = t + j * 256;
        int l = idx >> 4, kk = idx & 15;
        winv_s[l][kk] = winv[(((b*Ll + l0 + l)*Hh + h) << 4) + kk];
    }
    // zero zred
    for (int idx = t; idx < 4*32*33; idx += 256) ((float*)zred)[idx] = 0.f;
    __syncthreads();

    for (int ch = 0; ch < 8; ch++) {
        // stage B chunk [64 n][64 m] from kvsT (already bf16 hi/lo)
#pragma unroll
        for (int j = 0; j < 8; j++) {
            int idx = t + j * 256;           // < 2048 u32
            int n = idx >> 5, m2 = (idx & 31) * 2;
            size_t src = ((size_t)bh * 512 + ch*64 + n) * 64 + m2;
            *(uint32_t*)&Bs_hi[n*SQ + m2] = *(const uint32_t*)&kvsT_hi[src];
            *(uint32_t*)&Bs_lo[n*SQ + m2] = *(const uint32_t*)&kvsT_lo[src];
        }
        __syncthreads();

        float dfr[2][4];
#pragma unroll
        for (int nt = 0; nt < 2; nt++)
#pragma unroll
            for (int i = 0; i < 4; i++) dfr[nt][i] = 0.f;

#pragma unroll
        for (int ks = 0; ks < 4; ks++) {
            int kb = ks * 16;
            uint32_t ah[4], al[4];
            {
                int rb = wm * 16;
                const __nv_bfloat16* p0 = &Aq_hi[(rb + g) * SQ + kb + tg*2];
                const __nv_bfloat16* p1 = &Aq_hi[(rb + g + 8) * SQ + kb + tg*2];
                ah[0] = *(const uint32_t*)p0;
                ah[1] = *(const uint32_t*)p1;
                ah[2] = *(const uint32_t*)(p0 + 8);
                ah[3] = *(const uint32_t*)(p1 + 8);
                const __nv_bfloat16* q0 = &Aq_lo[(rb + g) * SQ + kb + tg*2];
                const __nv_bfloat16* q1 = &Aq_lo[(rb + g + 8) * SQ + kb + tg*2];
                al[0] = *(const uint32_t*)q0;
                al[1] = *(const uint32_t*)q1;
                al[2] = *(const uint32_t*)(q0 + 8);
                al[3] = *(const uint32_t*)(q1 + 8);
            }
#pragma unroll
            for (int nt = 0; nt < 2; nt++) {
                int nb = wn * 16 + nt * 8;
                const __nv_bfloat16* qh = &Bs_hi[(nb + g) * SQ + kb + tg*2];
                const __nv_bfloat16* ql = &Bs_lo[(nb + g) * SQ + kb + tg*2];
                uint32_t bh2[2] = {*(const uint32_t*)qh, *(const uint32_t*)(qh + 8)};
                uint32_t bl2[2] = {*(const uint32_t*)ql, *(const uint32_t*)(ql + 8)};
                mma16816(dfr[nt], ah, bh2);
                mma16816(dfr[nt], ah, bl2);
                mma16816(dfr[nt], al, bh2);
            }
        }
        // winv-weighted k reduction into zred
        int k = ch*2 + (wn >> 1);
        int la = wm*16 + g, lb = la + 8;
        float wia = winv_s[la][k], wib = winv_s[lb][k];
#pragma unroll
        for (int nt = 0; nt < 2; nt++) {
            int dl = (wn & 1)*16 + nt*8 + tg*2;
            zred[wn][la][dl]     += dfr[nt][0] * wia;
            zred[wn][la][dl + 1] += dfr[nt][1] * wia;
            zred[wn][lb][dl]     += dfr[nt][2] * wib;
            zred[wn][lb][dl + 1] += dfr[nt][3] * wib;
        }
        __syncthreads();
    }

    // final sum over wn + LayerNorm (warp per token, 4 tokens/warp)
    float gl = ln_g[lane], bl = ln_b[lane];
#pragma unroll
    for (int j = 0; j < 4; j++) {
        int tok = warp + j * 8;
        float ss = zred[0][tok][lane] + zred[1][tok][lane]
                 + zred[2][tok][lane] + zred[3][tok][lane];
        float mu = ss;
#pragma unroll
        for (int o = 16; o > 0; o >>= 1) mu += __shfl_xor_sync(0xffffffffu, mu, o);
        mu *= (1.0f / 32.0f);
        float df = ss - mu;
        float v2 = df * df;
#pragma unroll
        for (int o = 16; o > 0; o >>= 1) v2 += __shfl_xor_sync(0xffffffffu, v2, o);
        float var = v2 * (1.0f / 32.0f);
        z[(size_t)(b*Ll + l0 + tok)*Dm + h*32 + lane] =
            df * rsqrtf(var + 1e-5f) * gl + bl;
    }
}

// ======== fp32 GEMM (fc split-K): 128x128 tile, BK=16, FFMA2, dbuf ========
__device__ __forceinline__ void gemm128(const float* __restrict__ A,
                                        const float* __restrict__ W,
                                        float* __restrict__ C,
                                        int Nc, int Kd, int k0, int klen)
{
    __shared__ __align__(16) float As[2][16][132];
    __shared__ __align__(16) float Ws[2][16][132];
    int tid = threadIdx.x;
    int tx = tid & 15, ty = tid >> 4;
    int row0 = blockIdx.x * 128, col0 = blockIdx.y * 128;
    int lr = tid >> 1, lc = (tid & 1) * 8;

    const float* Ap = A + (size_t)(row0 + lr) * Kd + k0 + lc;
    const float* Wp = W + (size_t)(col0 + lr) * Kd + k0 + lc;

    ull acc[8][4];
#pragma unroll
    for (int i = 0; i < 8; i++)
#pragma unroll
        for (int j = 0; j < 4; j++) acc[i][j] = 0ULL;

    float4 pa0 = *(const float4*)(Ap);
    float4 pa1 = *(const float4*)(Ap + 4);
    float4 pw0 = *(const float4*)(Wp);
    float4 pw1 = *(const float4*)(Wp + 4);

    int nk = klen >> 4;
    int buf = 0;
    for (int it = 0; it < nk; it++) {
        As[buf][lc+0][lr] = pa0.x; As[buf][lc+1][lr] = pa0.y;
        As[buf][lc+2][lr] = pa0.z; As[buf][lc+3][lr] = pa0.w;
        As[buf][lc+4][lr] = pa1.x; As[buf][lc+5][lr] = pa1.y;
        As[buf][lc+6][lr] = pa1.z; As[buf][lc+7][lr] = pa1.w;
        Ws[buf][lc+0][lr] = pw0.x; Ws[buf][lc+1][lr] = pw0.y;
        Ws[buf][lc+2][lr] = pw0.z; Ws[buf][lc+3][lr] = pw0.w;
        Ws[buf][lc+4][lr] = pw1.x; Ws[buf][lc+5][lr] = pw1.y;
        Ws[buf][lc+6][lr] = pw1.z; Ws[buf][lc+7][lr] = pw1.w;
        __syncthreads();
        if (it + 1 < nk) {
            int off = (it + 1) * 16;
            pa0 = *(const float4*)(Ap + off);
            pa1 = *(const float4*)(Ap + off + 4);
            pw0 = *(const float4*)(Wp + off);
            pw1 = *(const float4*)(Wp + off + 4);
        }
#pragma unroll
        for (int c = 0; c < 16; c++) {
            float4 a0 = *(const float4*)&As[buf][c][ty*4];
            float4 a1 = *(const float4*)&As[buf][c][64 + ty*4];
            ulonglong2 w01 = *(const ulonglong2*)&Ws[buf][c][tx*4];
            ulonglong2 w23 = *(const ulonglong2*)&Ws[buf][c][64 + tx*4];
            ull wp[4] = {w01.x, w01.y, w23.x, w23.y};
            float av[8] = {a0.x,a0.y,a0.z,a0.w, a1.x,a1.y,a1.z,a1.w};
#pragma unroll
            for (int i = 0; i < 8; i++) {
                ull ad = pack2(av[i], av[i]);
#pragma unroll
                for (int j = 0; j < 4; j++) acc[i][j] = fma2(ad, wp[j], acc[i][j]);
            }
        }
        buf ^= 1;
        __syncthreads();
    }

#pragma unroll
    for (int i = 0; i < 8; i++) {
        int rr = row0 + ((i < 4) ? (ty*4 + i) : (64 + ty*4 + i - 4));
        float2 p0 = unpack2(acc[i][0]);
        float2 p1 = unpack2(acc[i][1]);
        float2 p2 = unpack2(acc[i][2]);
        float2 p3 = unpack2(acc[i][3]);
        float4 o0 = make_float4(p0.x, p0.y, p1.x, p1.y);
        float4 o1 = make_float4(p2.x, p2.y, p3.x, p3.y);
        *(float4*)&C[(size_t)rr * Nc + col0 + tx*4]      = o0;
        *(float4*)&C[(size_t)rr * Nc + col0 + 64 + tx*4] = o1;
    }
}

__global__ void gemm_sk(const float* __restrict__ A, const float* __restrict__ W,
                        float* __restrict__ C, int Mr, int Nc, int Kd, int klen)
{
    gemm128(A, W, C + (size_t)blockIdx.z * (size_t)Mr * Nc,
            Nc, Kd, blockIdx.z * klen, klen);
}

// ---------------- Performer feature map (FFMA2) ----------------
__global__ void phi_kernel(const float* __restrict__ din, const float* __restrict__ proj,
                           float* __restrict__ outphi, float* __restrict__ dd_out,
                           float* __restrict__ diag_out, float* __restrict__ rmax_out,
                           int is_query)
{
    __shared__ __align__(16) float proj_s[64][34];
    __shared__ __align__(16) float data_s[4][32];
    __shared__ float wmax[4][2];
    int tid = threadIdx.x;
    for (int i = tid; i < 2048; i += 256) proj_s[i >> 5][i & 31] = proj[i];
    int sub = tid >> 6;
    int m = tid & 63;
    int u0 = blockIdx.x * 16;
    for (int g = 0; g < 16; g += 4) {
        int u = u0 + g + sub;
        __syncthreads();
        if (m < 32) data_s[sub][m] = din[(size_t)u*32 + m] * PHI_SCALE;
        __syncthreads();
        ull dd2 = 0ULL, dg2 = 0ULL;
#pragma unroll
        for (int d2 = 0; d2 < 16; d2++) {
            ull x2 = *(const ull*)&data_s[sub][d2*2];
            ull p2 = *(const ull*)&proj_s[m][d2*2];
            dd2 = fma2(x2, p2, dd2);
            dg2 = fma2(x2, x2, dg2);
        }
        float2 dp = unpack2(dd2);
        float2 gp = unpack2(dg2);
        float dd = dp.x + dp.y;
        float diag = 0.5f * (gp.x + gp.y);
        float mx = dd;
#pragma unroll
        for (int o = 16; o > 0; o >>= 1) mx = fmaxf(mx, __shfl_xor_sync(0xffffffffu, mx, o));
        if ((tid & 31) == 0) wmax[sub][m >> 5] = mx;
        __syncthreads();
        float stab = fmaxf(wmax[sub][0], wmax[sub][1]);
        if (is_query) {
            outphi[(size_t)u*64 + m] = 0.125f * (expf(dd - diag - stab) + 1e-6f);
        } else {
            dd_out[(size_t)u*64 + m] = dd;
            if (m == 0) { diag_out[u] = diag; rmax_out[u] = stab; }
        }
    }
}

// ---------------- fused kmax + kp finalize ----------------
__global__ void kp_finalize(const float* __restrict__ kdd, const float* __restrict__ kdiag,
                            const float* __restrict__ krmax, float* __restrict__ kp)
{
    int bh = blockIdx.x; int b = bh >> 3, h = bh & 7;
    int t = threadIdx.x;
    __shared__ float red[256];
    float mx = -1e30f;
    for (int l = t; l < Ll; l += 256) mx = fmaxf(mx, krmax[(b*Ll + l)*Hh + h]);
    red[t] = mx; __syncthreads();
    for (int s = 128; s > 0; s >>= 1) {
        if (t < s) red[t] = fmaxf(red[t], red[t + s]);
        __syncthreads();
    }
    float km = red[0];
    for (int i = t; i < Ll * 64; i += 256) {
        int l = i >> 6, m = i & 63;
        size_t u = (size_t)(b*Ll + l)*Hh + h;
        kp[u*64 + m] = 0.125f * (expf(kdd[u*64 + m] - kdiag[u] - km) + 1e-6f);
    }
}

// ---------------- ksum[bh][k][m] = sum_l kp[l,m] * exp(gum[l,k]) ----------------
__global__ void ksum_kernel(const float* __restrict__ kp, const float* __restrict__ gum,
                            float* __restrict__ ksum)
{
    __shared__ __align__(16) float kp_s[16][64];
    __shared__ float eg_s[16][16];
    int bh = blockIdx.x; int b = bh >> 3, h = bh & 7;
    int t = threadIdx.x;
    int lc = t >> 4, lf = t & 15;
    float4 acc = make_float4(0,0,0,0);
    for (int l0 = 0; l0 < Ll; l0 += 16) {
        __syncthreads();
        *(float4*)&kp_s[lc][lf*4] =
            *(const float4*)&kp[((size_t)((b*Ll + l0 + lc)*Hh + h) << 6) + lf*4];
        eg_s[lc][lf] = expf(gum[(((b*Ll + l0 + lc)*Hh + h) << 4) + lf]);
        __syncthreads();
#pragma unroll
        for (int c = 0; c < 16; c++) {
            float e = eg_s[c][lc];
            float4 kp4 = *(const float4*)&kp_s[c][lf*4];
            acc.x += kp4.x * e; acc.y += kp4.y * e;
            acc.z += kp4.z * e; acc.w += kp4.w * e;
        }
    }
    *(float4*)&ksum[((size_t)(bh*16 + lc) << 6) + lf*4] = acc;
}

// ---------------- winv[l,k] = 1/((qp . ksum + 1e-8)*16) per bh ----------------
__global__ void winv_kernel(const float* __restrict__ qp, const float* __restrict__ ksum,
                            float* __restrict__ winv)
{
    __shared__ __align__(16) float ks_s[16][64];
    __shared__ __align__(16) float qp_s[16][64];
    int bh = blockIdx.x; int b = bh >> 3, h = bh & 7;
    int t = threadIdx.x;
    int lc = t >> 4, lf = t & 15;
    *(float4*)&ks_s[lc][lf*4] = *(const float4*)&ksum[((size_t)(bh*16 + lc) << 6) + lf*4];
    for (int l0 = 0; l0 < Ll; l0 += 16) {
        __syncthreads();
        *(float4*)&qp_s[lc][lf*4] =
            *(const float4*)&qp[((size_t)((b*Ll + l0 + lc)*Hh + h) << 6) + lf*4];
        __syncthreads();
        ull d2 = 0ULL;
#pragma unroll
        for (int m2 = 0; m2 < 32; m2++) {
            ull q2 = *(const ull*)&qp_s[lc][m2*2];
            ull k2 = *(const ull*)&ks_s[lf][m2*2];
            d2 = fma2(q2, k2, d2);
        }
        float2 dp = unpack2(d2);
        winv[(((b*Ll + l0 + lc)*Hh + h) << 4) + lf] =
            1.0f / ((dp.x + dp.y + 1e-8f) * 16.0f);
    }
}

// ---------------- patch score + softmax over patch dim ----------------
__global__ void score_kernel(const float* __restrict__ h1p, const float* __restrict__ fc_b,
                             const float* __restrict__ out_w, const float* __restrict__ out_b,
                             float* __restrict__ wout)
{
    int bp = blockIdx.x;
    int t = threadIdx.x >> 5, lane = threadIdx.x & 31;
    __shared__ float sc[8];
    float p = 0.f;
    for (int j = lane; j < 128; j += 32) {
        float hv = fc_b[j];
        for (int s = 0; s < NSPLIT; s++) hv += h1p[(size_t)s*65536 + (bp*8 + t)*128 + j];
        hv = fmaxf(hv, 0.f);
        p += hv * out_w[j];
    }
#pragma unroll
    for (int o = 16; o > 0; o >>= 1) p += __shfl_xor_sync(0xffffffffu, p, o);
    if (lane == 0) sc[t] = p + out_b[0];
    __syncthreads();
    if (threadIdx.x == 0) {
        float mx = sc[0];
#pragma unroll
        for (int i = 1; i < 8; i++) mx = fmaxf(mx, sc[i]);
        float e[8], sum = 0.f;
#pragma unroll
        for (int i = 0; i < 8; i++) { e[i] = expf(sc[i] - mx); sum += e[i]; }
#pragma unroll
        for (int i = 0; i < 8; i++) wout[bp*8 + i] = e[i] / sum;
    }
}

__global__ void fused_kernel(const float* __restrict__ adj, const float* __restrict__ wpat,
                             float* __restrict__ fused)
{
    int i4 = blockIdx.x * 256 + threadIdx.x;    // < 160000
    if (i4 >= 160000) return;
    int bp = i4 / 2500;
    int r4 = i4 - bp * 2500;
    float4 s = make_float4(0,0,0,0);
#pragma unroll
    for (int t = 0; t < 8; t++) {
        float w = wpat[bp*8 + t];
        float4 a = *(const float4*)&adj[(size_t)(bp*8 + t)*10000 + r4*4];
        s.x += a.x*w; s.y += a.y*w; s.z += a.z*w; s.w += a.w*w;
    }
    *(float4*)&fused[(size_t)bp*10000 + r4*4] = s;
}

__global__ void rden_kernel(const float* __restrict__ fused, float* __restrict__ rden)
{
    int w = threadIdx.x >> 5, lane = threadIdx.x & 31;
    int row = blockIdx.x * 8 + w;
    float s = 0.f;
    for (int j = lane; j < 100; j += 32) s += fabsf(fused[(size_t)row*100 + j]);
#pragma unroll
    for (int o = 16; o > 0; o >>= 1) s += __shfl_xor_sync(0xffffffffu, s, o);
    if (lane == 0) rden[row] = fmaxf(s, 1e-12f);
}

// relational bias: z += (fused/rden) @ V (FFMA2); grid (64, 5)
__global__ void biasadd_kernel(const float* __restrict__ fused, const float* __restrict__ rden,
                               const float* __restrict__ v, float* __restrict__ z)
{
    __shared__ __align__(16) float A_s[20][102];
    int blk = blockIdx.x;
    int i0 = blockIdx.y * 20;
    int t = threadIdx.x;
    for (int idx = t; idx < 2000; idx += 256) {
        int i = idx / 100, j = idx - i * 100;
        A_s[i][j] = fused[(size_t)blk*10000 + (i0 + i)*100 + j] / rden[blk*100 + i0 + i];
    }
    __syncthreads();
    int base = blk * 100;
    ull accp[20];
#pragma unroll
    for (int ii = 0; ii < 20; ii++) accp[ii] = 0ULL;
    for (int j = 0; j < 100; j += 2) {
        float vj0 = v[(size_t)(base + j)*256 + t];
        float vj1 = v[(size_t)(base + j + 1)*256 + t];
        ull vp = pack2(vj0, vj1);
#pragma unroll
        for (int ii = 0; ii < 20; ii++)
            accp[ii] = fma2(*(const ull*)&A_s[ii][j], vp, accp[ii]);
    }
#pragma unroll
    for (int ii = 0; ii < 20; ii++) {
        float2 p = unpack2(accp[ii]);
        z[(size_t)(base + i0 + ii)*256 + t] += p.x + p.y;
    }
}

// ---------------- launcher ----------------
extern "C" void kernel_launch(void* const* d_in, const int* in_sizes, int n_in,
                              void* d_out, int out_size)
{
    const float* x     = (const float*)d_in[0];
    const float* adj   = (const float*)d_in[1];
    const float* Wq_w  = (const float*)d_in[2];
    const float* Wq_b  = (const float*)d_in[3];
    const float* Wk_w  = (const float*)d_in[4];
    const float* Wk_b  = (const float*)d_in[5];
    const float* Wv_w  = (const float*)d_in[6];
    const float* Wv_b  = (const float*)d_in[7];
    const float* Wo_w  = (const float*)d_in[8];
    const float* Wo_b  = (const float*)d_in[9];
    const float* ln_g  = (const float*)d_in[10];
    const float* ln_b  = (const float*)d_in[11];
    const float* fc_w  = (const float*)d_in[12];
    const float* fc_b  = (const float*)d_in[13];
    const float* out_w = (const float*)d_in[14];
    const float* out_b = (const float*)d_in[15];
    const float* proj  = (const float*)d_in[16];
    const float* gum   = (const float*)d_in[17];
    float* out = (float*)d_out;

    float *q, *k, *v, *qp, *kdd, *kdiag, *krmax, *kp, *ksum, *winv, *z;
    float *h1p, *wpat, *fused, *rden;
    __nv_bfloat16 *kvsT_hi, *kvsT_lo;
    cudaGetSymbolAddress((void**)&q,     g_q);
    cudaGetSymbolAddress((void**)&k,     g_k);
    cudaGetSymbolAddress((void**)&v,     g_v);
    cudaGetSymbolAddress((void**)&qp,    g_qp);
    cudaGetSymbolAddress((void**)&kdd,   g_kdd);
    cudaGetSymbolAddress((void**)&kdiag, g_kdiag);
    cudaGetSymbolAddress((void**)&krmax, g_krmax);
    cudaGetSymbolAddress((void**)&kp,    g_kp);
    cudaGetSymbolAddress((void**)&kvsT_hi, g_kvsT_hi);
    cudaGetSymbolAddress((void**)&kvsT_lo, g_kvsT_lo);
    cudaGetSymbolAddress((void**)&ksum,  g_ksum);
    cudaGetSymbolAddress((void**)&winv,  g_winv);
    cudaGetSymbolAddress((void**)&z,     g_z);
    cudaGetSymbolAddress((void**)&h1p,   g_h1p);
    cudaGetSymbolAddress((void**)&wpat,  g_wpat);
    cudaGetSymbolAddress((void**)&fused, g_fused);
    cudaGetSymbolAddress((void**)&rden,  g_rden);

    // 1) fused Q/K/V projections (HMMA)
    qkv_mma<<<dim3(BL/128, 2, 3), 256>>>(x, Wq_w, Wk_w, Wv_w,
                                         Wq_b, Wk_b, Wv_b, q, k, v);
    // 2) key feature map
    phi_kernel<<<BL*Hh/16, 256>>>(k, proj, nullptr, kdd, kdiag, krmax, 0);
    // 3) fused kmax + kp finalize
    kp_finalize<<<Bq*Hh, 256>>>(kdd, kdiag, krmax, kp);
    // 4) kvs on HMMA (single pass, packed staging)  <-- profiled launch slot
    kvs_mma<<<dim3(Bq*Hh, 4), 256>>>(kp, v, gum, kvsT_hi, kvsT_lo);
    // 5) query feature map
    phi_kernel<<<BL*Hh/16, 256>>>(q, proj, qp, nullptr, nullptr, nullptr, 1);
    // 6) ksum, 7) winv
    ksum_kernel<<<Bq*Hh, 256>>>(kp, gum, ksum);
    winv_kernel<<<Bq*Hh, 256>>>(qp, ksum, winv);
    // 8) z on HMMA (+winv reduction + LayerNorm)
    z_mma<<<dim3(Bq*Hh, 25), 256>>>(qp, kvsT_hi, kvsT_lo, winv, z, ln_g, ln_b);
    // 9) adjacency patch fusion (fp32 split-K, as in R8)
    gemm_sk<<<dim3(4, 1, NSPLIT), 256>>>(adj, fc_w, h1p, 512, 128, 10000, KCHUNK);
    score_kernel<<<Bq*Pp, 256>>>(h1p, fc_b, out_w, out_b, wpat);
    fused_kernel<<<(160000 + 255)/256, 256>>>(adj, wpat, fused);
    rden_kernel<<<Bq*Pp*Nn/8, 256>>>(fused, rden);
    // 10) relational bias
    biasadd_kernel<<<dim3(Bq*Pp, 5), 256>>>(fused, rden, v, z);
    // 11) output projection (HMMA)
    wo_mma<<<dim3(BL/128, 2), 256>>>(z, Wo_w, Wo_b, out);
}

// round 13
// speedup vs baseline: 1.4487x; 1.0135x over previous
#include <cuda_runtime.h>
#include <cuda_bf16.h>
#include <math.h>
#include <stdint.h>

// ---------------- static problem config ----------------
#define Bq    8
#define Pp    8
#define Nn    100
#define Dm    256
#define Hh    8
#define DKk   32
#define Mm    64
#define Kg    16
#define Ll    800            // P*N
#define BL    6400           // B*L
#define NSPLIT 125
#define KCHUNK 80            // 125*80 = 10000

#define PHI_SCALE 0.84089641525f   // 2 * 32^-0.25
#define KVS_ELEMS (64*512*64)

typedef unsigned long long ull;

// ---------------- packed f32x2 helpers ----------------
__device__ __forceinline__ ull pack2(float x, float y) {
    ull r; asm("mov.b64 %0, {%1,%2};" : "=l"(r) : "f"(x), "f"(y)); return r;
}
__device__ __forceinline__ ull fma2(ull a, ull b, ull c) {
    ull d; asm("fma.rn.f32x2 %0, %1, %2, %3;" : "=l"(d) : "l"(a), "l"(b), "l"(c)); return d;
}
__device__ __forceinline__ float2 unpack2(ull p) {
    float2 r; asm("mov.b64 {%0,%1}, %2;" : "=f"(r.x), "=f"(r.y) : "l"(p)); return r;
}

// ---------------- scratch (device globals; no allocation) ----------------
__device__ __align__(16) float g_q   [BL*Dm];
__device__ __align__(16) float g_k   [BL*Dm];
__device__ __align__(16) float g_v   [BL*Dm];
__device__ __align__(16) float g_qp  [BL*Hh*Mm];
__device__ __align__(16) float g_kdd [BL*Hh*Mm];
__device__              float g_kdiag[BL*Hh];
__device__              float g_krmax[BL*Hh];
__device__ __align__(16) float g_kp  [BL*Hh*Mm];
__device__ __align__(16) __nv_bfloat16 g_kvsT_hi[KVS_ELEMS];
__device__ __align__(16) __nv_bfloat16 g_kvsT_lo[KVS_ELEMS];
__device__ __align__(16) float g_ksum[Bq*Hh*Kg*Mm];
__device__ __align__(16) float g_winv[BL*Hh*Kg];
__device__ __align__(16) float g_z   [BL*Dm];
__device__ __align__(16) float g_h1p [NSPLIT*512*128];
__device__              float g_wpat [512];
__device__ __align__(16) float g_fused[Bq*Pp*Nn*Nn];
__device__              float g_rden [Bq*Pp*Nn];

// ================= mma.sync primitive =================
__device__ __forceinline__ void mma16816(float* d, const uint32_t* a, const uint32_t* b)
{
    asm volatile(
        "mma.sync.aligned.m16n8k16.row.col.f32.bf16.bf16.f32 "
        "{%0,%1,%2,%3}, {%4,%5,%6,%7}, {%8,%9}, {%0,%1,%2,%3};"
        : "+f"(d[0]), "+f"(d[1]), "+f"(d[2]), "+f"(d[3])
        : "r"(a[0]), "r"(a[1]), "r"(a[2]), "r"(a[3]), "r"(b[0]), "r"(b[1]));
}

__device__ __forceinline__ void bf16_split(float f, __nv_bfloat16& hi, __nv_bfloat16& lo)
{
    hi = __float2bfloat16(f);
    lo = __float2bfloat16(f - __bfloat162float(hi));
}
__device__ __forceinline__ uint32_t pack_bf2(__nv_bfloat16 a, __nv_bfloat16 b)
{
    __nv_bfloat162 p = __halves2bfloat162(a, b);
    return reinterpret_cast<uint32_t&>(p);
}

// ================= projection GEMM (bf16x3, proven in R6) =================
#define SMS 40

__device__ __forceinline__ void load_slab32(const float* __restrict__ src,
                                            __nv_bfloat16* __restrict__ hi,
                                            __nv_bfloat16* __restrict__ lo, int tid)
{
    for (int idx = tid; idx < 1024; idx += 256) {
        int r = idx >> 3, c4 = (idx & 7) * 4;
        float4 f = *(const float4*)(src + (size_t)r * 256 + c4);
        __nv_bfloat16 h0, l0, h1, l1, h2, l2, h3, l3;
        bf16_split(f.x, h0, l0); bf16_split(f.y, h1, l1);
        bf16_split(f.z, h2, l2); bf16_split(f.w, h3, l3);
        uint2 hw = make_uint2(pack_bf2(h0, h1), pack_bf2(h2, h3));
        uint2 lw = make_uint2(pack_bf2(l0, l1), pack_bf2(l2, l3));
        *(uint2*)(hi + r * SMS + c4) = hw;
        *(uint2*)(lo + r * SMS + c4) = lw;
    }
}

__device__ __forceinline__ void mma_gemm_body(const float* __restrict__ A,
                                              const float* __restrict__ W,
                                              const float* __restrict__ bias,
                                              float* __restrict__ C)
{
    __shared__ __align__(16) __nv_bfloat16 sm[4 * 128 * SMS];
    __nv_bfloat16* Ah = sm;
    __nv_bfloat16* Al = sm + 128 * SMS;
    __nv_bfloat16* Wh = sm + 2 * 128 * SMS;
    __nv_bfloat16* Wl = sm + 3 * 128 * SMS;

    int tid = threadIdx.x, lane = tid & 31, warp = tid >> 5;
    int wm = warp & 3, wn = warp >> 2;
    int row0 = blockIdx.x * 128, col0 = blockIdx.y * 128;
    int g = lane >> 2, tg = lane & 3;

    float d[2][8][4];
#pragma unroll
    for (int mt = 0; mt < 2; mt++)
#pragma unroll
        for (int nt = 0; nt < 8; nt++)
#pragma unroll
            for (int i = 0; i < 4; i++) d[mt][nt][i] = 0.f;

    for (int kc = 0; kc < 8; kc++) {
        load_slab32(A + (size_t)row0 * 256 + kc * 32, Ah, Al, tid);
        load_slab32(W + (size_t)col0 * 256 + kc * 32, Wh, Wl, tid);
        __syncthreads();
#pragma unroll
        for (int ks = 0; ks < 2; ks++) {
            int kb = ks * 16;
            uint32_t ah[2][4], al[2][4];
#pragma unroll
            for (int mt = 0; mt < 2; mt++) {
                int rb = wm * 32 + mt * 16;
                const __nv_bfloat16* p0 = &Ah[(rb + g) * SMS + kb + tg * 2];
                const __nv_bfloat16* p1 = &Ah[(rb + g + 8) * SMS + kb + tg * 2];
                ah[mt][0] = *(const uint32_t*)p0;
                ah[mt][1] = *(const uint32_t*)p1;
                ah[mt][2] = *(const uint32_t*)(p0 + 8);
                ah[mt][3] = *(const uint32_t*)(p1 + 8);
                const __nv_bfloat16* q0 = &Al[(rb + g) * SMS + kb + tg * 2];
                const __nv_bfloat16* q1 = &Al[(rb + g + 8) * SMS + kb + tg * 2];
                al[mt][0] = *(const uint32_t*)q0;
                al[mt][1] = *(const uint32_t*)q1;
                al[mt][2] = *(const uint32_t*)(q0 + 8);
                al[mt][3] = *(const uint32_t*)(q1 + 8);
            }
#pragma unroll
            for (int nt = 0; nt < 8; nt++) {
                int nb = wn * 64 + nt * 8;
                const __nv_bfloat16* qh = &Wh[(nb + g) * SMS + kb + tg * 2];
                const __nv_bfloat16* ql = &Wl[(nb + g) * SMS + kb + tg * 2];
                uint32_t bh2[2] = {*(const uint32_t*)qh, *(const uint32_t*)(qh + 8)};
                uint32_t bl2[2] = {*(const uint32_t*)ql, *(const uint32_t*)(ql + 8)};
#pragma unroll
                for (int mt = 0; mt < 2; mt++) {
                    mma16816(d[mt][nt], ah[mt], bh2);
                    mma16816(d[mt][nt], ah[mt], bl2);
                    mma16816(d[mt][nt], al[mt], bh2);
                }
            }
        }
        __syncthreads();
    }

#pragma unroll
    for (int mt = 0; mt < 2; mt++) {
        int r0 = row0 + wm * 32 + mt * 16 + g;
#pragma unroll
        for (int nt = 0; nt < 8; nt++) {
            int col = col0 + wn * 64 + nt * 8 + tg * 2;
            float2 b2 = *(const float2*)&bias[col];
            float2 o0 = make_float2(d[mt][nt][0] + b2.x, d[mt][nt][1] + b2.y);
            float2 o1 = make_float2(d[mt][nt][2] + b2.x, d[mt][nt][3] + b2.y);
            *(float2*)&C[(size_t)r0 * 256 + col]       = o0;
            *(float2*)&C[(size_t)(r0 + 8) * 256 + col] = o1;
        }
    }
}

__global__ void __launch_bounds__(256) qkv_mma(
    const float* __restrict__ x,
    const float* __restrict__ Wq, const float* __restrict__ Wk, const float* __restrict__ Wv,
    const float* __restrict__ bq, const float* __restrict__ bk, const float* __restrict__ bv,
    float* __restrict__ q, float* __restrict__ k, float* __restrict__ v)
{
    const float* W = blockIdx.z == 0 ? Wq : (blockIdx.z == 1 ? Wk : Wv);
    const float* b = blockIdx.z == 0 ? bq : (blockIdx.z == 1 ? bk : bv);
    float* C       = blockIdx.z == 0 ? q  : (blockIdx.z == 1 ? k  : v);
    mma_gemm_body(x, W, b, C);
}

__global__ void __launch_bounds__(256) wo_mma(
    const float* __restrict__ A, const float* __restrict__ W,
    const float* __restrict__ b, float* __restrict__ C)
{
    mma_gemm_body(A, W, b, C);
}

// ================= kvs on HMMA, register-prefetch pipeline =================
// grid (64 bh, 4 q). Direct transposed bf16 hi/lo output.
#define SA 36
__global__ void __launch_bounds__(256) kvs_mma(
    const float* __restrict__ kp, const float* __restrict__ v,
    const float* __restrict__ gum,
    __nv_bfloat16* __restrict__ kvsT_hi, __nv_bfloat16* __restrict__ kvsT_lo)
{
    __shared__ __align__(16) __nv_bfloat16 As_hi[64*SA], As_lo[64*SA];
    __shared__ __align__(16) __nv_bfloat16 Bs_hi[128*SA], Bs_lo[128*SA];
    __shared__ float v_s[32][32];
    __shared__ float e_s[32][4];

    int bh = blockIdx.x, q = blockIdx.y;
    int b = bh >> 3, h = bh & 7;
    int t = threadIdx.x, lane = t & 31, warp = t >> 5;
    int wm = warp & 3, wn = warp >> 2;
    int g = lane >> 2, tg = lane & 3;

    int vl = t >> 3, vd4 = (t & 7) * 4;
    int el = t >> 2, ekq = t & 3;

    float d[8][4];
#pragma unroll
    for (int nt = 0; nt < 8; nt++)
#pragma unroll
        for (int i = 0; i < 4; i++) d[nt][i] = 0.f;

    // prefetch registers for chunk staging
    float4 pv;
    float pe = 0.f;
    float pk0[4], pk1[4];
    {
        pv = *(const float4*)&v[(size_t)(b*Ll + vl)*Dm + h*32 + vd4];
        if (t < 128) pe = gum[(((b*Ll + el)*Hh + h) << 4) + q*4 + ekq];
#pragma unroll
        for (int j = 0; j < 4; j++) {
            int idx = t + j * 256;
            int m = idx & 63, lp = idx >> 6;
            int l = lp * 2;
            pk0[j] = kp[((size_t)((b*Ll + l    )*Hh + h) << 6) + m];
            pk1[j] = kp[((size_t)((b*Ll + l + 1)*Hh + h) << 6) + m];
        }
    }

    for (int ci = 0; ci < 25; ci++) {
        // write prefetched data to smem
        *(float4*)&v_s[vl][vd4] = pv;
        if (t < 128) e_s[el][ekq] = expf(pe);
#pragma unroll
        for (int j = 0; j < 4; j++) {
            int idx = t + j * 256;
            int m = idx & 63, lp = idx >> 6;
            __nv_bfloat16 h0, lo0, h1, lo1;
            bf16_split(pk0[j], h0, lo0); bf16_split(pk1[j], h1, lo1);
            *(uint32_t*)&As_hi[m*SA + lp*2] = pack_bf2(h0, h1);
            *(uint32_t*)&As_lo[m*SA + lp*2] = pack_bf2(lo0, lo1);
        }
        __syncthreads();
        // build B[n=kd][l] = e[l, n>>5] * v[l, n&31], packed (2 l's per u32)
        {
            int n = t >> 1;
            int lpb = (t & 1) * 8;
            int kq = n >> 5, dd = n & 31;
#pragma unroll
            for (int j = 0; j < 8; j++) {
                int lp = lpb + j;
                float f0 = e_s[2*lp][kq]     * v_s[2*lp][dd];
                float f1 = e_s[2*lp + 1][kq] * v_s[2*lp + 1][dd];
                __nv_bfloat16 h0, lo0, h1, lo1;
                bf16_split(f0, h0, lo0); bf16_split(f1, h1, lo1);
                *(uint32_t*)&Bs_hi[n*SA + lp*2] = pack_bf2(h0, h1);
                *(uint32_t*)&Bs_lo[n*SA + lp*2] = pack_bf2(lo0, lo1);
            }
        }
        // prefetch next chunk (overlaps with MMA below)
        if (ci < 24) {
            int l0 = (ci + 1) * 32;
            pv = *(const float4*)&v[(size_t)(b*Ll + l0 + vl)*Dm + h*32 + vd4];
            if (t < 128) pe = gum[(((b*Ll + l0 + el)*Hh + h) << 4) + q*4 + ekq];
#pragma unroll
            for (int j = 0; j < 4; j++) {
                int idx = t + j * 256;
                int m = idx & 63, lp = idx >> 6;
                int l = l0 + lp * 2;
                pk0[j] = kp[((size_t)((b*Ll + l    )*Hh + h) << 6) + m];
                pk1[j] = kp[((size_t)((b*Ll + l + 1)*Hh + h) << 6) + m];
            }
        }
        __syncthreads();
        // MMA: warp tile 16m x 64n
#pragma unroll
        for (int ks = 0; ks < 2; ks++) {
            int kb = ks * 16;
            uint32_t ah[4], al[4];
            {
                int rb = wm * 16;
                const __nv_bfloat16* p0 = &As_hi[(rb + g) * SA + kb + tg*2];
                const __nv_bfloat16* p1 = &As_hi[(rb + g + 8) * SA + kb + tg*2];
                ah[0] = *(const uint32_t*)p0;
                ah[1] = *(const uint32_t*)p1;
                ah[2] = *(const uint32_t*)(p0 + 8);
                ah[3] = *(const uint32_t*)(p1 + 8);
                const __nv_bfloat16* q0 = &As_lo[(rb + g) * SA + kb + tg*2];
                const __nv_bfloat16* q1 = &As_lo[(rb + g + 8) * SA + kb + tg*2];
                al[0] = *(const uint32_t*)q0;
                al[1] = *(const uint32_t*)q1;
                al[2] = *(const uint32_t*)(q0 + 8);
                al[3] = *(const uint32_t*)(q1 + 8);
            }
#pragma unroll
            for (int nt = 0; nt < 8; nt++) {
                int nb = wn * 64 + nt * 8;
                const __nv_bfloat16* qh = &Bs_hi[(nb + g) * SA + kb + tg*2];
                const __nv_bfloat16* ql = &Bs_lo[(nb + g) * SA + kb + tg*2];
                uint32_t bh2[2] = {*(const uint32_t*)qh, *(const uint32_t*)(qh + 8)};
                uint32_t bl2[2] = {*(const uint32_t*)ql, *(const uint32_t*)(ql + 8)};
                mma16816(d[nt], ah, bh2);
                mma16816(d[nt], ah, bl2);
                mma16816(d[nt], al, bh2);
            }
        }
        __syncthreads();
    }
    // epilogue: store transposed [kd][m] hi/lo
    int m = wm * 16 + g;
#pragma unroll
    for (int nt = 0; nt < 8; nt++) {
        int n = q*128 + wn*64 + nt*8 + tg*2;
        size_t base0 = ((size_t)bh * 512 + n) * 64;
        size_t base1 = base0 + 64;   // n+1
        __nv_bfloat16 hi, lo;
        bf16_split(d[nt][0], hi, lo); kvsT_hi[base0 + m] = hi;     kvsT_lo[base0 + m] = lo;
        bf16_split(d[nt][1], hi, lo); kvsT_hi[base1 + m] = hi;     kvsT_lo[base1 + m] = lo;
        bf16_split(d[nt][2], hi, lo); kvsT_hi[base0 + m + 8] = hi; kvsT_lo[base0 + m + 8] = lo;
        bf16_split(d[nt][3], hi, lo); kvsT_hi[base1 + m + 8] = hi; kvsT_lo[base1 + m + 8] = lo;
    }
}

// ================= z on HMMA + winv reduction + LayerNorm (prefetch) =========
#define SQ 68
__global__ void __launch_bounds__(256) z_mma(
    const float* __restrict__ qp,
    const __nv_bfloat16* __restrict__ kvsT_hi, const __nv_bfloat16* __restrict__ kvsT_lo,
    const float* __restrict__ winv, float* __restrict__ z,
    const float* __restrict__ ln_g, const float* __restrict__ ln_b)
{
    __shared__ __align__(16) __nv_bfloat16 Aq_hi[32*SQ], Aq_lo[32*SQ];
    __shared__ __align__(16) __nv_bfloat16 Bs_hi[64*SQ], Bs_lo[64*SQ];
    __shared__ float winv_s[32][16];
    __shared__ float zred[4][32][33];

    int bh = blockIdx.x;
    int b = bh >> 3, h = bh & 7;
    int l0 = blockIdx.y * 32;
    int t = threadIdx.x, lane = t & 31, warp = t >> 5;
    int wm = warp & 1, wn = warp >> 1;       // 2 x 4 warps; warp tile 16l x 16n
    int g = lane >> 2, tg = lane & 3;

    // prefetch B chunk 0 from global
    uint32_t pbh[8], pbl[8];
#pragma unroll
    for (int j = 0; j < 8; j++) {
        int idx = t + j * 256;
        int n = idx >> 5, m2 = (idx & 31) * 2;
        size_t src = ((size_t)bh * 512 + n) * 64 + m2;
        pbh[j] = *(const uint32_t*)&kvsT_hi[src];
        pbl[j] = *(const uint32_t*)&kvsT_lo[src];
    }

    // stage A = qp tile [32 l][64 m] hi/lo
#pragma unroll
    for (int j = 0; j < 2; j++) {
        int idx = t + j * 256;
        int l = idx >> 4, m4 = (idx & 15) * 4;
        float4 q4 = *(const float4*)&qp[((size_t)((b*Ll + l0 + l)*Hh + h) << 6) + m4];
        float fv[4] = {q4.x, q4.y, q4.z, q4.w};
#pragma unroll
        for (int i = 0; i < 4; i++) {
            __nv_bfloat16 hi, lo; bf16_split(fv[i], hi, lo);
            Aq_hi[l*SQ + m4 + i] = hi;
            Aq_lo[l*SQ + m4 + i] = lo;
        }
    }
    // stage winv
#pragma unroll
    for (int j = 0; j < 2; j++) {
        int idx = t + j * 256;
        int l = idx >> 4, kk = idx & 15;
        winv_s[l][kk] = winv[(((b*Ll + l0 + l)*Hh + h) << 4) + kk];
    }
    // zero zred
    for (int idx = t; idx < 4*32*33; idx += 256) ((float*)zred)[idx] = 0.f;
    __syncthreads();

    for (int ch = 0; ch < 8; ch++) {
        // write prefetched B chunk to smem
#pragma unroll
        for (int j = 0; j < 8; j++) {
            int idx = t + j * 256;
            int n = idx >> 5, m2 = (idx & 31) * 2;
            *(uint32_t*)&Bs_hi[n*SQ + m2] = pbh[j];
            *(uint32_t*)&Bs_lo[n*SQ + m2] = pbl[j];
        }
        __syncthreads();
        // prefetch next chunk (overlaps with MMA below)
        if (ch < 7) {
#pragma unroll
            for (int j = 0; j < 8; j++) {
                int idx = t + j * 256;
                int n = idx >> 5, m2 = (idx & 31) * 2;
                size_t src = ((size_t)bh * 512 + (ch + 1)*64 + n) * 64 + m2;
                pbh[j] = *(const uint32_t*)&kvsT_hi[src];
                pbl[j] = *(const uint32_t*)&kvsT_lo[src];
            }
        }

        float dfr[2][4];
#pragma unroll
        for (int nt = 0; nt < 2; nt++)
#pragma unroll
            for (int i = 0; i < 4; i++) dfr[nt][i] = 0.f;

#pragma unroll
        for (int ks = 0; ks < 4; ks++) {
            int kb = ks * 16;
            uint32_t ah[4], al[4];
            {
                int rb = wm * 16;
                const __nv_bfloat16* p0 = &Aq_hi[(rb + g) * SQ + kb + tg*2];
                const __nv_bfloat16* p1 = &Aq_hi[(rb + g + 8) * SQ + kb + tg*2];
                ah[0] = *(const uint32_t*)p0;
                ah[1] = *(const uint32_t*)p1;
                ah[2] = *(const uint32_t*)(p0 + 8);
                ah[3] = *(const uint32_t*)(p1 + 8);
                const __nv_bfloat16* q0 = &Aq_lo[(rb + g) * SQ + kb + tg*2];
                const __nv_bfloat16* q1 = &Aq_lo[(rb + g + 8) * SQ + kb + tg*2];
                al[0] = *(const uint32_t*)q0;
                al[1] = *(const uint32_t*)q1;
                al[2] = *(const uint32_t*)(q0 + 8);
                al[3] = *(const uint32_t*)(q1 + 8);
            }
#pragma unroll
            for (int nt = 0; nt < 2; nt++) {
                int nb = wn * 16 + nt * 8;
                const __nv_bfloat16* qh = &Bs_hi[(nb + g) * SQ + kb + tg*2];
                const __nv_bfloat16* ql = &Bs_lo[(nb + g) * SQ + kb + tg*2];
                uint32_t bh2[2] = {*(const uint32_t*)qh, *(const uint32_t*)(qh + 8)};
                uint32_t bl2[2] = {*(const uint32_t*)ql, *(const uint32_t*)(ql + 8)};
                mma16816(dfr[nt], ah, bh2);
                mma16816(dfr[nt], ah, bl2);
                mma16816(dfr[nt], al, bh2);
            }
        }
        // winv-weighted k reduction into zred
        int k = ch*2 + (wn >> 1);
        int la = wm*16 + g, lb = la + 8;
        float wia = winv_s[la][k], wib = winv_s[lb][k];
#pragma unroll
        for (int nt = 0; nt < 2; nt++) {
            int dl = (wn & 1)*16 + nt*8 + tg*2;
            zred[wn][la][dl]     += dfr[nt][0] * wia;
            zred[wn][la][dl + 1] += dfr[nt][1] * wia;
            zred[wn][lb][dl]     += dfr[nt][2] * wib;
            zred[wn][lb][dl + 1] += dfr[nt][3] * wib;
        }
        __syncthreads();
    }

    // final sum over wn + LayerNorm (warp per token, 4 tokens/warp)
    float gl = ln_g[lane], bl = ln_b[lane];
#pragma unroll
    for (int j = 0; j < 4; j++) {
        int tok = warp + j * 8;
        float ss = zred[0][tok][lane] + zred[1][tok][lane]
                 + zred[2][tok][lane] + zred[3][tok][lane];
        float mu = ss;
#pragma unroll
        for (int o = 16; o > 0; o >>= 1) mu += __shfl_xor_sync(0xffffffffu, mu, o);
        mu *= (1.0f / 32.0f);
        float df = ss - mu;
        float v2 = df * df;
#pragma unroll
        for (int o = 16; o > 0; o >>= 1) v2 += __shfl_xor_sync(0xffffffffu, v2, o);
        float var = v2 * (1.0f / 32.0f);
        z[(size_t)(b*Ll + l0 + tok)*Dm + h*32 + lane] =
            df * rsqrtf(var + 1e-5f) * gl + bl;
    }
}

// ======== fp32 GEMM (fc split-K): 128x128 tile, BK=16, FFMA2, dbuf ========
__device__ __forceinline__ void gemm128(const float* __restrict__ A,
                                        const float* __restrict__ W,
                                        float* __restrict__ C,
                                        int Nc, int Kd, int k0, int klen)
{
    __shared__ __align__(16) float As[2][16][132];
    __shared__ __align__(16) float Ws[2][16][132];
    int tid = threadIdx.x;
    int tx = tid & 15, ty = tid >> 4;
    int row0 = blockIdx.x * 128, col0 = blockIdx.y * 128;
    int lr = tid >> 1, lc = (tid & 1) * 8;

    const float* Ap = A + (size_t)(row0 + lr) * Kd + k0 + lc;
    const float* Wp = W + (size_t)(col0 + lr) * Kd + k0 + lc;

    ull acc[8][4];
#pragma unroll
    for (int i = 0; i < 8; i++)
#pragma unroll
        for (int j = 0; j < 4; j++) acc[i][j] = 0ULL;

    float4 pa0 = *(const float4*)(Ap);
    float4 pa1 = *(const float4*)(Ap + 4);
    float4 pw0 = *(const float4*)(Wp);
    float4 pw1 = *(const float4*)(Wp + 4);

    int nk = klen >> 4;
    int buf = 0;
    for (int it = 0; it < nk; it++) {
        As[buf][lc+0][lr] = pa0.x; As[buf][lc+1][lr] = pa0.y;
        As[buf][lc+2][lr] = pa0.z; As[buf][lc+3][lr] = pa0.w;
        As[buf][lc+4][lr] = pa1.x; As[buf][lc+5][lr] = pa1.y;
        As[buf][lc+6][lr] = pa1.z; As[buf][lc+7][lr] = pa1.w;
        Ws[buf][lc+0][lr] = pw0.x; Ws[buf][lc+1][lr] = pw0.y;
        Ws[buf][lc+2][lr] = pw0.z; Ws[buf][lc+3][lr] = pw0.w;
        Ws[buf][lc+4][lr] = pw1.x; Ws[buf][lc+5][lr] = pw1.y;
        Ws[buf][lc+6][lr] = pw1.z; Ws[buf][lc+7][lr] = pw1.w;
        __syncthreads();
        if (it + 1 < nk) {
            int off = (it + 1) * 16;
            pa0 = *(const float4*)(Ap + off);
            pa1 = *(const float4*)(Ap + off + 4);
            pw0 = *(const float4*)(Wp + off);
            pw1 = *(const float4*)(Wp + off + 4);
        }
#pragma unroll
        for (int c = 0; c < 16; c++) {
            float4 a0 = *(const float4*)&As[buf][c][ty*4];
            float4 a1 = *(const float4*)&As[buf][c][64 + ty*4];
            ulonglong2 w01 = *(const ulonglong2*)&Ws[buf][c][tx*4];
            ulonglong2 w23 = *(const ulonglong2*)&Ws[buf][c][64 + tx*4];
            ull wp[4] = {w01.x, w01.y, w23.x, w23.y};
            float av[8] = {a0.x,a0.y,a0.z,a0.w, a1.x,a1.y,a1.z,a1.w};
#pragma unroll
            for (int i = 0; i < 8; i++) {
                ull ad = pack2(av[i], av[i]);
#pragma unroll
                for (int j = 0; j < 4; j++) acc[i][j] = fma2(ad, wp[j], acc[i][j]);
            }
        }
        buf ^= 1;
        __syncthreads();
    }

#pragma unroll
    for (int i = 0; i < 8; i++) {
        int rr = row0 + ((i < 4) ? (ty*4 + i) : (64 + ty*4 + i - 4));
        float2 p0 = unpack2(acc[i][0]);
        float2 p1 = unpack2(acc[i][1]);
        float2 p2 = unpack2(acc[i][2]);
        float2 p3 = unpack2(acc[i][3]);
        float4 o0 = make_float4(p0.x, p0.y, p1.x, p1.y);
        float4 o1 = make_float4(p2.x, p2.y, p3.x, p3.y);
        *(float4*)&C[(size_t)rr * Nc + col0 + tx*4]      = o0;
        *(float4*)&C[(size_t)rr * Nc + col0 + 64 + tx*4] = o1;
    }
}

__global__ void gemm_sk(const float* __restrict__ A, const float* __restrict__ W,
                        float* __restrict__ C, int Mr, int Nc, int Kd, int klen)
{
    gemm128(A, W, C + (size_t)blockIdx.z * (size_t)Mr * Nc,
            Nc, Kd, blockIdx.z * klen, klen);
}

// ---------------- Performer feature map (FFMA2) ----------------
__global__ void phi_kernel(const float* __restrict__ din, const float* __restrict__ proj,
                           float* __restrict__ outphi, float* __restrict__ dd_out,
                           float* __restrict__ diag_out, float* __restrict__ rmax_out,
                           int is_query)
{
    __shared__ __align__(16) float proj_s[64][34];
    __shared__ __align__(16) float data_s[4][32];
    __shared__ float wmax[4][2];
    int tid = threadIdx.x;
    for (int i = tid; i < 2048; i += 256) proj_s[i >> 5][i & 31] = proj[i];
    int sub = tid >> 6;
    int m = tid & 63;
    int u0 = blockIdx.x * 16;
    for (int g = 0; g < 16; g += 4) {
        int u = u0 + g + sub;
        __syncthreads();
        if (m < 32) data_s[sub][m] = din[(size_t)u*32 + m] * PHI_SCALE;
        __syncthreads();
        ull dd2 = 0ULL, dg2 = 0ULL;
#pragma unroll
        for (int d2 = 0; d2 < 16; d2++) {
            ull x2 = *(const ull*)&data_s[sub][d2*2];
            ull p2 = *(const ull*)&proj_s[m][d2*2];
            dd2 = fma2(x2, p2, dd2);
            dg2 = fma2(x2, x2, dg2);
        }
        float2 dp = unpack2(dd2);
        float2 gp = unpack2(dg2);
        float dd = dp.x + dp.y;
        float diag = 0.5f * (gp.x + gp.y);
        float mx = dd;
#pragma unroll
        for (int o = 16; o > 0; o >>= 1) mx = fmaxf(mx, __shfl_xor_sync(0xffffffffu, mx, o));
        if ((tid & 31) == 0) wmax[sub][m >> 5] = mx;
        __syncthreads();
        float stab = fmaxf(wmax[sub][0], wmax[sub][1]);
        if (is_query) {
            outphi[(size_t)u*64 + m] = 0.125f * (expf(dd - diag - stab) + 1e-6f);
        } else {
            dd_out[(size_t)u*64 + m] = dd;
            if (m == 0) { diag_out[u] = diag; rmax_out[u] = stab; }
        }
    }
}

// ---------------- fused kmax + kp finalize ----------------
__global__ void kp_finalize(const float* __restrict__ kdd, const float* __restrict__ kdiag,
                            const float* __restrict__ krmax, float* __restrict__ kp)
{
    int bh = blockIdx.x; int b = bh >> 3, h = bh & 7;
    int t = threadIdx.x;
    __shared__ float red[256];
    float mx = -1e30f;
    for (int l = t; l < Ll; l += 256) mx = fmaxf(mx, krmax[(b*Ll + l)*Hh + h]);
    red[t] = mx; __syncthreads();
    for (int s = 128; s > 0; s >>= 1) {
        if (t < s) red[t] = fmaxf(red[t], red[t + s]);
        __syncthreads();
    }
    float km = red[0];
    for (int i = t; i < Ll * 64; i += 256) {
        int l = i >> 6, m = i & 63;
        size_t u = (size_t)(b*Ll + l)*Hh + h;
        kp[u*64 + m] = 0.125f * (expf(kdd[u*64 + m] - kdiag[u] - km) + 1e-6f);
    }
}

// ---------------- ksum[bh][k][m] = sum_l kp[l,m] * exp(gum[l,k]) ----------------
__global__ void ksum_kernel(const float* __restrict__ kp, const float* __restrict__ gum,
                            float* __restrict__ ksum)
{
    __shared__ __align__(16) float kp_s[16][64];
    __shared__ float eg_s[16][16];
    int bh = blockIdx.x; int b = bh >> 3, h = bh & 7;
    int t = threadIdx.x;
    int lc = t >> 4, lf = t & 15;
    float4 acc = make_float4(0,0,0,0);
    for (int l0 = 0; l0 < Ll; l0 += 16) {
        __syncthreads();
        *(float4*)&kp_s[lc][lf*4] =
            *(const float4*)&kp[((size_t)((b*Ll + l0 + lc)*Hh + h) << 6) + lf*4];
        eg_s[lc][lf] = expf(gum[(((b*Ll + l0 + lc)*Hh + h) << 4) + lf]);
        __syncthreads();
#pragma unroll
        for (int c = 0; c < 16; c++) {
            float e = eg_s[c][lc];
            float4 kp4 = *(const float4*)&kp_s[c][lf*4];
            acc.x += kp4.x * e; acc.y += kp4.y * e;
            acc.z += kp4.z * e; acc.w += kp4.w * e;
        }
    }
    *(float4*)&ksum[((size_t)(bh*16 + lc) << 6) + lf*4] = acc;
}

// ---------------- winv[l,k] = 1/((qp . ksum + 1e-8)*16) per bh ----------------
__global__ void winv_kernel(const float* __restrict__ qp, const float* __restrict__ ksum,
                            float* __restrict__ winv)
{
    __shared__ __align__(16) float ks_s[16][64];
    __shared__ __align__(16) float qp_s[16][64];
    int bh = blockIdx.x; int b = bh >> 3, h = bh & 7;
    int t = threadIdx.x;
    int lc = t >> 4, lf = t & 15;
    *(float4*)&ks_s[lc][lf*4] = *(const float4*)&ksum[((size_t)(bh*16 + lc) << 6) + lf*4];
    for (int l0 = 0; l0 < Ll; l0 += 16) {
        __syncthreads();
        *(float4*)&qp_s[lc][lf*4] =
            *(const float4*)&qp[((size_t)((b*Ll + l0 + lc)*Hh + h) << 6) + lf*4];
        __syncthreads();
        ull d2 = 0ULL;
#pragma unroll
        for (int m2 = 0; m2 < 32; m2++) {
            ull q2 = *(const ull*)&qp_s[lc][m2*2];
            ull k2 = *(const ull*)&ks_s[lf][m2*2];
            d2 = fma2(q2, k2, d2);
        }
        float2 dp = unpack2(d2);
        winv[(((b*Ll + l0 + lc)*Hh + h) << 4) + lf] =
            1.0f / ((dp.x + dp.y + 1e-8f) * 16.0f);
    }
}

// ---------------- patch score + softmax over patch dim ----------------
__global__ void score_kernel(const float* __restrict__ h1p, const float* __restrict__ fc_b,
                             const float* __restrict__ out_w, const float* __restrict__ out_b,
                             float* __restrict__ wout)
{
    int bp = blockIdx.x;
    int t = threadIdx.x >> 5, lane = threadIdx.x & 31;
    __shared__ float sc[8];
    float p = 0.f;
    for (int j = lane; j < 128; j += 32) {
        float hv = fc_b[j];
        for (int s = 0; s < NSPLIT; s++) hv += h1p[(size_t)s*65536 + (bp*8 + t)*128 + j];
        hv = fmaxf(hv, 0.f);
        p += hv * out_w[j];
    }
#pragma unroll
    for (int o = 16; o > 0; o >>= 1) p += __shfl_xor_sync(0xffffffffu, p, o);
    if (lane == 0) sc[t] = p + out_b[0];
    __syncthreads();
    if (threadIdx.x == 0) {
        float mx = sc[0];
#pragma unroll
        for (int i = 1; i < 8; i++) mx = fmaxf(mx, sc[i]);
        float e[8], sum = 0.f;
#pragma unroll
        for (int i = 0; i < 8; i++) { e[i] = expf(sc[i] - mx); sum += e[i]; }
#pragma unroll
        for (int i = 0; i < 8; i++) wout[bp*8 + i] = e[i] / sum;
    }
}

__global__ void fused_kernel(const float* __restrict__ adj, const float* __restrict__ wpat,
                             float* __restrict__ fused)
{
    int i4 = blockIdx.x * 256 + threadIdx.x;    // < 160000
    if (i4 >= 160000) return;
    int bp = i4 / 2500;
    int r4 = i4 - bp * 2500;
    float4 s = make_float4(0,0,0,0);
#pragma unroll
    for (int t = 0; t < 8; t++) {
        float w = wpat[bp*8 + t];
        float4 a = *(const float4*)&adj[(size_t)(bp*8 + t)*10000 + r4*4];
        s.x += a.x*w; s.y += a.y*w; s.z += a.z*w; s.w += a.w*w;
    }
    *(float4*)&fused[(size_t)bp*10000 + r4*4] = s;
}

__global__ void rden_kernel(const float* __restrict__ fused, float* __restrict__ rden)
{
    int w = threadIdx.x >> 5, lane = threadIdx.x & 31;
    int row = blockIdx.x * 8 + w;
    float s = 0.f;
    for (int j = lane; j < 100; j += 32) s += fabsf(fused[(size_t)row*100 + j]);
#pragma unroll
    for (int o = 16; o > 0; o >>= 1) s += __shfl_xor_sync(0xffffffffu, s, o);
    if (lane == 0) rden[row] = fmaxf(s, 1e-12f);
}

// relational bias: z += (fused/rden) @ V (FFMA2); grid (64, 5)
__global__ void biasadd_kernel(const float* __restrict__ fused, const float* __restrict__ rden,
                               const float* __restrict__ v, float* __restrict__ z)
{
    __shared__ __align__(16) float A_s[20][102];
    int blk = blockIdx.x;
    int i0 = blockIdx.y * 20;
    int t = threadIdx.x;
    for (int idx = t; idx < 2000; idx += 256) {
        int i = idx / 100, j = idx - i * 100;
        A_s[i][j] = fused[(size_t)blk*10000 + (i0 + i)*100 + j] / rden[blk*100 + i0 + i];
    }
    __syncthreads();
    int base = blk * 100;
    ull accp[20];
#pragma unroll
    for (int ii = 0; ii < 20; ii++) accp[ii] = 0ULL;
    for (int j = 0; j < 100; j += 2) {
        float vj0 = v[(size_t)(base + j)*256 + t];
        float vj1 = v[(size_t)(base + j + 1)*256 + t];
        ull vp = pack2(vj0, vj1);
#pragma unroll
        for (int ii = 0; ii < 20; ii++)
            accp[ii] = fma2(*(const ull*)&A_s[ii][j], vp, accp[ii]);
    }
#pragma unroll
    for (int ii = 0; ii < 20; ii++) {
        float2 p = unpack2(accp[ii]);
        z[(size_t)(base + i0 + ii)*256 + t] += p.x + p.y;
    }
}

// ---------------- launcher ----------------
extern "C" void kernel_launch(void* const* d_in, const int* in_sizes, int n_in,
                              void* d_out, int out_size)
{
    const float* x     = (const float*)d_in[0];
    const float* adj   = (const float*)d_in[1];
    const float* Wq_w  = (const float*)d_in[2];
    const float* Wq_b  = (const float*)d_in[3];
    const float* Wk_w  = (const float*)d_in[4];
    const float* Wk_b  = (const float*)d_in[5];
    const float* Wv_w  = (const float*)d_in[6];
    const float* Wv_b  = (const float*)d_in[7];
    const float* Wo_w  = (const float*)d_in[8];
    const float* Wo_b  = (const float*)d_in[9];
    const float* ln_g  = (const float*)d_in[10];
    const float* ln_b  = (const float*)d_in[11];
    const float* fc_w  = (const float*)d_in[12];
    const float* fc_b  = (const float*)d_in[13];
    const float* out_w = (const float*)d_in[14];
    const float* out_b = (const float*)d_in[15];
    const float* proj  = (const float*)d_in[16];
    const float* gum   = (const float*)d_in[17];
    float* out = (float*)d_out;

    float *q, *k, *v, *qp, *kdd, *kdiag, *krmax, *kp, *ksum, *winv, *z;
    float *h1p, *wpat, *fused, *rden;
    __nv_bfloat16 *kvsT_hi, *kvsT_lo;
    cudaGetSymbolAddress((void**)&q,     g_q);
    cudaGetSymbolAddress((void**)&k,     g_k);
    cudaGetSymbolAddress((void**)&v,     g_v);
    cudaGetSymbolAddress((void**)&qp,    g_qp);
    cudaGetSymbolAddress((void**)&kdd,   g_kdd);
    cudaGetSymbolAddress((void**)&kdiag, g_kdiag);
    cudaGetSymbolAddress((void**)&krmax, g_krmax);
    cudaGetSymbolAddress((void**)&kp,    g_kp);
    cudaGetSymbolAddress((void**)&kvsT_hi, g_kvsT_hi);
    cudaGetSymbolAddress((void**)&kvsT_lo, g_kvsT_lo);
    cudaGetSymbolAddress((void**)&ksum,  g_ksum);
    cudaGetSymbolAddress((void**)&winv,  g_winv);
    cudaGetSymbolAddress((void**)&z,     g_z);
    cudaGetSymbolAddress((void**)&h1p,   g_h1p);
    cudaGetSymbolAddress((void**)&wpat,  g_wpat);
    cudaGetSymbolAddress((void**)&fused, g_fused);
    cudaGetSymbolAddress((void**)&rden,  g_rden);

    // 1) fused Q/K/V projections (HMMA)
    qkv_mma<<<dim3(BL/128, 2, 3), 256>>>(x, Wq_w, Wk_w, Wv_w,
                                         Wq_b, Wk_b, Wv_b, q, k, v);
    // 2) key feature map
    phi_kernel<<<BL*Hh/16, 256>>>(k, proj, nullptr, kdd, kdiag, krmax, 0);
    // 3) fused kmax + kp finalize
    kp_finalize<<<Bq*Hh, 256>>>(kdd, kdiag, krmax, kp);
    // 4) kvs on HMMA (register-prefetch pipeline)  <-- profiled launch slot
    kvs_mma<<<dim3(Bq*Hh, 4), 256>>>(kp, v, gum, kvsT_hi, kvsT_lo);
    // 5) query feature map
    phi_kernel<<<BL*Hh/16, 256>>>(q, proj, qp, nullptr, nullptr, nullptr, 1);
    // 6) ksum, 7) winv
    ksum_kernel<<<Bq*Hh, 256>>>(kp, gum, ksum);
    winv_kernel<<<Bq*Hh, 256>>>(qp, ksum, winv);
    // 8) z on HMMA (+winv reduction + LayerNorm, B prefetch)
    z_mma<<<dim3(Bq*Hh, 25), 256>>>(qp, kvsT_hi, kvsT_lo, winv, z, ln_g, ln_b);
    // 9) adjacency patch fusion (fp32 split-K)
    gemm_sk<<<dim3(4, 1, NSPLIT), 256>>>(adj, fc_w, h1p, 512, 128, 10000, KCHUNK);
    score_kernel<<<Bq*Pp, 256>>>(h1p, fc_b, out_w, out_b, wpat);
    fused_kernel<<<(160000 + 255)/256, 256>>>(adj, wpat, fused);
    rden_kernel<<<Bq*Pp*Nn/8, 256>>>(fused, rden);
    // 10) relational bias
    biasadd_kernel<<<dim3(Bq*Pp, 5), 256>>>(fused, rden, v, z);
    // 11) output projection (HMMA)
    wo_mma<<<dim3(BL/128, 2), 256>>>(z, Wo_w, Wo_b, out);
}

// round 15
// speedup vs baseline: 1.4633x; 1.0101x over previous
#include <cuda_runtime.h>
#include <cuda_bf16.h>
#include <math.h>
#include <stdint.h>

// ---------------- static problem config ----------------
#define Bq    8
#define Pp    8
#define Nn    100
#define Dm    256
#define Hh    8
#define DKk   32
#define Mm    64
#define Kg    16
#define Ll    800            // P*N
#define BL    6400           // B*L
#define NSPLIT 125
#define KCHUNK 80            // 125*80 = 10000

#define PHI_SCALE 0.84089641525f   // 2 * 32^-0.25
#define KVS_ELEMS (64*512*64)

typedef unsigned long long ull;

// ---------------- packed f32x2 helpers ----------------
__device__ __forceinline__ ull pack2(float x, float y) {
    ull r; asm("mov.b64 %0, {%1,%2};" : "=l"(r) : "f"(x), "f"(y)); return r;
}
__device__ __forceinline__ ull fma2(ull a, ull b, ull c) {
    ull d; asm("fma.rn.f32x2 %0, %1, %2, %3;" : "=l"(d) : "l"(a), "l"(b), "l"(c)); return d;
}
__device__ __forceinline__ float2 unpack2(ull p) {
    float2 r; asm("mov.b64 {%0,%1}, %2;" : "=f"(r.x), "=f"(r.y) : "l"(p)); return r;
}

// ---------------- scratch (device globals; no allocation) ----------------
__device__ __align__(16) float g_q   [BL*Dm];
__device__ __align__(16) float g_k   [BL*Dm];
__device__ __align__(16) float g_v   [BL*Dm];
__device__ __align__(16) float g_qp  [BL*Hh*Mm];
__device__ __align__(16) float g_kdd [BL*Hh*Mm];
__device__              float g_kdiag[BL*Hh];
__device__              float g_krmax[BL*Hh];
__device__ __align__(16) float g_kp  [BL*Hh*Mm];
__device__ __align__(16) __nv_bfloat16 g_kvsT_hi[KVS_ELEMS];
__device__ __align__(16) __nv_bfloat16 g_kvsT_lo[KVS_ELEMS];
__device__ __align__(16) float g_ksum[Bq*Hh*Kg*Mm];
__device__ __align__(16) float g_winv[BL*Hh*Kg];
__device__ __align__(16) float g_z   [BL*Dm];
__device__ __align__(16) float g_h1p [NSPLIT*512*128];
__device__              float g_wpat [512];
__device__ __align__(16) float g_fused[Bq*Pp*Nn*Nn];
__device__              float g_rden [Bq*Pp*Nn];

// ================= mma.sync primitive =================
__device__ __forceinline__ void mma16816(float* d, const uint32_t* a, const uint32_t* b)
{
    asm volatile(
        "mma.sync.aligned.m16n8k16.row.col.f32.bf16.bf16.f32 "
        "{%0,%1,%2,%3}, {%4,%5,%6,%7}, {%8,%9}, {%0,%1,%2,%3};"
        : "+f"(d[0]), "+f"(d[1]), "+f"(d[2]), "+f"(d[3])
        : "r"(a[0]), "r"(a[1]), "r"(a[2]), "r"(a[3]), "r"(b[0]), "r"(b[1]));
}

__device__ __forceinline__ void bf16_split(float f, __nv_bfloat16& hi, __nv_bfloat16& lo)
{
    hi = __float2bfloat16(f);
    lo = __float2bfloat16(f - __bfloat162float(hi));
}
__device__ __forceinline__ uint32_t pack_bf2(__nv_bfloat16 a, __nv_bfloat16 b)
{
    __nv_bfloat162 p = __halves2bfloat162(a, b);
    return reinterpret_cast<uint32_t&>(p);
}

// ================= projection GEMM body (bf16x3), smem passed in ============
#define SMS 40

__device__ __forceinline__ void load_slab32(const float* __restrict__ src,
                                            __nv_bfloat16* __restrict__ hi,
                                            __nv_bfloat16* __restrict__ lo, int tid)
{
    for (int idx = tid; idx < 1024; idx += 256) {
        int r = idx >> 3, c4 = (idx & 7) * 4;
        float4 f = *(const float4*)(src + (size_t)r * 256 + c4);
        __nv_bfloat16 h0, l0, h1, l1, h2, l2, h3, l3;
        bf16_split(f.x, h0, l0); bf16_split(f.y, h1, l1);
        bf16_split(f.z, h2, l2); bf16_split(f.w, h3, l3);
        uint2 hw = make_uint2(pack_bf2(h0, h1), pack_bf2(h2, h3));
        uint2 lw = make_uint2(pack_bf2(l0, l1), pack_bf2(l2, l3));
        *(uint2*)(hi + r * SMS + c4) = hw;
        *(uint2*)(lo + r * SMS + c4) = lw;
    }
}

__device__ __forceinline__ void mma_gemm_body(const float* __restrict__ A,
                                              const float* __restrict__ W,
                                              const float* __restrict__ bias,
                                              float* __restrict__ C,
                                              int row0, int col0,
                                              __nv_bfloat16* sm)
{
    __nv_bfloat16* Ah = sm;
    __nv_bfloat16* Al = sm + 128 * SMS;
    __nv_bfloat16* Wh = sm + 2 * 128 * SMS;
    __nv_bfloat16* Wl = sm + 3 * 128 * SMS;

    int tid = threadIdx.x, lane = tid & 31, warp = tid >> 5;
    int wm = warp & 3, wn = warp >> 2;
    int g = lane >> 2, tg = lane & 3;

    float d[2][8][4];
#pragma unroll
    for (int mt = 0; mt < 2; mt++)
#pragma unroll
        for (int nt = 0; nt < 8; nt++)
#pragma unroll
            for (int i = 0; i < 4; i++) d[mt][nt][i] = 0.f;

    for (int kc = 0; kc < 8; kc++) {
        load_slab32(A + (size_t)row0 * 256 + kc * 32, Ah, Al, tid);
        load_slab32(W + (size_t)col0 * 256 + kc * 32, Wh, Wl, tid);
        __syncthreads();
#pragma unroll
        for (int ks = 0; ks < 2; ks++) {
            int kb = ks * 16;
            uint32_t ah[2][4], al[2][4];
#pragma unroll
            for (int mt = 0; mt < 2; mt++) {
                int rb = wm * 32 + mt * 16;
                const __nv_bfloat16* p0 = &Ah[(rb + g) * SMS + kb + tg * 2];
                const __nv_bfloat16* p1 = &Ah[(rb + g + 8) * SMS + kb + tg * 2];
                ah[mt][0] = *(const uint32_t*)p0;
                ah[mt][1] = *(const uint32_t*)p1;
                ah[mt][2] = *(const uint32_t*)(p0 + 8);
                ah[mt][3] = *(const uint32_t*)(p1 + 8);
                const __nv_bfloat16* q0 = &Al[(rb + g) * SMS + kb + tg * 2];
                const __nv_bfloat16* q1 = &Al[(rb + g + 8) * SMS + kb + tg * 2];
                al[mt][0] = *(const uint32_t*)q0;
                al[mt][1] = *(const uint32_t*)q1;
                al[mt][2] = *(const uint32_t*)(q0 + 8);
                al[mt][3] = *(const uint32_t*)(q1 + 8);
            }
#pragma unroll
            for (int nt = 0; nt < 8; nt++) {
                int nb = wn * 64 + nt * 8;
                const __nv_bfloat16* qh = &Wh[(nb + g) * SMS + kb + tg * 2];
                const __nv_bfloat16* ql = &Wl[(nb + g) * SMS + kb + tg * 2];
                uint32_t bh2[2] = {*(const uint32_t*)qh, *(const uint32_t*)(qh + 8)};
                uint32_t bl2[2] = {*(const uint32_t*)ql, *(const uint32_t*)(ql + 8)};
#pragma unroll
                for (int mt = 0; mt < 2; mt++) {
                    mma16816(d[mt][nt], ah[mt], bh2);
                    mma16816(d[mt][nt], ah[mt], bl2);
                    mma16816(d[mt][nt], al[mt], bh2);
                }
            }
        }
        __syncthreads();
    }

#pragma unroll
    for (int mt = 0; mt < 2; mt++) {
        int r0 = row0 + wm * 32 + mt * 16 + g;
#pragma unroll
        for (int nt = 0; nt < 8; nt++) {
            int col = col0 + wn * 64 + nt * 8 + tg * 2;
            float2 b2 = *(const float2*)&bias[col];
            float2 o0 = make_float2(d[mt][nt][0] + b2.x, d[mt][nt][1] + b2.y);
            float2 o1 = make_float2(d[mt][nt][2] + b2.x, d[mt][nt][3] + b2.y);
            *(float2*)&C[(size_t)r0 * 256 + col]       = o0;
            *(float2*)&C[(size_t)(r0 + 8) * 256 + col] = o1;
        }
    }
}

// ================= fp32 GEMM body (fc split-K), smem passed in ==============
__device__ __forceinline__ void gemm128_body(const float* __restrict__ A,
                                             const float* __restrict__ W,
                                             float* __restrict__ C,
                                             int Nc, int Kd, int k0, int klen,
                                             int row0, int col0, float* smem)
{
    typedef float Tile[16][132];
    Tile* As = (Tile*)smem;
    Tile* Ws = (Tile*)(smem + 2 * 16 * 132);
    int tid = threadIdx.x;
    int tx = tid & 15, ty = tid >> 4;
    int lr = tid >> 1, lc = (tid & 1) * 8;

    const float* Ap = A + (size_t)(row0 + lr) * Kd + k0 + lc;
    const float* Wp = W + (size_t)(col0 + lr) * Kd + k0 + lc;

    ull acc[8][4];
#pragma unroll
    for (int i = 0; i < 8; i++)
#pragma unroll
        for (int j = 0; j < 4; j++) acc[i][j] = 0ULL;

    float4 pa0 = *(const float4*)(Ap);
    float4 pa1 = *(const float4*)(Ap + 4);
    float4 pw0 = *(const float4*)(Wp);
    float4 pw1 = *(const float4*)(Wp + 4);

    int nk = klen >> 4;
    int buf = 0;
    for (int it = 0; it < nk; it++) {
        As[buf][lc+0][lr] = pa0.x; As[buf][lc+1][lr] = pa0.y;
        As[buf][lc+2][lr] = pa0.z; As[buf][lc+3][lr] = pa0.w;
        As[buf][lc+4][lr] = pa1.x; As[buf][lc+5][lr] = pa1.y;
        As[buf][lc+6][lr] = pa1.z; As[buf][lc+7][lr] = pa1.w;
        Ws[buf][lc+0][lr] = pw0.x; Ws[buf][lc+1][lr] = pw0.y;
        Ws[buf][lc+2][lr] = pw0.z; Ws[buf][lc+3][lr] = pw0.w;
        Ws[buf][lc+4][lr] = pw1.x; Ws[buf][lc+5][lr] = pw1.y;
        Ws[buf][lc+6][lr] = pw1.z; Ws[buf][lc+7][lr] = pw1.w;
        __syncthreads();
        if (it + 1 < nk) {
            int off = (it + 1) * 16;
            pa0 = *(const float4*)(Ap + off);
            pa1 = *(const float4*)(Ap + off + 4);
            pw0 = *(const float4*)(Wp + off);
            pw1 = *(const float4*)(Wp + off + 4);
        }
#pragma unroll
        for (int c = 0; c < 16; c++) {
            float4 a0 = *(const float4*)&As[buf][c][ty*4];
            float4 a1 = *(const float4*)&As[buf][c][64 + ty*4];
            ulonglong2 w01 = *(const ulonglong2*)&Ws[buf][c][tx*4];
            ulonglong2 w23 = *(const ulonglong2*)&Ws[buf][c][64 + tx*4];
            ull wp[4] = {w01.x, w01.y, w23.x, w23.y};
            float av[8] = {a0.x,a0.y,a0.z,a0.w, a1.x,a1.y,a1.z,a1.w};
#pragma unroll
            for (int i = 0; i < 8; i++) {
                ull ad = pack2(av[i], av[i]);
#pragma unroll
                for (int j = 0; j < 4; j++) acc[i][j] = fma2(ad, wp[j], acc[i][j]);
            }
        }
        buf ^= 1;
        __syncthreads();
    }

#pragma unroll
    for (int i = 0; i < 8; i++) {
        int rr = row0 + ((i < 4) ? (ty*4 + i) : (64 + ty*4 + i - 4));
        float2 p0 = unpack2(acc[i][0]);
        float2 p1 = unpack2(acc[i][1]);
        float2 p2 = unpack2(acc[i][2]);
        float2 p3 = unpack2(acc[i][3]);
        float4 o0 = make_float4(p0.x, p0.y, p1.x, p1.y);
        float4 o1 = make_float4(p2.x, p2.y, p3.x, p3.y);
        *(float4*)&C[(size_t)rr * Nc + col0 + tx*4]      = o0;
        *(float4*)&C[(size_t)rr * Nc + col0 + 64 + tx*4] = o1;
    }
}

// ================= STAGE A: qkv (300) || fc split-K (500) ===================
__global__ void __launch_bounds__(256) stage_a(
    const float* __restrict__ x,
    const float* __restrict__ Wq, const float* __restrict__ Wk, const float* __restrict__ Wv,
    const float* __restrict__ bq, const float* __restrict__ bk, const float* __restrict__ bv,
    float* __restrict__ q, float* __restrict__ k, float* __restrict__ v,
    const float* __restrict__ adj, const float* __restrict__ fc_w, float* __restrict__ h1p)
{
    extern __shared__ __align__(16) char uni[];
    int blk = blockIdx.x;
    if (blk < 300) {
        int bx = blk % 50, by = (blk / 50) & 1, bz = blk / 100;
        const float* W = bz == 0 ? Wq : (bz == 1 ? Wk : Wv);
        const float* bb = bz == 0 ? bq : (bz == 1 ? bk : bv);
        float* C = bz == 0 ? q : (bz == 1 ? k : v);
        mma_gemm_body(x, W, bb, C, bx * 128, by * 128, (__nv_bfloat16*)uni);
    } else {
        int s = blk - 300;
        int bx = s & 3, bz = s >> 2;
        gemm128_body(adj, fc_w, h1p + (size_t)bz * 512 * 128,
                     128, 10000, bz * KCHUNK, KCHUNK, bx * 128, 0, (float*)uni);
    }
}

// ================= STAGE B: phi_k (3200) || phi_q (3200) || score (64) ======
__device__ __forceinline__ void phi_body(const float* __restrict__ din,
                                         const float* __restrict__ proj,
                                         float* __restrict__ outphi,
                                         float* __restrict__ dd_out,
                                         float* __restrict__ diag_out,
                                         float* __restrict__ rmax_out,
                                         int is_query, int bx)
{
    __shared__ __align__(16) float proj_s[64][34];
    __shared__ __align__(16) float data_s[4][32];
    __shared__ float wmax[4][2];
    int tid = threadIdx.x;
    for (int i = tid; i < 2048; i += 256) proj_s[i >> 5][i & 31] = proj[i];
    int sub = tid >> 6;
    int m = tid & 63;
    int u0 = bx * 16;
    for (int g = 0; g < 16; g += 4) {
        int u = u0 + g + sub;
        __syncthreads();
        if (m < 32) data_s[sub][m] = din[(size_t)u*32 + m] * PHI_SCALE;
        __syncthreads();
        ull dd2 = 0ULL, dg2 = 0ULL;
#pragma unroll
        for (int d2 = 0; d2 < 16; d2++) {
            ull x2 = *(const ull*)&data_s[sub][d2*2];
            ull p2 = *(const ull*)&proj_s[m][d2*2];
            dd2 = fma2(x2, p2, dd2);
            dg2 = fma2(x2, x2, dg2);
        }
        float2 dp = unpack2(dd2);
        float2 gp = unpack2(dg2);
        float dd = dp.x + dp.y;
        float diag = 0.5f * (gp.x + gp.y);
        float mx = dd;
#pragma unroll
        for (int o = 16; o > 0; o >>= 1) mx = fmaxf(mx, __shfl_xor_sync(0xffffffffu, mx, o));
        if ((tid & 31) == 0) wmax[sub][m >> 5] = mx;
        __syncthreads();
        float stab = fmaxf(wmax[sub][0], wmax[sub][1]);
        if (is_query) {
            outphi[(size_t)u*64 + m] = 0.125f * (expf(dd - diag - stab) + 1e-6f);
        } else {
            dd_out[(size_t)u*64 + m] = dd;
            if (m == 0) { diag_out[u] = diag; rmax_out[u] = stab; }
        }
    }
}

__device__ __forceinline__ void score_body(const float* __restrict__ h1p,
                                           const float* __restrict__ fc_b,
                                           const float* __restrict__ out_w,
                                           const float* __restrict__ out_b,
                                           float* __restrict__ wout, int bp)
{
    int t = threadIdx.x >> 5, lane = threadIdx.x & 31;
    __shared__ float sc[8];
    float p = 0.f;
    for (int j = lane; j < 128; j += 32) {
        float hv = fc_b[j];
        for (int s = 0; s < NSPLIT; s++) hv += h1p[(size_t)s*65536 + (bp*8 + t)*128 + j];
        hv = fmaxf(hv, 0.f);
        p += hv * out_w[j];
    }
#pragma unroll
    for (int o = 16; o > 0; o >>= 1) p += __shfl_xor_sync(0xffffffffu, p, o);
    if (lane == 0) sc[t] = p + out_b[0];
    __syncthreads();
    if (threadIdx.x == 0) {
        float mx = sc[0];
#pragma unroll
        for (int i = 1; i < 8; i++) mx = fmaxf(mx, sc[i]);
        float e[8], sum = 0.f;
#pragma unroll
        for (int i = 0; i < 8; i++) { e[i] = expf(sc[i] - mx); sum += e[i]; }
#pragma unroll
        for (int i = 0; i < 8; i++) wout[bp*8 + i] = e[i] / sum;
    }
}

__global__ void __launch_bounds__(256) stage_b(
    const float* __restrict__ q, const float* __restrict__ k,
    const float* __restrict__ proj,
    float* __restrict__ qp, float* __restrict__ kdd,
    float* __restrict__ kdiag, float* __restrict__ krmax,
    const float* __restrict__ h1p, const float* __restrict__ fc_b,
    const float* __restrict__ out_w, const float* __restrict__ out_b,
    float* __restrict__ wpat)
{
    int blk = blockIdx.x;
    if (blk < 6400) {
        int isq = blk >= 3200;
        int bx = isq ? blk - 3200 : blk;
        phi_body(isq ? q : k, proj, qp, kdd, kdiag, krmax, isq, bx);
    } else {
        score_body(h1p, fc_b, out_w, out_b, wpat, blk - 6400);
    }
}

// ================= STAGE C: kp_finalize (64) || fused (625) =================
__device__ __forceinline__ void kp_finalize_body(const float* __restrict__ kdd,
                                                 const float* __restrict__ kdiag,
                                                 const float* __restrict__ krmax,
                                                 float* __restrict__ kp, int bh)
{
    int b = bh >> 3, h = bh & 7;
    int t = threadIdx.x;
    __shared__ float red[256];
    float mx = -1e30f;
    for (int l = t; l < Ll; l += 256) mx = fmaxf(mx, krmax[(b*Ll + l)*Hh + h]);
    red[t] = mx; __syncthreads();
    for (int s = 128; s > 0; s >>= 1) {
        if (t < s) red[t] = fmaxf(red[t], red[t + s]);
        __syncthreads();
    }
    float km = red[0];
    for (int i = t; i < Ll * 64; i += 256) {
        int l = i >> 6, m = i & 63;
        size_t u = (size_t)(b*Ll + l)*Hh + h;
        kp[u*64 + m] = 0.125f * (expf(kdd[u*64 + m] - kdiag[u] - km) + 1e-6f);
    }
}

__device__ __forceinline__ void fused_body(const float* __restrict__ adj,
                                           const float* __restrict__ wpat,
                                           float* __restrict__ fused, int blk)
{
    int i4 = blk * 256 + threadIdx.x;    // < 160000
    if (i4 >= 160000) return;
    int bp = i4 / 2500;
    int r4 = i4 - bp * 2500;
    float4 s = make_float4(0,0,0,0);
#pragma unroll
    for (int t = 0; t < 8; t++) {
        float w = wpat[bp*8 + t];
        float4 a = *(const float4*)&adj[(size_t)(bp*8 + t)*10000 + r4*4];
        s.x += a.x*w; s.y += a.y*w; s.z += a.z*w; s.w += a.w*w;
    }
    *(float4*)&fused[(size_t)bp*10000 + r4*4] = s;
}

__global__ void __launch_bounds__(256) stage_c(
    const float* __restrict__ kdd, const float* __restrict__ kdiag,
    const float* __restrict__ krmax, float* __restrict__ kp,
    const float* __restrict__ adj, const float* __restrict__ wpat,
    float* __restrict__ fused)
{
    int blk = blockIdx.x;
    if (blk < 64) kp_finalize_body(kdd, kdiag, krmax, kp, blk);
    else          fused_body(adj, wpat, fused, blk - 64);
}

// ================= STAGE D: kvs (256) || rden (800) || ksum (64) ============
#define SA 36
__device__ __forceinline__ void kvs_body(
    const float* __restrict__ kp, const float* __restrict__ v,
    const float* __restrict__ gum,
    __nv_bfloat16* __restrict__ kvsT_hi, __nv_bfloat16* __restrict__ kvsT_lo,
    int bh, int qq)
{
    __shared__ __align__(16) __nv_bfloat16 As_hi[64*SA], As_lo[64*SA];
    __shared__ __align__(16) __nv_bfloat16 Bs_hi[128*SA], Bs_lo[128*SA];
    __shared__ float v_s[32][32];
    __shared__ float e_s[32][4];

    int b = bh >> 3, h = bh & 7;
    int t = threadIdx.x, lane = t & 31, warp = t >> 5;
    int wm = warp & 3, wn = warp >> 2;
    int g = lane >> 2, tg = lane & 3;

    int vl = t >> 3, vd4 = (t & 7) * 4;
    int el = t >> 2, ekq = t & 3;

    float d[8][4];
#pragma unroll
    for (int nt = 0; nt < 8; nt++)
#pragma unroll
        for (int i = 0; i < 4; i++) d[nt][i] = 0.f;

    float4 pv;
    float pe = 0.f;
    float pk0[4], pk1[4];
    {
        pv = *(const float4*)&v[(size_t)(b*Ll + vl)*Dm + h*32 + vd4];
        if (t < 128) pe = gum[(((b*Ll + el)*Hh + h) << 4) + qq*4 + ekq];
#pragma unroll
        for (int j = 0; j < 4; j++) {
            int idx = t + j * 256;
            int m = idx & 63, lp = idx >> 6;
            int l = lp * 2;
            pk0[j] = kp[((size_t)((b*Ll + l    )*Hh + h) << 6) + m];
            pk1[j] = kp[((size_t)((b*Ll + l + 1)*Hh + h) << 6) + m];
        }
    }

    for (int ci = 0; ci < 25; ci++) {
        *(float4*)&v_s[vl][vd4] = pv;
        if (t < 128) e_s[el][ekq] = expf(pe);
#pragma unroll
        for (int j = 0; j < 4; j++) {
            int idx = t + j * 256;
            int m = idx & 63, lp = idx >> 6;
            __nv_bfloat16 h0, lo0, h1, lo1;
            bf16_split(pk0[j], h0, lo0); bf16_split(pk1[j], h1, lo1);
            *(uint32_t*)&As_hi[m*SA + lp*2] = pack_bf2(h0, h1);
            *(uint32_t*)&As_lo[m*SA + lp*2] = pack_bf2(lo0, lo1);
        }
        __syncthreads();
        {
            int n = t >> 1;
            int lpb = (t & 1) * 8;
            int kq = n >> 5, dd2 = n & 31;
#pragma unroll
            for (int j = 0; j < 8; j++) {
                int lp = lpb + j;
                float f0 = e_s[2*lp][kq]     * v_s[2*lp][dd2];
                float f1 = e_s[2*lp + 1][kq] * v_s[2*lp + 1][dd2];
                __nv_bfloat16 h0, lo0, h1, lo1;
                bf16_split(f0, h0, lo0); bf16_split(f1, h1, lo1);
                *(uint32_t*)&Bs_hi[n*SA + lp*2] = pack_bf2(h0, h1);
                *(uint32_t*)&Bs_lo[n*SA + lp*2] = pack_bf2(lo0, lo1);
            }
        }
        if (ci < 24) {
            int l0 = (ci + 1) * 32;
            pv = *(const float4*)&v[(size_t)(b*Ll + l0 + vl)*Dm + h*32 + vd4];
            if (t < 128) pe = gum[(((b*Ll + l0 + el)*Hh + h) << 4) + qq*4 + ekq];
#pragma unroll
            for (int j = 0; j < 4; j++) {
                int idx = t + j * 256;
                int m = idx & 63, lp = idx >> 6;
                int l = l0 + lp * 2;
                pk0[j] = kp[((size_t)((b*Ll + l    )*Hh + h) << 6) + m];
                pk1[j] = kp[((size_t)((b*Ll + l + 1)*Hh + h) << 6) + m];
            }
        }
        __syncthreads();
#pragma unroll
        for (int ks = 0; ks < 2; ks++) {
            int kb = ks * 16;
            uint32_t ah[4], al[4];
            {
                int rb = wm * 16;
                const __nv_bfloat16* p0 = &As_hi[(rb + g) * SA + kb + tg*2];
                const __nv_bfloat16* p1 = &As_hi[(rb + g + 8) * SA + kb + tg*2];
                ah[0] = *(const uint32_t*)p0;
                ah[1] = *(const uint32_t*)p1;
                ah[2] = *(const uint32_t*)(p0 + 8);
                ah[3] = *(const uint32_t*)(p1 + 8);
                const __nv_bfloat16* q0 = &As_lo[(rb + g) * SA + kb + tg*2];
                const __nv_bfloat16* q1 = &As_lo[(rb + g + 8) * SA + kb + tg*2];
                al[0] = *(const uint32_t*)q0;
                al[1] = *(const uint32_t*)q1;
                al[2] = *(const uint32_t*)(q0 + 8);
                al[3] = *(const uint32_t*)(q1 + 8);
            }
#pragma unroll
            for (int nt = 0; nt < 8; nt++) {
                int nb = wn * 64 + nt * 8;
                const __nv_bfloat16* qh = &Bs_hi[(nb + g) * SA + kb + tg*2];
                const __nv_bfloat16* ql = &Bs_lo[(nb + g) * SA + kb + tg*2];
                uint32_t bh2[2] = {*(const uint32_t*)qh, *(const uint32_t*)(qh + 8)};
                uint32_t bl2[2] = {*(const uint32_t*)ql, *(const uint32_t*)(ql + 8)};
                mma16816(d[nt], ah, bh2);
                mma16816(d[nt], ah, bl2);
                mma16816(d[nt], al, bh2);
            }
        }
        __syncthreads();
    }
    int m = wm * 16 + g;
#pragma unroll
    for (int nt = 0; nt < 8; nt++) {
        int n = qq*128 + wn*64 + nt*8 + tg*2;
        size_t base0 = ((size_t)bh * 512 + n) * 64;
        size_t base1 = base0 + 64;
        __nv_bfloat16 hi, lo;
        bf16_split(d[nt][0], hi, lo); kvsT_hi[base0 + m] = hi;     kvsT_lo[base0 + m] = lo;
        bf16_split(d[nt][1], hi, lo); kvsT_hi[base1 + m] = hi;     kvsT_lo[base1 + m] = lo;
        bf16_split(d[nt][2], hi, lo); kvsT_hi[base0 + m + 8] = hi; kvsT_lo[base0 + m + 8] = lo;
        bf16_split(d[nt][3], hi, lo); kvsT_hi[base1 + m + 8] = hi; kvsT_lo[base1 + m + 8] = lo;
    }
}

__device__ __forceinline__ void rden_body(const float* __restrict__ fused,
                                          float* __restrict__ rden, int blk)
{
    int w = threadIdx.x >> 5, lane = threadIdx.x & 31;
    int row = blk * 8 + w;
    float s = 0.f;
    for (int j = lane; j < 100; j += 32) s += fabsf(fused[(size_t)row*100 + j]);
#pragma unroll
    for (int o = 16; o > 0; o >>= 1) s += __shfl_xor_sync(0xffffffffu, s, o);
    if (lane == 0) rden[row] = fmaxf(s, 1e-12f);
}

__device__ __forceinline__ void ksum_body(const float* __restrict__ kp,
                                          const float* __restrict__ gum,
                                          float* __restrict__ ksum, int bh)
{
    __shared__ __align__(16) float kp_s[16][64];
    __shared__ float eg_s[16][16];
    int b = bh >> 3, h = bh & 7;
    int t = threadIdx.x;
    int lc = t >> 4, lf = t & 15;
    float4 acc = make_float4(0,0,0,0);
    for (int l0 = 0; l0 < Ll; l0 += 16) {
        __syncthreads();
        *(float4*)&kp_s[lc][lf*4] =
            *(const float4*)&kp[((size_t)((b*Ll + l0 + lc)*Hh + h) << 6) + lf*4];
        eg_s[lc][lf] = expf(gum[(((b*Ll + l0 + lc)*Hh + h) << 4) + lf]);
        __syncthreads();
#pragma unroll
        for (int c = 0; c < 16; c++) {
            float e = eg_s[c][lc];
            float4 kp4 = *(const float4*)&kp_s[c][lf*4];
            acc.x += kp4.x * e; acc.y += kp4.y * e;
            acc.z += kp4.z * e; acc.w += kp4.w * e;
        }
    }
    *(float4*)&ksum[((size_t)(bh*16 + lc) << 6) + lf*4] = acc;
}

__global__ void __launch_bounds__(256) stage_d(
    const float* __restrict__ kp, const float* __restrict__ v,
    const float* __restrict__ gum,
    __nv_bfloat16* __restrict__ kvsT_hi, __nv_bfloat16* __restrict__ kvsT_lo,
    const float* __restrict__ fused, float* __restrict__ rden,
    float* __restrict__ ksum)
{
    int blk = blockIdx.x;
    if (blk < 256)       kvs_body(kp, v, gum, kvsT_hi, kvsT_lo, blk & 63, blk >> 6);
    else if (blk < 1056) rden_body(fused, rden, blk - 256);
    else                 ksum_body(kp, gum, ksum, blk - 1056);
}

// ---------------- winv (standalone) ----------------
__global__ void winv_kernel(const float* __restrict__ qp, const float* __restrict__ ksum,
                            float* __restrict__ winv)
{
    __shared__ __align__(16) float ks_s[16][64];
    __shared__ __align__(16) float qp_s[16][64];
    int bh = blockIdx.x; int b = bh >> 3, h = bh & 7;
    int t = threadIdx.x;
    int lc = t >> 4, lf = t & 15;
    *(float4*)&ks_s[lc][lf*4] = *(const float4*)&ksum[((size_t)(bh*16 + lc) << 6) + lf*4];
    for (int l0 = 0; l0 < Ll; l0 += 16) {
        __syncthreads();
        *(float4*)&qp_s[lc][lf*4] =
            *(const float4*)&qp[((size_t)((b*Ll + l0 + lc)*Hh + h) << 6) + lf*4];
        __syncthreads();
        ull d2 = 0ULL;
#pragma unroll
        for (int m2 = 0; m2 < 32; m2++) {
            ull q2 = *(const ull*)&qp_s[lc][m2*2];
            ull k2 = *(const ull*)&ks_s[lf][m2*2];
            d2 = fma2(q2, k2, d2);
        }
        float2 dp = unpack2(d2);
        winv[(((b*Ll + l0 + lc)*Hh + h) << 4) + lf] =
            1.0f / ((dp.x + dp.y + 1e-8f) * 16.0f);
    }
}

// ================= z on HMMA + winv reduction + LayerNorm (prefetch) =========
#define SQ 68
__global__ void __launch_bounds__(256) z_mma(
    const float* __restrict__ qp,
    const __nv_bfloat16* __restrict__ kvsT_hi, const __nv_bfloat16* __restrict__ kvsT_lo,
    const float* __restrict__ winv, float* __restrict__ z,
    const float* __restrict__ ln_g, const float* __restrict__ ln_b)
{
    __shared__ __align__(16) __nv_bfloat16 Aq_hi[32*SQ], Aq_lo[32*SQ];
    __shared__ __align__(16) __nv_bfloat16 Bs_hi[64*SQ], Bs_lo[64*SQ];
    __shared__ float winv_s[32][16];
    __shared__ float zred[4][32][33];

    int bh = blockIdx.x;
    int b = bh >> 3, h = bh & 7;
    int l0 = blockIdx.y * 32;
    int t = threadIdx.x, lane = t & 31, warp = t >> 5;
    int wm = warp & 1, wn = warp >> 1;
    int g = lane >> 2, tg = lane & 3;

    uint32_t pbh[8], pbl[8];
#pragma unroll
    for (int j = 0; j < 8; j++) {
        int idx = t + j * 256;
        int n = idx >> 5, m2 = (idx & 31) * 2;
        size_t src = ((size_t)bh * 512 + n) * 64 + m2;
        pbh[j] = *(const uint32_t*)&kvsT_hi[src];
        pbl[j] = *(const uint32_t*)&kvsT_lo[src];
    }

#pragma unroll
    for (int j = 0; j < 2; j++) {
        int idx = t + j * 256;
        int l = idx >> 4, m4 = (idx & 15) * 4;
        float4 q4 = *(const float4*)&qp[((size_t)((b*Ll + l0 + l)*Hh + h) << 6) + m4];
        float fv[4] = {q4.x, q4.y, q4.z, q4.w};
#pragma unroll
        for (int i = 0; i < 4; i++) {
            __nv_bfloat16 hi, lo; bf16_split(fv[i], hi, lo);
            Aq_hi[l*SQ + m4 + i] = hi;
            Aq_lo[l*SQ + m4 + i] = lo;
        }
    }
#pragma unroll
    for (int j = 0; j < 2; j++) {
        int idx = t + j * 256;
        int l = idx >> 4, kk = idx & 15;
        winv_s[l][kk] = winv[(((b*Ll + l0 + l)*Hh + h) << 4) + kk];
    }
    for (int idx = t; idx < 4*32*33; idx += 256) ((float*)zred)[idx] = 0.f;
    __syncthreads();

    for (int ch = 0; ch < 8; ch++) {
#pragma unroll
        for (int j = 0; j < 8; j++) {
            int idx = t + j * 256;
            int n = idx >> 5, m2 = (idx & 31) * 2;
            *(uint32_t*)&Bs_hi[n*SQ + m2] = pbh[j];
            *(uint32_t*)&Bs_lo[n*SQ + m2] = pbl[j];
        }
        __syncthreads();
        if (ch < 7) {
#pragma unroll
            for (int j = 0; j < 8; j++) {
                int idx = t + j * 256;
                int n = idx >> 5, m2 = (idx & 31) * 2;
                size_t src = ((size_t)bh * 512 + (ch + 1)*64 + n) * 64 + m2;
                pbh[j] = *(const uint32_t*)&kvsT_hi[src];
                pbl[j] = *(const uint32_t*)&kvsT_lo[src];
            }
        }

        float dfr[2][4];
#pragma unroll
        for (int nt = 0; nt < 2; nt++)
#pragma unroll
            for (int i = 0; i < 4; i++) dfr[nt][i] = 0.f;

#pragma unroll
        for (int ks = 0; ks < 4; ks++) {
            int kb = ks * 16;
            uint32_t ah[4], al[4];
            {
                int rb = wm * 16;
                const __nv_bfloat16* p0 = &Aq_hi[(rb + g) * SQ + kb + tg*2];
                const __nv_bfloat16* p1 = &Aq_hi[(rb + g + 8) * SQ + kb + tg*2];
                ah[0] = *(const uint32_t*)p0;
                ah[1] = *(const uint32_t*)p1;
                ah[2] = *(const uint32_t*)(p0 + 8);
                ah[3] = *(const uint32_t*)(p1 + 8);
                const __nv_bfloat16* q0 = &Aq_lo[(rb + g) * SQ + kb + tg*2];
                const __nv_bfloat16* q1 = &Aq_lo[(rb + g + 8) * SQ + kb + tg*2];
                al[0] = *(const uint32_t*)q0;
                al[1] = *(const uint32_t*)q1;
                al[2] = *(const uint32_t*)(q0 + 8);
                al[3] = *(const uint32_t*)(q1 + 8);
            }
#pragma unroll
            for (int nt = 0; nt < 2; nt++) {
                int nb = wn * 16 + nt * 8;
                const __nv_bfloat16* qh = &Bs_hi[(nb + g) * SQ + kb + tg*2];
                const __nv_bfloat16* ql = &Bs_lo[(nb + g) * SQ + kb + tg*2];
                uint32_t bh2[2] = {*(const uint32_t*)qh, *(const uint32_t*)(qh + 8)};
                uint32_t bl2[2] = {*(const uint32_t*)ql, *(const uint32_t*)(ql + 8)};
                mma16816(dfr[nt], ah, bh2);
                mma16816(dfr[nt], ah, bl2);
                mma16816(dfr[nt], al, bh2);
            }
        }
        int k = ch*2 + (wn >> 1);
        int la = wm*16 + g, lb = la + 8;
        float wia = winv_s[la][k], wib = winv_s[lb][k];
#pragma unroll
        for (int nt = 0; nt < 2; nt++) {
            int dl = (wn & 1)*16 + nt*8 + tg*2;
            zred[wn][la][dl]     += dfr[nt][0] * wia;
            zred[wn][la][dl + 1] += dfr[nt][1] * wia;
            zred[wn][lb][dl]     += dfr[nt][2] * wib;
            zred[wn][lb][dl + 1] += dfr[nt][3] * wib;
        }
        __syncthreads();
    }

    float gl = ln_g[lane], bl = ln_b[lane];
#pragma unroll
    for (int j = 0; j < 4; j++) {
        int tok = warp + j * 8;
        float ss = zred[0][tok][lane] + zred[1][tok][lane]
                 + zred[2][tok][lane] + zred[3][tok][lane];
        float mu = ss;
#pragma unroll
        for (int o = 16; o > 0; o >>= 1) mu += __shfl_xor_sync(0xffffffffu, mu, o);
        mu *= (1.0f / 32.0f);
        float df = ss - mu;
        float v2 = df * df;
#pragma unroll
        for (int o = 16; o > 0; o >>= 1) v2 += __shfl_xor_sync(0xffffffffu, v2, o);
        float var = v2 * (1.0f / 32.0f);
        z[(size_t)(b*Ll + l0 + tok)*Dm + h*32 + lane] =
            df * rsqrtf(var + 1e-5f) * gl + bl;
    }
}

// relational bias: z += (fused/rden) @ V (FFMA2); grid (64, 5)
__global__ void biasadd_kernel(const float* __restrict__ fused, const float* __restrict__ rden,
                               const float* __restrict__ v, float* __restrict__ z)
{
    __shared__ __align__(16) float A_s[20][102];
    int blk = blockIdx.x;
    int i0 = blockIdx.y * 20;
    int t = threadIdx.x;
    for (int idx = t; idx < 2000; idx += 256) {
        int i = idx / 100, j = idx - i * 100;
        A_s[i][j] = fused[(size_t)blk*10000 + (i0 + i)*100 + j] / rden[blk*100 + i0 + i];
    }
    __syncthreads();
    int base = blk * 100;
    ull accp[20];
#pragma unroll
    for (int ii = 0; ii < 20; ii++) accp[ii] = 0ULL;
    for (int j = 0; j < 100; j += 2) {
        float vj0 = v[(size_t)(base + j)*256 + t];
        float vj1 = v[(size_t)(base + j + 1)*256 + t];
        ull vp = pack2(vj0, vj1);
#pragma unroll
        for (int ii = 0; ii < 20; ii++)
            accp[ii] = fma2(*(const ull*)&A_s[ii][j], vp, accp[ii]);
    }
#pragma unroll
    for (int ii = 0; ii < 20; ii++) {
        float2 p = unpack2(accp[ii]);
        z[(size_t)(base + i0 + ii)*256 + t] += p.x + p.y;
    }
}

// ---------------- wo projection (standalone, static smem) ----------------
__global__ void __launch_bounds__(256) wo_mma(
    const float* __restrict__ A, const float* __restrict__ W,
    const float* __restrict__ b, float* __restrict__ C)
{
    __shared__ __align__(16) __nv_bfloat16 sm[4 * 128 * SMS];
    mma_gemm_body(A, W, b, C, blockIdx.x * 128, blockIdx.y * 128, sm);
}

// ---------------- launcher: fused-stage serial graph ----------------
extern "C" void kernel_launch(void* const* d_in, const int* in_sizes, int n_in,
                              void* d_out, int out_size)
{
    const float* x     = (const float*)d_in[0];
    const float* adj   = (const float*)d_in[1];
    const float* Wq_w  = (const float*)d_in[2];
    const float* Wq_b  = (const float*)d_in[3];
    const float* Wk_w  = (const float*)d_in[4];
    const float* Wk_b  = (const float*)d_in[5];
    const float* Wv_w  = (const float*)d_in[6];
    const float* Wv_b  = (const float*)d_in[7];
    const float* Wo_w  = (const float*)d_in[8];
    const float* Wo_b  = (const float*)d_in[9];
    const float* ln_g  = (const float*)d_in[10];
    const float* ln_b  = (const float*)d_in[11];
    const float* fc_w  = (const float*)d_in[12];
    const float* fc_b  = (const float*)d_in[13];
    const float* out_w = (const float*)d_in[14];
    const float* out_b = (const float*)d_in[15];
    const float* proj  = (const float*)d_in[16];
    const float* gum   = (const float*)d_in[17];
    float* out = (float*)d_out;

    float *q, *k, *v, *qp, *kdd, *kdiag, *krmax, *kp, *ksum, *winv, *z;
    float *h1p, *wpat, *fused, *rden;
    __nv_bfloat16 *kvsT_hi, *kvsT_lo;
    cudaGetSymbolAddress((void**)&q,     g_q);
    cudaGetSymbolAddress((void**)&k,     g_k);
    cudaGetSymbolAddress((void**)&v,     g_v);
    cudaGetSymbolAddress((void**)&qp,    g_qp);
    cudaGetSymbolAddress((void**)&kdd,   g_kdd);
    cudaGetSymbolAddress((void**)&kdiag, g_kdiag);
    cudaGetSymbolAddress((void**)&krmax, g_krmax);
    cudaGetSymbolAddress((void**)&kp,    g_kp);
    cudaGetSymbolAddress((void**)&kvsT_hi, g_kvsT_hi);
    cudaGetSymbolAddress((void**)&kvsT_lo, g_kvsT_lo);
    cudaGetSymbolAddress((void**)&ksum,  g_ksum);
    cudaGetSymbolAddress((void**)&winv,  g_winv);
    cudaGetSymbolAddress((void**)&z,     g_z);
    cudaGetSymbolAddress((void**)&h1p,   g_h1p);
    cudaGetSymbolAddress((void**)&wpat,  g_wpat);
    cudaGetSymbolAddress((void**)&fused, g_fused);
    cudaGetSymbolAddress((void**)&rden,  g_rden);

    // A) qkv || adjacency fc (union dynamic smem: 40960 B)
    stage_a<<<800, 256, 40960>>>(x, Wq_w, Wk_w, Wv_w, Wq_b, Wk_b, Wv_b,
                                 q, k, v, adj, fc_w, h1p);
    // B) phi_k || phi_q || score
    stage_b<<<6464, 256>>>(q, k, proj, qp, kdd, kdiag, krmax,
                           h1p, fc_b, out_w, out_b, wpat);
    // C) kp finalize || fused adjacency
    stage_c<<<689, 256>>>(kdd, kdiag, krmax, kp, adj, wpat, fused);
    // D) kvs || rden || ksum   <-- profiled launch slot
    stage_d<<<1120, 256>>>(kp, v, gum, kvsT_hi, kvsT_lo, fused, rden, ksum);
    // E) winv
    winv_kernel<<<Bq*Hh, 256>>>(qp, ksum, winv);
    // F) z (+LayerNorm)
    z_mma<<<dim3(Bq*Hh, 25), 256>>>(qp, kvsT_hi, kvsT_lo, winv, z, ln_g, ln_b);
    // G) relational bias
    biasadd_kernel<<<dim3(Bq*Pp, 5), 256>>>(fused, rden, v, z);
    // H) output projection
    wo_mma<<<dim3(BL/128, 2), 256>>>(z, Wo_w, Wo_b, out);
}

// round 16
// speedup vs baseline: 1.8457x; 1.2613x over previous
#include <cuda_runtime.h>
#include <cuda_bf16.h>
#include <math.h>
#include <stdint.h>

// ---------------- static problem config ----------------
#define Bq    8
#define Pp    8
#define Nn    100
#define Dm    256
#define Hh    8
#define DKk   32
#define Mm    64
#define Kg    16
#define Ll    800            // P*N
#define BL    6400           // B*L
#define NSPLIT 125
#define KCHUNK 80            // 125*80 = 10000

#define PHI_SCALE 0.84089641525f   // 2 * 32^-0.25
#define KVS_ELEMS (64*512*64)

typedef unsigned long long ull;

// ---------------- packed f32x2 helpers ----------------
__device__ __forceinline__ ull pack2(float x, float y) {
    ull r; asm("mov.b64 %0, {%1,%2};" : "=l"(r) : "f"(x), "f"(y)); return r;
}
__device__ __forceinline__ ull fma2(ull a, ull b, ull c) {
    ull d; asm("fma.rn.f32x2 %0, %1, %2, %3;" : "=l"(d) : "l"(a), "l"(b), "l"(c)); return d;
}
__device__ __forceinline__ float2 unpack2(ull p) {
    float2 r; asm("mov.b64 {%0,%1}, %2;" : "=f"(r.x), "=f"(r.y) : "l"(p)); return r;
}

// ---------------- cp.async helpers ----------------
__device__ __forceinline__ void cp_async16(void* sptr, const void* gptr) {
    uint32_t s = (uint32_t)__cvta_generic_to_shared(sptr);
    asm volatile("cp.async.ca.shared.global [%0], [%1], 16;" :: "r"(s), "l"(gptr));
}
#define CP_COMMIT() asm volatile("cp.async.commit_group;" ::: "memory")
#define CP_WAIT1()  asm volatile("cp.async.wait_group 1;"  ::: "memory")
#define CP_WAIT0()  asm volatile("cp.async.wait_group 0;"  ::: "memory")

// ---------------- scratch (device globals; no allocation) ----------------
__device__ __align__(16) float g_q   [BL*Dm];
__device__ __align__(16) float g_k   [BL*Dm];
__device__ __align__(16) float g_v   [BL*Dm];
__device__ __align__(16) float g_qp  [BL*Hh*Mm];
__device__ __align__(16) float g_kdd [BL*Hh*Mm];
__device__              float g_kdiag[BL*Hh];
__device__              float g_krmax[BL*Hh];
__device__ __align__(16) float g_kp  [BL*Hh*Mm];
__device__ __align__(16) __nv_bfloat16 g_kvsT_hi[KVS_ELEMS];
__device__ __align__(16) __nv_bfloat16 g_kvsT_lo[KVS_ELEMS];
__device__ __align__(16) float g_ksum[Bq*Hh*Kg*Mm];
__device__ __align__(16) float g_z   [BL*Dm];
__device__ __align__(16) float g_h1p [NSPLIT*512*128];
__device__              float g_wpat [512];
__device__ __align__(16) float g_fused[Bq*Pp*Nn*Nn];
__device__              float g_rden [Bq*Pp*Nn];

// ================= mma.sync primitive =================
__device__ __forceinline__ void mma16816(float* d, const uint32_t* a, const uint32_t* b)
{
    asm volatile(
        "mma.sync.aligned.m16n8k16.row.col.f32.bf16.bf16.f32 "
        "{%0,%1,%2,%3}, {%4,%5,%6,%7}, {%8,%9}, {%0,%1,%2,%3};"
        : "+f"(d[0]), "+f"(d[1]), "+f"(d[2]), "+f"(d[3])
        : "r"(a[0]), "r"(a[1]), "r"(a[2]), "r"(a[3]), "r"(b[0]), "r"(b[1]));
}

__device__ __forceinline__ void bf16_split(float f, __nv_bfloat16& hi, __nv_bfloat16& lo)
{
    hi = __float2bfloat16(f);
    lo = __float2bfloat16(f - __bfloat162float(hi));
}
__device__ __forceinline__ uint32_t pack_bf2(__nv_bfloat16 a, __nv_bfloat16 b)
{
    __nv_bfloat162 p = __halves2bfloat162(a, b);
    return reinterpret_cast<uint32_t&>(p);
}

// ================= projection GEMM body (bf16x3, cp.async dbuf) =============
#define SMS 40
// dynamic smem layout:
//   Af: float[2][4096]  @ 0       (32768 B)
//   Wf: float[2][4096]  @ 32768   (32768 B)
//   bf16 Ah/Al/Wh/Wl    @ 65536   (4*128*SMS*2 = 40960 B)
#define PROJ_SMEM 106496

__device__ __forceinline__ void issue_chunk(const float* __restrict__ A,
                                            const float* __restrict__ W,
                                            int row0, int col0, int kc,
                                            float* Af, float* Wf, int tid)
{
#pragma unroll
    for (int j = 0; j < 4; j++) {
        int idx = tid + j * 256;
        int r = idx >> 3, c4 = (idx & 7) * 4;
        cp_async16(&Af[r*32 + c4], A + (size_t)(row0 + r) * 256 + kc*32 + c4);
        cp_async16(&Wf[r*32 + c4], W + (size_t)(col0 + r) * 256 + kc*32 + c4);
    }
}

__device__ __forceinline__ void convert_slab(const float* __restrict__ Ff,
                                             __nv_bfloat16* __restrict__ hi,
                                             __nv_bfloat16* __restrict__ lo, int tid)
{
#pragma unroll
    for (int j = 0; j < 4; j++) {
        int idx = tid + j * 256;
        int r = idx >> 3, c4 = (idx & 7) * 4;
        float4 f = *(const float4*)&Ff[r*32 + c4];
        __nv_bfloat16 h0, l0, h1, l1, h2, l2, h3, l3;
        bf16_split(f.x, h0, l0); bf16_split(f.y, h1, l1);
        bf16_split(f.z, h2, l2); bf16_split(f.w, h3, l3);
        uint2 hw = make_uint2(pack_bf2(h0, h1), pack_bf2(h2, h3));
        uint2 lw = make_uint2(pack_bf2(l0, l1), pack_bf2(l2, l3));
        *(uint2*)(hi + r * SMS + c4) = hw;
        *(uint2*)(lo + r * SMS + c4) = lw;
    }
}

__device__ __forceinline__ void mma_gemm_body(const float* __restrict__ A,
                                              const float* __restrict__ W,
                                              const float* __restrict__ bias,
                                              float* __restrict__ C,
                                              int row0, int col0, char* smem)
{
    float* Af = (float*)smem;
    float* Wf = (float*)(smem + 32768);
    __nv_bfloat16* Ah = (__nv_bfloat16*)(smem + 65536);
    __nv_bfloat16* Al = Ah + 128 * SMS;
    __nv_bfloat16* Wh = Ah + 2 * 128 * SMS;
    __nv_bfloat16* Wl = Ah + 3 * 128 * SMS;

    int tid = threadIdx.x, lane = tid & 31, warp = tid >> 5;
    int wm = warp & 3, wn = warp >> 2;
    int g = lane >> 2, tg = lane & 3;

    float d[2][8][4];
#pragma unroll
    for (int mt = 0; mt < 2; mt++)
#pragma unroll
        for (int nt = 0; nt < 8; nt++)
#pragma unroll
            for (int i = 0; i < 4; i++) d[mt][nt][i] = 0.f;

    issue_chunk(A, W, row0, col0, 0, Af, Wf, tid);
    CP_COMMIT();
    int buf = 0;

    for (int kc = 0; kc < 8; kc++) {
        if (kc < 7) {
            issue_chunk(A, W, row0, col0, kc + 1,
                        Af + (buf ^ 1) * 4096, Wf + (buf ^ 1) * 4096, tid);
            CP_COMMIT();
            CP_WAIT1();
        } else {
            CP_WAIT0();
        }
        __syncthreads();
        convert_slab(Af + buf * 4096, Ah, Al, tid);
        convert_slab(Wf + buf * 4096, Wh, Wl, tid);
        __syncthreads();
#pragma unroll
        for (int ks = 0; ks < 2; ks++) {
            int kb = ks * 16;
            uint32_t ah[2][4], al[2][4];
#pragma unroll
            for (int mt = 0; mt < 2; mt++) {
                int rb = wm * 32 + mt * 16;
                const __nv_bfloat16* p0 = &Ah[(rb + g) * SMS + kb + tg * 2];
                const __nv_bfloat16* p1 = &Ah[(rb + g + 8) * SMS + kb + tg * 2];
                ah[mt][0] = *(const uint32_t*)p0;
                ah[mt][1] = *(const uint32_t*)p1;
                ah[mt][2] = *(const uint32_t*)(p0 + 8);
                ah[mt][3] = *(const uint32_t*)(p1 + 8);
                const __nv_bfloat16* q0 = &Al[(rb + g) * SMS + kb + tg * 2];
                const __nv_bfloat16* q1 = &Al[(rb + g + 8) * SMS + kb + tg * 2];
                al[mt][0] = *(const uint32_t*)q0;
                al[mt][1] = *(const uint32_t*)q1;
                al[mt][2] = *(const uint32_t*)(q0 + 8);
                al[mt][3] = *(const uint32_t*)(q1 + 8);
            }
#pragma unroll
            for (int nt = 0; nt < 8; nt++) {
                int nb = wn * 64 + nt * 8;
                const __nv_bfloat16* qh = &Wh[(nb + g) * SMS + kb + tg * 2];
                const __nv_bfloat16* ql = &Wl[(nb + g) * SMS + kb + tg * 2];
                uint32_t bh2[2] = {*(const uint32_t*)qh, *(const uint32_t*)(qh + 8)};
                uint32_t bl2[2] = {*(const uint32_t*)ql, *(const uint32_t*)(ql + 8)};
#pragma unroll
                for (int mt = 0; mt < 2; mt++) {
                    mma16816(d[mt][nt], ah[mt], bh2);
                    mma16816(d[mt][nt], ah[mt], bl2);
                    mma16816(d[mt][nt], al[mt], bh2);
                }
            }
        }
        __syncthreads();
        buf ^= 1;
    }

#pragma unroll
    for (int mt = 0; mt < 2; mt++) {
        int r0 = row0 + wm * 32 + mt * 16 + g;
#pragma unroll
        for (int nt = 0; nt < 8; nt++) {
            int col = col0 + wn * 64 + nt * 8 + tg * 2;
            float2 b2 = *(const float2*)&bias[col];
            float2 o0 = make_float2(d[mt][nt][0] + b2.x, d[mt][nt][1] + b2.y);
            float2 o1 = make_float2(d[mt][nt][2] + b2.x, d[mt][nt][3] + b2.y);
            *(float2*)&C[(size_t)r0 * 256 + col]       = o0;
            *(float2*)&C[(size_t)(r0 + 8) * 256 + col] = o1;
        }
    }
}

// ================= fp32 GEMM body (fc split-K), smem passed in ==============
__device__ __forceinline__ void gemm128_body(const float* __restrict__ A,
                                             const float* __restrict__ W,
                                             float* __restrict__ C,
                                             int Nc, int Kd, int k0, int klen,
                                             int row0, int col0, float* smem)
{
    typedef float Tile[16][132];
    Tile* As = (Tile*)smem;
    Tile* Ws = (Tile*)(smem + 2 * 16 * 132);
    int tid = threadIdx.x;
    int tx = tid & 15, ty = tid >> 4;
    int lr = tid >> 1, lc = (tid & 1) * 8;

    const float* Ap = A + (size_t)(row0 + lr) * Kd + k0 + lc;
    const float* Wp = W + (size_t)(col0 + lr) * Kd + k0 + lc;

    ull acc[8][4];
#pragma unroll
    for (int i = 0; i < 8; i++)
#pragma unroll
        for (int j = 0; j < 4; j++) acc[i][j] = 0ULL;

    float4 pa0 = *(const float4*)(Ap);
    float4 pa1 = *(const float4*)(Ap + 4);
    float4 pw0 = *(const float4*)(Wp);
    float4 pw1 = *(const float4*)(Wp + 4);

    int nk = klen >> 4;
    int buf = 0;
    for (int it = 0; it < nk; it++) {
        As[buf][lc+0][lr] = pa0.x; As[buf][lc+1][lr] = pa0.y;
        As[buf][lc+2][lr] = pa0.z; As[buf][lc+3][lr] = pa0.w;
        As[buf][lc+4][lr] = pa1.x; As[buf][lc+5][lr] = pa1.y;
        As[buf][lc+6][lr] = pa1.z; As[buf][lc+7][lr] = pa1.w;
        Ws[buf][lc+0][lr] = pw0.x; Ws[buf][lc+1][lr] = pw0.y;
        Ws[buf][lc+2][lr] = pw0.z; Ws[buf][lc+3][lr] = pw0.w;
        Ws[buf][lc+4][lr] = pw1.x; Ws[buf][lc+5][lr] = pw1.y;
        Ws[buf][lc+6][lr] = pw1.z; Ws[buf][lc+7][lr] = pw1.w;
        __syncthreads();
        if (it + 1 < nk) {
            int off = (it + 1) * 16;
            pa0 = *(const float4*)(Ap + off);
            pa1 = *(const float4*)(Ap + off + 4);
            pw0 = *(const float4*)(Wp + off);
            pw1 = *(const float4*)(Wp + off + 4);
        }
#pragma unroll
        for (int c = 0; c < 16; c++) {
            float4 a0 = *(const float4*)&As[buf][c][ty*4];
            float4 a1 = *(const float4*)&As[buf][c][64 + ty*4];
            ulonglong2 w01 = *(const ulonglong2*)&Ws[buf][c][tx*4];
            ulonglong2 w23 = *(const ulonglong2*)&Ws[buf][c][64 + tx*4];
            ull wp[4] = {w01.x, w01.y, w23.x, w23.y};
            float av[8] = {a0.x,a0.y,a0.z,a0.w, a1.x,a1.y,a1.z,a1.w};
#pragma unroll
            for (int i = 0; i < 8; i++) {
                ull ad = pack2(av[i], av[i]);
#pragma unroll
                for (int j = 0; j < 4; j++) acc[i][j] = fma2(ad, wp[j], acc[i][j]);
            }
        }
        buf ^= 1;
        __syncthreads();
    }

#pragma unroll
    for (int i = 0; i < 8; i++) {
        int rr = row0 + ((i < 4) ? (ty*4 + i) : (64 + ty*4 + i - 4));
        float2 p0 = unpack2(acc[i][0]);
        float2 p1 = unpack2(acc[i][1]);
        float2 p2 = unpack2(acc[i][2]);
        float2 p3 = unpack2(acc[i][3]);
        float4 o0 = make_float4(p0.x, p0.y, p1.x, p1.y);
        float4 o1 = make_float4(p2.x, p2.y, p3.x, p3.y);
        *(float4*)&C[(size_t)rr * Nc + col0 + tx*4]      = o0;
        *(float4*)&C[(size_t)rr * Nc + col0 + 64 + tx*4] = o1;
    }
}

// ================= STAGE A: qkv (300) || fc split-K (500) ===================
__global__ void __launch_bounds__(256) stage_a(
    const float* __restrict__ x,
    const float* __restrict__ Wq, const float* __restrict__ Wk, const float* __restrict__ Wv,
    const float* __restrict__ bq, const float* __restrict__ bk, const float* __restrict__ bv,
    float* __restrict__ q, float* __restrict__ k, float* __restrict__ v,
    const float* __restrict__ adj, const float* __restrict__ fc_w, float* __restrict__ h1p)
{
    extern __shared__ __align__(16) char uni[];
    int blk = blockIdx.x;
    if (blk < 300) {
        int bx = blk % 50, by = (blk / 50) & 1, bz = blk / 100;
        const float* W = bz == 0 ? Wq : (bz == 1 ? Wk : Wv);
        const float* bb = bz == 0 ? bq : (bz == 1 ? bk : bv);
        float* C = bz == 0 ? q : (bz == 1 ? k : v);
        mma_gemm_body(x, W, bb, C, bx * 128, by * 128, uni);
    } else {
        int s = blk - 300;
        int bx = s & 3, bz = s >> 2;
        gemm128_body(adj, fc_w, h1p + (size_t)bz * 512 * 128,
                     128, 10000, bz * KCHUNK, KCHUNK, bx * 128, 0, (float*)uni);
    }
}

// ================= STAGE B: phi_k (3200) || phi_q (3200) || score (64) ======
__device__ __forceinline__ void phi_body(const float* __restrict__ din,
                                         const float* __restrict__ proj,
                                         float* __restrict__ outphi,
                                         float* __restrict__ dd_out,
                                         float* __restrict__ diag_out,
                                         float* __restrict__ rmax_out,
                                         int is_query, int bx)
{
    __shared__ __align__(16) float proj_s[64][34];
    __shared__ __align__(16) float data_s[4][32];
    __shared__ float wmax[4][2];
    int tid = threadIdx.x;
    for (int i = tid; i < 2048; i += 256) proj_s[i >> 5][i & 31] = proj[i];
    int sub = tid >> 6;
    int m = tid & 63;
    int u0 = bx * 16;
    for (int g = 0; g < 16; g += 4) {
        int u = u0 + g + sub;
        __syncthreads();
        if (m < 32) data_s[sub][m] = din[(size_t)u*32 + m] * PHI_SCALE;
        __syncthreads();
        ull dd2 = 0ULL, dg2 = 0ULL;
#pragma unroll
        for (int d2 = 0; d2 < 16; d2++) {
            ull x2 = *(const ull*)&data_s[sub][d2*2];
            ull p2 = *(const ull*)&proj_s[m][d2*2];
            dd2 = fma2(x2, p2, dd2);
            dg2 = fma2(x2, x2, dg2);
        }
        float2 dp = unpack2(dd2);
        float2 gp = unpack2(dg2);
        float dd = dp.x + dp.y;
        float diag = 0.5f * (gp.x + gp.y);
        float mx = dd;
#pragma unroll
        for (int o = 16; o > 0; o >>= 1) mx = fmaxf(mx, __shfl_xor_sync(0xffffffffu, mx, o));
        if ((tid & 31) == 0) wmax[sub][m >> 5] = mx;
        __syncthreads();
        float stab = fmaxf(wmax[sub][0], wmax[sub][1]);
        if (is_query) {
            outphi[(size_t)u*64 + m] = 0.125f * (expf(dd - diag - stab) + 1e-6f);
        } else {
            dd_out[(size_t)u*64 + m] = dd;
            if (m == 0) { diag_out[u] = diag; rmax_out[u] = stab; }
        }
    }
}

__device__ __forceinline__ void score_body(const float* __restrict__ h1p,
                                           const float* __restrict__ fc_b,
                                           const float* __restrict__ out_w,
                                           const float* __restrict__ out_b,
                                           float* __restrict__ wout, int bp)
{
    int t = threadIdx.x >> 5, lane = threadIdx.x & 31;
    __shared__ float sc[8];
    float p = 0.f;
    for (int j = lane; j < 128; j += 32) {
        float hv = fc_b[j];
        for (int s = 0; s < NSPLIT; s++) hv += h1p[(size_t)s*65536 + (bp*8 + t)*128 + j];
        hv = fmaxf(hv, 0.f);
        p += hv * out_w[j];
    }
#pragma unroll
    for (int o = 16; o > 0; o >>= 1) p += __shfl_xor_sync(0xffffffffu, p, o);
    if (lane == 0) sc[t] = p + out_b[0];
    __syncthreads();
    if (threadIdx.x == 0) {
        float mx = sc[0];
#pragma unroll
        for (int i = 1; i < 8; i++) mx = fmaxf(mx, sc[i]);
        float e[8], sum = 0.f;
#pragma unroll
        for (int i = 0; i < 8; i++) { e[i] = expf(sc[i] - mx); sum += e[i]; }
#pragma unroll
        for (int i = 0; i < 8; i++) wout[bp*8 + i] = e[i] / sum;
    }
}

__global__ void __launch_bounds__(256) stage_b(
    const float* __restrict__ q, const float* __restrict__ k,
    const float* __restrict__ proj,
    float* __restrict__ qp, float* __restrict__ kdd,
    float* __restrict__ kdiag, float* __restrict__ krmax,
    const float* __restrict__ h1p, const float* __restrict__ fc_b,
    const float* __restrict__ out_w, const float* __restrict__ out_b,
    float* __restrict__ wpat)
{
    int blk = blockIdx.x;
    if (blk < 6400) {
        int isq = blk >= 3200;
        int bx = isq ? blk - 3200 : blk;
        phi_body(isq ? q : k, proj, qp, kdd, kdiag, krmax, isq, bx);
    } else {
        score_body(h1p, fc_b, out_w, out_b, wpat, blk - 6400);
    }
}

// ================= STAGE C: kp_finalize (64) || fused (625) =================
__device__ __forceinline__ void kp_finalize_body(const float* __restrict__ kdd,
                                                 const float* __restrict__ kdiag,
                                                 const float* __restrict__ krmax,
                                                 float* __restrict__ kp, int bh)
{
    int b = bh >> 3, h = bh & 7;
    int t = threadIdx.x;
    __shared__ float red[256];
    float mx = -1e30f;
    for (int l = t; l < Ll; l += 256) mx = fmaxf(mx, krmax[(b*Ll + l)*Hh + h]);
    red[t] = mx; __syncthreads();
    for (int s = 128; s > 0; s >>= 1) {
        if (t < s) red[t] = fmaxf(red[t], red[t + s]);
        __syncthreads();
    }
    float km = red[0];
    for (int i = t; i < Ll * 64; i += 256) {
        int l = i >> 6, m = i & 63;
        size_t u = (size_t)(b*Ll + l)*Hh + h;
        kp[u*64 + m] = 0.125f * (expf(kdd[u*64 + m] - kdiag[u] - km) + 1e-6f);
    }
}

__device__ __forceinline__ void fused_body(const float* __restrict__ adj,
                                           const float* __restrict__ wpat,
                                           float* __restrict__ fused, int blk)
{
    int i4 = blk * 256 + threadIdx.x;    // < 160000
    if (i4 >= 160000) return;
    int bp = i4 / 2500;
    int r4 = i4 - bp * 2500;
    float4 s = make_float4(0,0,0,0);
#pragma unroll
    for (int t = 0; t < 8; t++) {
        float w = wpat[bp*8 + t];
        float4 a = *(const float4*)&adj[(size_t)(bp*8 + t)*10000 + r4*4];
        s.x += a.x*w; s.y += a.y*w; s.z += a.z*w; s.w += a.w*w;
    }
    *(float4*)&fused[(size_t)bp*10000 + r4*4] = s;
}

__global__ void __launch_bounds__(256) stage_c(
    const float* __restrict__ kdd, const float* __restrict__ kdiag,
    const float* __restrict__ krmax, float* __restrict__ kp,
    const float* __restrict__ adj, const float* __restrict__ wpat,
    float* __restrict__ fused)
{
    int blk = blockIdx.x;
    if (blk < 64) kp_finalize_body(kdd, kdiag, krmax, kp, blk);
    else          fused_body(adj, wpat, fused, blk - 64);
}

// ================= STAGE D: kvs (256) || rden (800) || ksum (64) ============
#define SA 36
__device__ __forceinline__ void kvs_body(
    const float* __restrict__ kp, const float* __restrict__ v,
    const float* __restrict__ gum,
    __nv_bfloat16* __restrict__ kvsT_hi, __nv_bfloat16* __restrict__ kvsT_lo,
    int bh, int qq)
{
    __shared__ __align__(16) __nv_bfloat16 As_hi[64*SA], As_lo[64*SA];
    __shared__ __align__(16) __nv_bfloat16 Bs_hi[128*SA], Bs_lo[128*SA];
    __shared__ float v_s[32][32];
    __shared__ float e_s[32][4];

    int b = bh >> 3, h = bh & 7;
    int t = threadIdx.x, lane = t & 31, warp = t >> 5;
    int wm = warp & 3, wn = warp >> 2;
    int g = lane >> 2, tg = lane & 3;

    int vl = t >> 3, vd4 = (t & 7) * 4;
    int el = t >> 2, ekq = t & 3;

    float d[8][4];
#pragma unroll
    for (int nt = 0; nt < 8; nt++)
#pragma unroll
        for (int i = 0; i < 4; i++) d[nt][i] = 0.f;

    float4 pv;
    float pe = 0.f;
    float pk0[4], pk1[4];
    {
        pv = *(const float4*)&v[(size_t)(b*Ll + vl)*Dm + h*32 + vd4];
        if (t < 128) pe = gum[(((b*Ll + el)*Hh + h) << 4) + qq*4 + ekq];
#pragma unroll
        for (int j = 0; j < 4; j++) {
            int idx = t + j * 256;
            int m = idx & 63, lp = idx >> 6;
            int l = lp * 2;
            pk0[j] = kp[((size_t)((b*Ll + l    )*Hh + h) << 6) + m];
            pk1[j] = kp[((size_t)((b*Ll + l + 1)*Hh + h) << 6) + m];
        }
    }

    for (int ci = 0; ci < 25; ci++) {
        *(float4*)&v_s[vl][vd4] = pv;
        if (t < 128) e_s[el][ekq] = expf(pe);
#pragma unroll
        for (int j = 0; j < 4; j++) {
            int idx = t + j * 256;
            int m = idx & 63, lp = idx >> 6;
            __nv_bfloat16 h0, lo0, h1, lo1;
            bf16_split(pk0[j], h0, lo0); bf16_split(pk1[j], h1, lo1);
            *(uint32_t*)&As_hi[m*SA + lp*2] = pack_bf2(h0, h1);
            *(uint32_t*)&As_lo[m*SA + lp*2] = pack_bf2(lo0, lo1);
        }
        __syncthreads();
        {
            int n = t >> 1;
            int lpb = (t & 1) * 8;
            int kq = n >> 5, dd2 = n & 31;
#pragma unroll
            for (int j = 0; j < 8; j++) {
                int lp = lpb + j;
                float f0 = e_s[2*lp][kq]     * v_s[2*lp][dd2];
                float f1 = e_s[2*lp + 1][kq] * v_s[2*lp + 1][dd2];
                __nv_bfloat16 h0, lo0, h1, lo1;
                bf16_split(f0, h0, lo0); bf16_split(f1, h1, lo1);
                *(uint32_t*)&Bs_hi[n*SA + lp*2] = pack_bf2(h0, h1);
                *(uint32_t*)&Bs_lo[n*SA + lp*2] = pack_bf2(lo0, lo1);
            }
        }
        if (ci < 24) {
            int l0 = (ci + 1) * 32;
            pv = *(const float4*)&v[(size_t)(b*Ll + l0 + vl)*Dm + h*32 + vd4];
            if (t < 128) pe = gum[(((b*Ll + l0 + el)*Hh + h) << 4) + qq*4 + ekq];
#pragma unroll
            for (int j = 0; j < 4; j++) {
                int idx = t + j * 256;
                int m = idx & 63, lp = idx >> 6;
                int l = l0 + lp * 2;
                pk0[j] = kp[((size_t)((b*Ll + l    )*Hh + h) << 6) + m];
                pk1[j] = kp[((size_t)((b*Ll + l + 1)*Hh + h) << 6) + m];
            }
        }
        __syncthreads();
#pragma unroll
        for (int ks = 0; ks < 2; ks++) {
            int kb = ks * 16;
            uint32_t ah[4], al[4];
            {
                int rb = wm * 16;
                const __nv_bfloat16* p0 = &As_hi[(rb + g) * SA + kb + tg*2];
                const __nv_bfloat16* p1 = &As_hi[(rb + g + 8) * SA + kb + tg*2];
                ah[0] = *(const uint32_t*)p0;
                ah[1] = *(const uint32_t*)p1;
                ah[2] = *(const uint32_t*)(p0 + 8);
                ah[3] = *(const uint32_t*)(p1 + 8);
                const __nv_bfloat16* q0 = &As_lo[(rb + g) * SA + kb + tg*2];
                const __nv_bfloat16* q1 = &As_lo[(rb + g + 8) * SA + kb + tg*2];
                al[0] = *(const uint32_t*)q0;
                al[1] = *(const uint32_t*)q1;
                al[2] = *(const uint32_t*)(q0 + 8);
                al[3] = *(const uint32_t*)(q1 + 8);
            }
#pragma unroll
            for (int nt = 0; nt < 8; nt++) {
                int nb = wn * 64 + nt * 8;
                const __nv_bfloat16* qh = &Bs_hi[(nb + g) * SA + kb + tg*2];
                const __nv_bfloat16* ql = &Bs_lo[(nb + g) * SA + kb + tg*2];
                uint32_t bh2[2] = {*(const uint32_t*)qh, *(const uint32_t*)(qh + 8)};
                uint32_t bl2[2] = {*(const uint32_t*)ql, *(const uint32_t*)(ql + 8)};
                mma16816(d[nt], ah, bh2);
                mma16816(d[nt], ah, bl2);
                mma16816(d[nt], al, bh2);
            }
        }
        __syncthreads();
    }
    int m = wm * 16 + g;
#pragma unroll
    for (int nt = 0; nt < 8; nt++) {
        int n = qq*128 + wn*64 + nt*8 + tg*2;
        size_t base0 = ((size_t)bh * 512 + n) * 64;
        size_t base1 = base0 + 64;
        __nv_bfloat16 hi, lo;
        bf16_split(d[nt][0], hi, lo); kvsT_hi[base0 + m] = hi;     kvsT_lo[base0 + m] = lo;
        bf16_split(d[nt][1], hi, lo); kvsT_hi[base1 + m] = hi;     kvsT_lo[base1 + m] = lo;
        bf16_split(d[nt][2], hi, lo); kvsT_hi[base0 + m + 8] = hi; kvsT_lo[base0 + m + 8] = lo;
        bf16_split(d[nt][3], hi, lo); kvsT_hi[base1 + m + 8] = hi; kvsT_lo[base1 + m + 8] = lo;
    }
}

__device__ __forceinline__ void rden_body(const float* __restrict__ fused,
                                          float* __restrict__ rden, int blk)
{
    int w = threadIdx.x >> 5, lane = threadIdx.x & 31;
    int row = blk * 8 + w;
    float s = 0.f;
    for (int j = lane; j < 100; j += 32) s += fabsf(fused[(size_t)row*100 + j]);
#pragma unroll
    for (int o = 16; o > 0; o >>= 1) s += __shfl_xor_sync(0xffffffffu, s, o);
    if (lane == 0) rden[row] = fmaxf(s, 1e-12f);
}

__device__ __forceinline__ void ksum_body(const float* __restrict__ kp,
                                          const float* __restrict__ gum,
                                          float* __restrict__ ksum, int bh)
{
    __shared__ __align__(16) float kp_s[16][64];
    __shared__ float eg_s[16][16];
    int b = bh >> 3, h = bh & 7;
    int t = threadIdx.x;
    int lc = t >> 4, lf = t & 15;
    float4 acc = make_float4(0,0,0,0);
    for (int l0 = 0; l0 < Ll; l0 += 16) {
        __syncthreads();
        *(float4*)&kp_s[lc][lf*4] =
            *(const float4*)&kp[((size_t)((b*Ll + l0 + lc)*Hh + h) << 6) + lf*4];
        eg_s[lc][lf] = expf(gum[(((b*Ll + l0 + lc)*Hh + h) << 4) + lf]);
        __syncthreads();
#pragma unroll
        for (int c = 0; c < 16; c++) {
            float e = eg_s[c][lc];
            float4 kp4 = *(const float4*)&kp_s[c][lf*4];
            acc.x += kp4.x * e; acc.y += kp4.y * e;
            acc.z += kp4.z * e; acc.w += kp4.w * e;
        }
    }
    *(float4*)&ksum[((size_t)(bh*16 + lc) << 6) + lf*4] = acc;
}

__global__ void __launch_bounds__(256) stage_d(
    const float* __restrict__ kp, const float* __restrict__ v,
    const float* __restrict__ gum,
    __nv_bfloat16* __restrict__ kvsT_hi, __nv_bfloat16* __restrict__ kvsT_lo,
    const float* __restrict__ fused, float* __restrict__ rden,
    float* __restrict__ ksum)
{
    int blk = blockIdx.x;
    if (blk < 256)       kvs_body(kp, v, gum, kvsT_hi, kvsT_lo, blk & 63, blk >> 6);
    else if (blk < 1056) rden_body(fused, rden, blk - 256);
    else                 ksum_body(kp, gum, ksum, blk - 1056);
}

// ========== z on HMMA + fused winv + winv reduction + LayerNorm =============
#define SQ 68
__global__ void __launch_bounds__(256) z_mma(
    const float* __restrict__ qp,
    const __nv_bfloat16* __restrict__ kvsT_hi, const __nv_bfloat16* __restrict__ kvsT_lo,
    const float* __restrict__ ksum, float* __restrict__ z,
    const float* __restrict__ ln_g, const float* __restrict__ ln_b)
{
    __shared__ __align__(16) __nv_bfloat16 Aq_hi[32*SQ], Aq_lo[32*SQ];
    __shared__ __align__(16) __nv_bfloat16 Bs_hi[64*SQ], Bs_lo[64*SQ];
    __shared__ __align__(16) float ksum_s[16*64];
    __shared__ float winv_s[32][16];
    __shared__ float zred[4][32][33];

    int bh = blockIdx.x;
    int b = bh >> 3, h = bh & 7;
    int l0 = blockIdx.y * 32;
    int t = threadIdx.x, lane = t & 31, warp = t >> 5;
    int wm = warp & 1, wn = warp >> 1;
    int g = lane >> 2, tg = lane & 3;

    uint32_t pbh[8], pbl[8];
#pragma unroll
    for (int j = 0; j < 8; j++) {
        int idx = t + j * 256;
        int n = idx >> 5, m2 = (idx & 31) * 2;
        size_t src = ((size_t)bh * 512 + n) * 64 + m2;
        pbh[j] = *(const uint32_t*)&kvsT_hi[src];
        pbl[j] = *(const uint32_t*)&kvsT_lo[src];
    }

    // stage A = qp tile [32 l][64 m] hi/lo
#pragma unroll
    for (int j = 0; j < 2; j++) {
        int idx = t + j * 256;
        int l = idx >> 4, m4 = (idx & 15) * 4;
        float4 q4 = *(const float4*)&qp[((size_t)((b*Ll + l0 + l)*Hh + h) << 6) + m4];
        float fv[4] = {q4.x, q4.y, q4.z, q4.w};
#pragma unroll
        for (int i = 0; i < 4; i++) {
            __nv_bfloat16 hi, lo; bf16_split(fv[i], hi, lo);
            Aq_hi[l*SQ + m4 + i] = hi;
            Aq_lo[l*SQ + m4 + i] = lo;
        }
    }
    // stage ksum (16x64 floats)
    *(float4*)&ksum_s[t*4] = *(const float4*)&ksum[((size_t)bh << 10) + t*4];
    // zero zred
    for (int idx = t; idx < 4*32*33; idx += 256) ((float*)zred)[idx] = 0.f;
    __syncthreads();

    // compute winv_s[l][k] = 1/((qp . ksum + 1e-8)*16), qp ~ hi+lo
#pragma unroll
    for (int p = 0; p < 2; p++) {
        int pr = t * 2 + p;
        int l = pr >> 4, kk = pr & 15;
        float acc = 0.f;
#pragma unroll 8
        for (int m = 0; m < 64; m++) {
            float qv = __bfloat162float(Aq_hi[l*SQ + m]) + __bfloat162float(Aq_lo[l*SQ + m]);
            acc += qv * ksum_s[kk*64 + m];
        }
        winv_s[l][kk] = 1.0f / ((acc + 1e-8f) * 16.0f);
    }
    __syncthreads();

    for (int ch = 0; ch < 8; ch++) {
#pragma unroll
        for (int j = 0; j < 8; j++) {
            int idx = t + j * 256;
            int n = idx >> 5, m2 = (idx & 31) * 2;
            *(uint32_t*)&Bs_hi[n*SQ + m2] = pbh[j];
            *(uint32_t*)&Bs_lo[n*SQ + m2] = pbl[j];
        }
        __syncthreads();
        if (ch < 7) {
#pragma unroll
            for (int j = 0; j < 8; j++) {
                int idx = t + j * 256;
                int n = idx >> 5, m2 = (idx & 31) * 2;
                size_t src = ((size_t)bh * 512 + (ch + 1)*64 + n) * 64 + m2;
                pbh[j] = *(const uint32_t*)&kvsT_hi[src];
                pbl[j] = *(const uint32_t*)&kvsT_lo[src];
            }
        }

        float dfr[2][4];
#pragma unroll
        for (int nt = 0; nt < 2; nt++)
#pragma unroll
            for (int i = 0; i < 4; i++) dfr[nt][i] = 0.f;

#pragma unroll
        for (int ks = 0; ks < 4; ks++) {
            int kb = ks * 16;
            uint32_t ah[4], al[4];
            {
                int rb = wm * 16;
                const __nv_bfloat16* p0 = &Aq_hi[(rb + g) * SQ + kb + tg*2];
                const __nv_bfloat16* p1 = &Aq_hi[(rb + g + 8) * SQ + kb + tg*2];
                ah[0] = *(const uint32_t*)p0;
                ah[1] = *(const uint32_t*)p1;
                ah[2] = *(const uint32_t*)(p0 + 8);
                ah[3] = *(const uint32_t*)(p1 + 8);
                const __nv_bfloat16* q0 = &Aq_lo[(rb + g) * SQ + kb + tg*2];
                const __nv_bfloat16* q1 = &Aq_lo[(rb + g + 8) * SQ + kb + tg*2];
                al[0] = *(const uint32_t*)q0;
                al[1] = *(const uint32_t*)q1;
                al[2] = *(const uint32_t*)(q0 + 8);
                al[3] = *(const uint32_t*)(q1 + 8);
            }
#pragma unroll
            for (int nt = 0; nt < 2; nt++) {
                int nb = wn * 16 + nt * 8;
                const __nv_bfloat16* qh = &Bs_hi[(nb + g) * SQ + kb + tg*2];
                const __nv_bfloat16* ql = &Bs_lo[(nb + g) * SQ + kb + tg*2];
                uint32_t bh2[2] = {*(const uint32_t*)qh, *(const uint32_t*)(qh + 8)};
                uint32_t bl2[2] = {*(const uint32_t*)ql, *(const uint32_t*)(ql + 8)};
                mma16816(dfr[nt], ah, bh2);
                mma16816(dfr[nt], ah, bl2);
                mma16816(dfr[nt], al, bh2);
            }
        }
        int k = ch*2 + (wn >> 1);
        int la = wm*16 + g, lb = la + 8;
        float wia = winv_s[la][k], wib = winv_s[lb][k];
#pragma unroll
        for (int nt = 0; nt < 2; nt++) {
            int dl = (wn & 1)*16 + nt*8 + tg*2;
            zred[wn][la][dl]     += dfr[nt][0] * wia;
            zred[wn][la][dl + 1] += dfr[nt][1] * wia;
            zred[wn][lb][dl]     += dfr[nt][2] * wib;
            zred[wn][lb][dl + 1] += dfr[nt][3] * wib;
        }
        __syncthreads();
    }

    float gl = ln_g[lane], bl = ln_b[lane];
#pragma unroll
    for (int j = 0; j < 4; j++) {
        int tok = warp + j * 8;
        float ss = zred[0][tok][lane] + zred[1][tok][lane]
                 + zred[2][tok][lane] + zred[3][tok][lane];
        float mu = ss;
#pragma unroll
        for (int o = 16; o > 0; o >>= 1) mu += __shfl_xor_sync(0xffffffffu, mu, o);
        mu *= (1.0f / 32.0f);
        float df = ss - mu;
        float v2 = df * df;
#pragma unroll
        for (int o = 16; o > 0; o >>= 1) v2 += __shfl_xor_sync(0xffffffffu, v2, o);
        float var = v2 * (1.0f / 32.0f);
        z[(size_t)(b*Ll + l0 + tok)*Dm + h*32 + lane] =
            df * rsqrtf(var + 1e-5f) * gl + bl;
    }
}

// relational bias: z += (fused/rden) @ V (FFMA2); grid (64, 5)
__global__ void biasadd_kernel(const float* __restrict__ fused, const float* __restrict__ rden,
                               const float* __restrict__ v, float* __restrict__ z)
{
    __shared__ __align__(16) float A_s[20][102];
    int blk = blockIdx.x;
    int i0 = blockIdx.y * 20;
    int t = threadIdx.x;
    for (int idx = t; idx < 2000; idx += 256) {
        int i = idx / 100, j = idx - i * 100;
        A_s[i][j] = fused[(size_t)blk*10000 + (i0 + i)*100 + j] / rden[blk*100 + i0 + i];
    }
    __syncthreads();
    int base = blk * 100;
    ull accp[20];
#pragma unroll
    for (int ii = 0; ii < 20; ii++) accp[ii] = 0ULL;
    for (int j = 0; j < 100; j += 2) {
        float vj0 = v[(size_t)(base + j)*256 + t];
        float vj1 = v[(size_t)(base + j + 1)*256 + t];
        ull vp = pack2(vj0, vj1);
#pragma unroll
        for (int ii = 0; ii < 20; ii++)
            accp[ii] = fma2(*(const ull*)&A_s[ii][j], vp, accp[ii]);
    }
#pragma unroll
    for (int ii = 0; ii < 20; ii++) {
        float2 p = unpack2(accp[ii]);
        z[(size_t)(base + i0 + ii)*256 + t] += p.x + p.y;
    }
}

// ---------------- wo projection (dynamic smem, cp.async) ----------------
__global__ void __launch_bounds__(256) wo_mma(
    const float* __restrict__ A, const float* __restrict__ W,
    const float* __restrict__ b, float* __restrict__ C)
{
    extern __shared__ __align__(16) char uni[];
    mma_gemm_body(A, W, b, C, blockIdx.x * 128, blockIdx.y * 128, uni);
}

// ---------------- launcher: fused-stage serial graph ----------------
extern "C" void kernel_launch(void* const* d_in, const int* in_sizes, int n_in,
                              void* d_out, int out_size)
{
    const float* x     = (const float*)d_in[0];
    const float* adj   = (const float*)d_in[1];
    const float* Wq_w  = (const float*)d_in[2];
    const float* Wq_b  = (const float*)d_in[3];
    const float* Wk_w  = (const float*)d_in[4];
    const float* Wk_b  = (const float*)d_in[5];
    const float* Wv_w  = (const float*)d_in[6];
    const float* Wv_b  = (const float*)d_in[7];
    const float* Wo_w  = (const float*)d_in[8];
    const float* Wo_b  = (const float*)d_in[9];
    const float* ln_g  = (const float*)d_in[10];
    const float* ln_b  = (const float*)d_in[11];
    const float* fc_w  = (const float*)d_in[12];
    const float* fc_b  = (const float*)d_in[13];
    const float* out_w = (const float*)d_in[14];
    const float* out_b = (const float*)d_in[15];
    const float* proj  = (const float*)d_in[16];
    const float* gum   = (const float*)d_in[17];
    float* out = (float*)d_out;

    float *q, *k, *v, *qp, *kdd, *kdiag, *krmax, *kp, *ksum, *z;
    float *h1p, *wpat, *fused, *rden;
    __nv_bfloat16 *kvsT_hi, *kvsT_lo;
    cudaGetSymbolAddress((void**)&q,     g_q);
    cudaGetSymbolAddress((void**)&k,     g_k);
    cudaGetSymbolAddress((void**)&v,     g_v);
    cudaGetSymbolAddress((void**)&qp,    g_qp);
    cudaGetSymbolAddress((void**)&kdd,   g_kdd);
    cudaGetSymbolAddress((void**)&kdiag, g_kdiag);
    cudaGetSymbolAddress((void**)&krmax, g_krmax);
    cudaGetSymbolAddress((void**)&kp,    g_kp);
    cudaGetSymbolAddress((void**)&kvsT_hi, g_kvsT_hi);
    cudaGetSymbolAddress((void**)&kvsT_lo, g_kvsT_lo);
    cudaGetSymbolAddress((void**)&ksum,  g_ksum);
    cudaGetSymbolAddress((void**)&z,     g_z);
    cudaGetSymbolAddress((void**)&h1p,   g_h1p);
    cudaGetSymbolAddress((void**)&wpat,  g_wpat);
    cudaGetSymbolAddress((void**)&fused, g_fused);
    cudaGetSymbolAddress((void**)&rden,  g_rden);

    cudaFuncSetAttribute(stage_a, cudaFuncAttributeMaxDynamicSharedMemorySize, PROJ_SMEM);
    cudaFuncSetAttribute(wo_mma,  cudaFuncAttributeMaxDynamicSharedMemorySize, PROJ_SMEM);

    // A) qkv (cp.async dbuf) || adjacency fc
    stage_a<<<800, 256, PROJ_SMEM>>>(x, Wq_w, Wk_w, Wv_w, Wq_b, Wk_b, Wv_b,
                                     q, k, v, adj, fc_w, h1p);
    // B) phi_k || phi_q || score
    stage_b<<<6464, 256>>>(q, k, proj, qp, kdd, kdiag, krmax,
                           h1p, fc_b, out_w, out_b, wpat);
    // C) kp finalize || fused adjacency
    stage_c<<<689, 256>>>(kdd, kdiag, krmax, kp, adj, wpat, fused);
    // D) kvs || rden || ksum   <-- profiled launch slot
    stage_d<<<1120, 256>>>(kp, v, gum, kvsT_hi, kvsT_lo, fused, rden, ksum);
    // E) z (+fused winv + LayerNorm)
    z_mma<<<dim3(Bq*Hh, 25), 256>>>(qp, kvsT_hi, kvsT_lo, ksum, z, ln_g, ln_b);
    // F) relational bias
    biasadd_kernel<<<dim3(Bq*Pp, 5), 256>>>(fused, rden, v, z);
    // G) output projection (cp.async dbuf)
    wo_mma<<<dim3(BL/128, 2), 256, PROJ_SMEM>>>(z, Wo_w, Wo_b, out);
}